// round 2
// baseline (speedup 1.0000x reference)
#include <cuda_runtime.h>
#include <cstdint>
#include <cstddef>

#define Nn 8
#define Bb 4
#define Tt 1024
#define Dd 512
#define Hh 4
#define HDc 128
#define Rr 64
#define BTc (Bb*Tt)
#define NROWS (Nn*BTc)
#define EPSV 1e-5f
#define INV_SQRT_HD 0.08838834764831845f
#define L2E 1.4426950408889634f

// ---------------- device scratch ----------------
__device__ float g_mu[NROWS];
__device__ float g_rs[NROWS];
__device__ float g_maskf[Nn];
__device__ float g_invna;
__device__ float g_Wq[Nn*Dd*Dd];
__device__ float g_Sq[Nn*Dd];
__device__ float g_Cq[Nn*Dd];
__device__ float g_M[Nn*128*Dd];   // rows 0-63: k_comp@w_k (folded), 64-127: v_comp@w_v
__device__ float g_SM[Nn*128];
__device__ float g_CM[Nn*128];
__device__ float g_kq[(size_t)NROWS*Rr];
__device__ float g_vq[(size_t)NROWS*Rr];
__device__ float g_kdecT[Rr*Dd];
__device__ float g_vdecT[Rr*Dd];
__device__ float g_K[(size_t)Bb*Hh*Tt*HDc];
__device__ float g_V[(size_t)Bb*Hh*Tt*HDc];
__device__ float g_Q[(size_t)NROWS*Dd];
__device__ float g_AO[(size_t)NROWS*Dd];

// ---------------- mask decode (bool8 / int32 / float32) ----------------
__global__ void k_mask(const unsigned char* __restrict__ p)
{
    if (threadIdx.x == 0) {
        bool isF = (p[0]==0 && p[1]==0 && p[2]==0x80 && p[3]==0x3f);
        bool isI = (!isF && p[1]==0 && p[2]==0 && p[3]==0 && (p[4]!=0 || p[5]==0));
        // heuristic fallback: try byte layout if neither
        float na = 0.f;
        for (int n = 0; n < Nn; n++) {
            bool bit;
            if (isF)      bit = (((const float*)p)[n] != 0.f);
            else if (isI) bit = (((const int*)p)[n]   != 0);
            else          bit = (p[n] != 0);
            g_maskf[n] = bit ? 1.f : 0.f;
            na += bit ? 1.f : 0.f;
        }
        g_invna = 1.f / fmaxf(na, 1.f);
    }
}

// ---------------- LN row stats: one warp per row ----------------
__global__ __launch_bounds__(256) void k_lnstats(const float* __restrict__ x)
{
    int row  = blockIdx.x * 8 + (threadIdx.x >> 5);
    int lane = threadIdx.x & 31;
    const float4* xp = (const float4*)(x + (size_t)row * Dd);
    float s = 0.f, sq = 0.f;
    #pragma unroll
    for (int i = 0; i < 4; i++) {
        float4 v = xp[lane + 32*i];
        s  += v.x + v.y + v.z + v.w;
        sq += v.x*v.x + v.y*v.y + v.z*v.z + v.w*v.w;
    }
    #pragma unroll
    for (int o = 16; o > 0; o >>= 1) {
        s  += __shfl_xor_sync(0xffffffffu, s,  o);
        sq += __shfl_xor_sync(0xffffffffu, sq, o);
    }
    if (lane == 0) {
        float mu  = s * (1.f / Dd);
        float var = sq * (1.f / Dd) - mu * mu;
        g_mu[row] = mu;
        g_rs[row] = rsqrtf(var + EPSV);
    }
}

// ---------------- M_raw[n] = comp @ w  ([64,512]@[512,512] per n, per half) ------
__global__ __launch_bounds__(256) void k_compgemm(
    const float* __restrict__ kcomp, const float* __restrict__ vcomp,
    const float* __restrict__ wk,    const float* __restrict__ wv)
{
    __shared__ float As[32*68];
    __shared__ float Bs[32*68];
    const int n    = blockIdx.x;
    const int half = blockIdx.y;
    const int i0   = blockIdx.z * 64;
    const float* comp = (half == 0 ? kcomp : vcomp) + (size_t)n * Rr * Dd;
    const float* w    = (half == 0 ? wk    : wv   ) + (size_t)n * Dd * Dd;
    const int tid = threadIdx.x, ty = tid >> 4, tx = tid & 15;
    const int arA = tid & 63, acA = (tid >> 6) * 8;
    const int arB = tid & 31, acB = (tid >> 5) * 8;

    float acc[4][4] = {};
    for (int k0 = 0; k0 < Dd; k0 += 32) {
        float4 a0 = *(const float4*)(comp + (size_t)arA*Dd + k0 + acA);
        float4 a1 = *(const float4*)(comp + (size_t)arA*Dd + k0 + acA + 4);
        float4 b0 = *(const float4*)(w + (size_t)(k0+arB)*Dd + i0 + acB);
        float4 b1 = *(const float4*)(w + (size_t)(k0+arB)*Dd + i0 + acB + 4);
        __syncthreads();
        As[(acA+0)*68+arA]=a0.x; As[(acA+1)*68+arA]=a0.y; As[(acA+2)*68+arA]=a0.z; As[(acA+3)*68+arA]=a0.w;
        As[(acA+4)*68+arA]=a1.x; As[(acA+5)*68+arA]=a1.y; As[(acA+6)*68+arA]=a1.z; As[(acA+7)*68+arA]=a1.w;
        *(float4*)&Bs[arB*68 + acB]     = b0;
        *(float4*)&Bs[arB*68 + acB + 4] = b1;
        __syncthreads();
        #pragma unroll
        for (int kk = 0; kk < 32; kk++) {
            float4 a  = *(const float4*)&As[kk*68 + ty*4];
            float4 bb = *(const float4*)&Bs[kk*68 + tx*4];
            float av[4] = {a.x,a.y,a.z,a.w};
            float bv[4] = {bb.x,bb.y,bb.z,bb.w};
            #pragma unroll
            for (int i = 0; i < 4; i++)
                #pragma unroll
                for (int j = 0; j < 4; j++)
                    acc[i][j] = fmaf(av[i], bv[j], acc[i][j]);
        }
    }
    #pragma unroll
    for (int i = 0; i < 4; i++) {
        int row = n*128 + half*64 + ty*4 + i;
        float4 o = make_float4(acc[i][0], acc[i][1], acc[i][2], acc[i][3]);
        *(float4*)(g_M + (size_t)row*Dd + i0 + tx*4) = o;
    }
}

// ---------------- fold LN(kv) into M; SM/CM ----------------
__global__ __launch_bounds__(256) void k_foldM(const float* __restrict__ lnw,
                                               const float* __restrict__ lnb)
{
    int row  = blockIdx.x * 8 + (threadIdx.x >> 5);   // 0..1023
    int lane = threadIdx.x & 31;
    int n = row >> 7;
    const float* lw = lnw + n*Dd;
    const float* lb = lnb + n*Dd;
    float* Mrow = g_M + (size_t)row * Dd;
    float sm = 0.f, cm = 0.f;
    for (int i = lane; i < Dd; i += 32) {
        float m = Mrow[i], w = lw[i], b = lb[i];
        sm += w * m; cm += b * m;
        Mrow[i] = w * m;
    }
    #pragma unroll
    for (int o = 16; o > 0; o >>= 1) {
        sm += __shfl_xor_sync(0xffffffffu, sm, o);
        cm += __shfl_xor_sync(0xffffffffu, cm, o);
    }
    if (lane == 0) { g_SM[row] = sm; g_CM[row] = cm; }
}

// ---------------- fold LN(q) into w_q -> g_Wq; Sq/Cq ----------------
__global__ __launch_bounds__(256) void k_foldQ(const float* __restrict__ lnw,
                                               const float* __restrict__ lnb,
                                               const float* __restrict__ wq)
{
    int row  = blockIdx.x * 8 + (threadIdx.x >> 5);   // 0..4095 = n*512+o
    int lane = threadIdx.x & 31;
    int n = row >> 9;
    const float* lw = lnw + n*Dd;
    const float* lb = lnb + n*Dd;
    const float* wr = wq + (size_t)row * Dd;
    float* dst = g_Wq + (size_t)row * Dd;
    float sm = 0.f, cm = 0.f;
    for (int i = lane; i < Dd; i += 32) {
        float m = wr[i], w = lw[i], b = lb[i];
        sm += w * m; cm += b * m;
        dst[i] = w * m;
    }
    #pragma unroll
    for (int o = 16; o > 0; o >>= 1) {
        sm += __shfl_xor_sync(0xffffffffu, sm, o);
        cm += __shfl_xor_sync(0xffffffffu, cm, o);
    }
    if (lane == 0) { g_Sq[row] = sm; g_Cq[row] = cm; }
}

// ---------------- 128x128x16 SGEMM (NT). MODE 0 = Q proj, 1 = O proj -------------
template<int MODE>
__global__ __launch_bounds__(256) void k_sgemm(
    const float* __restrict__ Ain, const float* __restrict__ Bw,
    const float* __restrict__ X, float* __restrict__ Out)
{
    __shared__ float As[16*132];
    __shared__ float Bs[16*132];
    const int m0 = blockIdx.y * 128;
    const int o0 = blockIdx.x * 128;
    const int n  = m0 >> 12;
    const int tid = threadIdx.x;
    const int ty = tid >> 4, tx = tid & 15;

    const float* A = (MODE == 1) ? (const float*)g_AO : Ain;
    const float* B = (MODE == 0) ? (const float*)g_Wq : (Bw + (size_t)n * Dd * Dd);
    if (MODE == 0) B += (size_t)n * Dd * Dd;

    const int lr = tid >> 1;
    const int lc = (tid & 1) * 8;
    const float* Ag = A + (size_t)(m0 + lr) * Dd + lc;
    const float* Bg = B + (size_t)(o0 + lr) * Dd + lc;

    float acc[8][8];
    #pragma unroll
    for (int i = 0; i < 8; i++)
        #pragma unroll
        for (int j = 0; j < 8; j++) acc[i][j] = 0.f;

    for (int k0 = 0; k0 < Dd; k0 += 16) {
        float4 a0 = *(const float4*)(Ag + k0);
        float4 a1 = *(const float4*)(Ag + k0 + 4);
        float4 b0 = *(const float4*)(Bg + k0);
        float4 b1 = *(const float4*)(Bg + k0 + 4);
        __syncthreads();
        As[(lc+0)*132+lr]=a0.x; As[(lc+1)*132+lr]=a0.y; As[(lc+2)*132+lr]=a0.z; As[(lc+3)*132+lr]=a0.w;
        As[(lc+4)*132+lr]=a1.x; As[(lc+5)*132+lr]=a1.y; As[(lc+6)*132+lr]=a1.z; As[(lc+7)*132+lr]=a1.w;
        Bs[(lc+0)*132+lr]=b0.x; Bs[(lc+1)*132+lr]=b0.y; Bs[(lc+2)*132+lr]=b0.z; Bs[(lc+3)*132+lr]=b0.w;
        Bs[(lc+4)*132+lr]=b1.x; Bs[(lc+5)*132+lr]=b1.y; Bs[(lc+6)*132+lr]=b1.z; Bs[(lc+7)*132+lr]=b1.w;
        __syncthreads();
        #pragma unroll
        for (int kk = 0; kk < 16; kk++) {
            float av[8], bv[8];
            *(float4*)&av[0] = *(const float4*)&As[kk*132 + ty*8];
            *(float4*)&av[4] = *(const float4*)&As[kk*132 + ty*8 + 4];
            *(float4*)&bv[0] = *(const float4*)&Bs[kk*132 + tx*8];
            *(float4*)&bv[4] = *(const float4*)&Bs[kk*132 + tx*8 + 4];
            #pragma unroll
            for (int i = 0; i < 8; i++)
                #pragma unroll
                for (int j = 0; j < 8; j++)
                    acc[i][j] = fmaf(av[i], bv[j], acc[i][j]);
        }
    }

    if (MODE == 0) {
        float sq[8], cq[8];
        #pragma unroll
        for (int j = 0; j < 8; j++) {
            int o = o0 + tx*8 + j;
            sq[j] = g_Sq[n*Dd + o]; cq[j] = g_Cq[n*Dd + o];
        }
        #pragma unroll
        for (int i = 0; i < 8; i++) {
            int m = m0 + ty*8 + i;
            float rsv = g_rs[m], murs = g_mu[m] * rsv;
            float r[8];
            #pragma unroll
            for (int j = 0; j < 8; j++) r[j] = rsv*acc[i][j] - murs*sq[j] + cq[j];
            *(float4*)(g_Q + (size_t)m*Dd + o0 + tx*8)     = make_float4(r[0],r[1],r[2],r[3]);
            *(float4*)(g_Q + (size_t)m*Dd + o0 + tx*8 + 4) = make_float4(r[4],r[5],r[6],r[7]);
        }
    } else {
        float mf = g_maskf[n];
        #pragma unroll
        for (int i = 0; i < 8; i++) {
            int m = m0 + ty*8 + i;
            const float* xr = X + (size_t)m*Dd + o0 + tx*8;
            float4 x0 = *(const float4*)(xr);
            float4 x1 = *(const float4*)(xr + 4);
            float4 r0, r1;
            r0.x = x0.x + mf*acc[i][0]; r0.y = x0.y + mf*acc[i][1];
            r0.z = x0.z + mf*acc[i][2]; r0.w = x0.w + mf*acc[i][3];
            r1.x = x1.x + mf*acc[i][4]; r1.y = x1.y + mf*acc[i][5];
            r1.z = x1.z + mf*acc[i][6]; r1.w = x1.w + mf*acc[i][7];
            *(float4*)(Out + (size_t)m*Dd + o0 + tx*8)     = r0;
            *(float4*)(Out + (size_t)m*Dd + o0 + tx*8 + 4) = r1;
        }
    }
}

// ---------------- fused kv-compress GEMM + LN + mask + int8 STE quant ------------
__global__ __launch_bounds__(256) void k_kvgemm(const float* __restrict__ A)
{
    __shared__ float As[16*68];
    __shared__ float Bs[16*132];
    const int m0 = blockIdx.x * 64;
    const int n  = m0 >> 12;
    const float* Bw = g_M + (size_t)n * 128 * Dd;
    const int tid = threadIdx.x;
    const int ty = tid >> 4, tx = tid & 15;

    const int lrA = tid & 63, lcA = (tid >> 6) * 4;
    const int lrB = tid >> 1, lcB = (tid & 1) * 8;
    const float* Ag = A  + (size_t)(m0 + lrA) * Dd + lcA;
    const float* Bg = Bw + (size_t)lrB * Dd + lcB;

    float acc[4][8];
    #pragma unroll
    for (int i = 0; i < 4; i++)
        #pragma unroll
        for (int j = 0; j < 8; j++) acc[i][j] = 0.f;

    for (int k0 = 0; k0 < Dd; k0 += 16) {
        float4 a0 = *(const float4*)(Ag + k0);
        float4 b0 = *(const float4*)(Bg + k0);
        float4 b1 = *(const float4*)(Bg + k0 + 4);
        __syncthreads();
        As[(lcA+0)*68+lrA]=a0.x; As[(lcA+1)*68+lrA]=a0.y; As[(lcA+2)*68+lrA]=a0.z; As[(lcA+3)*68+lrA]=a0.w;
        Bs[(lcB+0)*132+lrB]=b0.x; Bs[(lcB+1)*132+lrB]=b0.y; Bs[(lcB+2)*132+lrB]=b0.z; Bs[(lcB+3)*132+lrB]=b0.w;
        Bs[(lcB+4)*132+lrB]=b1.x; Bs[(lcB+5)*132+lrB]=b1.y; Bs[(lcB+6)*132+lrB]=b1.z; Bs[(lcB+7)*132+lrB]=b1.w;
        __syncthreads();
        #pragma unroll
        for (int kk = 0; kk < 16; kk++) {
            float av[4], bv[8];
            *(float4*)&av[0] = *(const float4*)&As[kk*68 + ty*4];
            *(float4*)&bv[0] = *(const float4*)&Bs[kk*132 + tx*8];
            *(float4*)&bv[4] = *(const float4*)&Bs[kk*132 + tx*8 + 4];
            #pragma unroll
            for (int i = 0; i < 4; i++)
                #pragma unroll
                for (int j = 0; j < 8; j++)
                    acc[i][j] = fmaf(av[i], bv[j], acc[i][j]);
        }
    }

    const float mf = g_maskf[n];
    float sm[8], cm[8];
    #pragma unroll
    for (int j = 0; j < 8; j++) {
        int o = tx*8 + j;
        sm[j] = g_SM[n*128 + o]; cm[j] = g_CM[n*128 + o];
    }
    float* dst = (tx < 8) ? g_kq : g_vq;
    int col = (tx & 7) * 8;
    #pragma unroll
    for (int i = 0; i < 4; i++) {
        int m = m0 + ty*4 + i;
        float rsv = g_rs[m], murs = g_mu[m] * rsv;
        float v[8]; float am = 0.f;
        #pragma unroll
        for (int j = 0; j < 8; j++) {
            v[j] = (rsv*acc[i][j] - murs*sm[j] + cm[j]) * mf;
            am = fmaxf(am, fabsf(v[j]));
        }
        am = fmaxf(am, __shfl_xor_sync(0xffffffffu, am, 1));
        am = fmaxf(am, __shfl_xor_sync(0xffffffffu, am, 2));
        am = fmaxf(am, __shfl_xor_sync(0xffffffffu, am, 4));
        am = fmaxf(am, 1e-8f);
        float scq = 127.f / am;
        float inv = am * (1.f / 127.f);
        float q[8];
        #pragma unroll
        for (int j = 0; j < 8; j++) q[j] = rintf(v[j] * scq) * inv;
        *(float4*)(dst + (size_t)m*64 + col)     = make_float4(q[0],q[1],q[2],q[3]);
        *(float4*)(dst + (size_t)m*64 + col + 4) = make_float4(q[4],q[5],q[6],q[7]);
    }
}

// ---------------- transpose decoders ----------------
__global__ void k_transdec(const float* __restrict__ kd, const float* __restrict__ vd)
{
    int idx = blockIdx.x * 256 + threadIdx.x;   // 32768
    int d = idx >> 6, r = idx & 63;
    g_kdecT[r*Dd + d] = kd[idx];
    g_vdecT[r*Dd + d] = vd[idx];
}

// ---------------- average over n + decompress -> K/V [B,H,T,HD] -----------------
__global__ __launch_bounds__(256) void k_decomp()
{
    __shared__ float avg[16][64];
    int bt0 = blockIdx.x * 16;
    int isv = blockIdx.y;
    const float* src = isv ? g_vq : g_kq;
    const float* dec = isv ? g_vdecT : g_kdecT;
    float* dstb = isv ? g_V : g_K;
    float invna = g_invna;
    int tid = threadIdx.x;
    #pragma unroll
    for (int j = 0; j < 4; j++) {
        int p = j*256 + tid;
        int row = p >> 6, r = p & 63;
        float s = 0.f;
        #pragma unroll
        for (int n = 0; n < Nn; n++)
            s += src[((size_t)(n*BTc + bt0 + row))*64 + r];
        avg[row][r] = s * invna;
    }
    __syncthreads();
    int d0 = tid * 2;
    float2 acc[16];
    #pragma unroll
    for (int row = 0; row < 16; row++) { acc[row].x = 0.f; acc[row].y = 0.f; }
    for (int r = 0; r < 64; r++) {
        float2 kd = *(const float2*)(dec + r*Dd + d0);
        #pragma unroll
        for (int row = 0; row < 16; row++) {
            float a = avg[row][r];
            acc[row].x = fmaf(a, kd.x, acc[row].x);
            acc[row].y = fmaf(a, kd.y, acc[row].y);
        }
    }
    float sc = isv ? 1.f : INV_SQRT_HD;
    int h = d0 >> 7, hd = d0 & 127;
    #pragma unroll
    for (int row = 0; row < 16; row++) {
        int bt = bt0 + row;
        int b = bt >> 10, t = bt & 1023;
        float* dst = dstb + (((size_t)(b*Hh+h)*Tt + t)*HDc + hd);
        dst[0] = acc[row].x * sc;
        dst[1] = acc[row].y * sc;
    }
}

// ---------------- causal flash attention: 64 q-rows/block, 32 kv/tile ------------
__global__ __launch_bounds__(256) void k_flash()
{
    extern __shared__ float smem[];
    float* Qs = smem;               // [64][132]
    float* Ks = Qs + 64*132;        // [32][132]
    float* Vs = Ks + 32*132;        // [32][132]
    float* Ps = Vs + 32*132;        // [64][33]
    int nbh = blockIdx.y;
    int n = nbh >> 4, b = (nbh >> 2) & 3, h = nbh & 3;
    int qt = blockIdx.x;
    int tid = threadIdx.x;
    int qp = tid >> 3, kg = tid & 7;
    int q0 = qt * 64;
    size_t qbase  = ((size_t)(n*Bb + b)*Tt + q0) * Dd + h*HDc;
    size_t kvbase = (size_t)(b*Hh + h) * Tt * HDc;

    for (int idx = tid; idx < 64*32; idx += 256) {
        int r = idx >> 5, c = idx & 31;
        *(float4*)&Qs[r*132 + c*4] = *(const float4*)(g_Q + qbase + (size_t)r*Dd + c*4);
    }

    float accO[2][16];
    #pragma unroll
    for (int i = 0; i < 2; i++)
        #pragma unroll
        for (int j = 0; j < 16; j++) accO[i][j] = 0.f;
    float mrow[2] = {-1e30f, -1e30f};
    float lrow[2] = {0.f, 0.f};

    int ntiles = 2*qt + 2;
    for (int kt = 0; kt < ntiles; kt++) {
        int k0 = kt * 32;
        __syncthreads();
        for (int idx = tid; idx < 32*32; idx += 256) {
            int r = idx >> 5, c = idx & 31;
            *(float4*)&Ks[r*132 + c*4] = *(const float4*)(g_K + kvbase + (size_t)(k0+r)*HDc + c*4);
            *(float4*)&Vs[r*132 + c*4] = *(const float4*)(g_V + kvbase + (size_t)(k0+r)*HDc + c*4);
        }
        __syncthreads();

        float s[2][4];
        #pragma unroll
        for (int i = 0; i < 2; i++)
            #pragma unroll
            for (int j = 0; j < 4; j++) s[i][j] = 0.f;
        #pragma unroll 8
        for (int c = 0; c < 32; c++) {
            float4 qa = *(const float4*)&Qs[(2*qp)*132 + c*4];
            float4 qb = *(const float4*)&Qs[(2*qp+1)*132 + c*4];
            #pragma unroll
            for (int j = 0; j < 4; j++) {
                float4 kv = *(const float4*)&Ks[(kg + 8*j)*132 + c*4];
                s[0][j] = fmaf(qa.x, kv.x, s[0][j]); s[0][j] = fmaf(qa.y, kv.y, s[0][j]);
                s[0][j] = fmaf(qa.z, kv.z, s[0][j]); s[0][j] = fmaf(qa.w, kv.w, s[0][j]);
                s[1][j] = fmaf(qb.x, kv.x, s[1][j]); s[1][j] = fmaf(qb.y, kv.y, s[1][j]);
                s[1][j] = fmaf(qb.z, kv.z, s[1][j]); s[1][j] = fmaf(qb.w, kv.w, s[1][j]);
            }
        }
        #pragma unroll
        for (int qi = 0; qi < 2; qi++) {
            int qg = q0 + 2*qp + qi;
            float tm = -1e30f;
            #pragma unroll
            for (int j = 0; j < 4; j++) {
                int kgi = k0 + kg + 8*j;
                if (kgi > qg) s[qi][j] = -1e30f;
                tm = fmaxf(tm, s[qi][j]);
            }
            tm = fmaxf(tm, __shfl_xor_sync(0xffffffffu, tm, 1));
            tm = fmaxf(tm, __shfl_xor_sync(0xffffffffu, tm, 2));
            tm = fmaxf(tm, __shfl_xor_sync(0xffffffffu, tm, 4));
            float mnew = fmaxf(mrow[qi], tm);
            float scale = exp2f((mrow[qi] - mnew) * L2E);
            float psum = 0.f;
            #pragma unroll
            for (int j = 0; j < 4; j++) {
                float p = exp2f((s[qi][j] - mnew) * L2E);
                Ps[(2*qp + qi)*33 + kg + 8*j] = p;
                psum += p;
            }
            psum += __shfl_xor_sync(0xffffffffu, psum, 1);
            psum += __shfl_xor_sync(0xffffffffu, psum, 2);
            psum += __shfl_xor_sync(0xffffffffu, psum, 4);
            lrow[qi] = lrow[qi] * scale + psum;
            mrow[qi] = mnew;
            #pragma unroll
            for (int j = 0; j < 16; j++) accO[qi][j] *= scale;
        }
        __syncthreads();
        #pragma unroll 4
        for (int k = 0; k < 32; k++) {
            float p0 = Ps[(2*qp)*33 + k];
            float p1 = Ps[(2*qp+1)*33 + k];
            #pragma unroll
            for (int u = 0; u < 4; u++) {
                float4 vv = *(const float4*)&Vs[k*132 + kg*16 + u*4];
                accO[0][u*4+0] = fmaf(p0, vv.x, accO[0][u*4+0]);
                accO[0][u*4+1] = fmaf(p0, vv.y, accO[0][u*4+1]);
                accO[0][u*4+2] = fmaf(p0, vv.z, accO[0][u*4+2]);
                accO[0][u*4+3] = fmaf(p0, vv.w, accO[0][u*4+3]);
                accO[1][u*4+0] = fmaf(p1, vv.x, accO[1][u*4+0]);
                accO[1][u*4+1] = fmaf(p1, vv.y, accO[1][u*4+1]);
                accO[1][u*4+2] = fmaf(p1, vv.z, accO[1][u*4+2]);
                accO[1][u*4+3] = fmaf(p1, vv.w, accO[1][u*4+3]);
            }
        }
    }

    #pragma unroll
    for (int qi = 0; qi < 2; qi++) {
        float inv = 1.f / lrow[qi];
        size_t row = (size_t)(n*Bb + b)*Tt + q0 + 2*qp + qi;
        float* dst = g_AO + row*Dd + h*HDc + kg*16;
        #pragma unroll
        for (int u = 0; u < 4; u++) {
            float4 o = make_float4(accO[qi][u*4+0]*inv, accO[qi][u*4+1]*inv,
                                   accO[qi][u*4+2]*inv, accO[qi][u*4+3]*inv);
            *(float4*)(dst + u*4) = o;
        }
    }
}

// ---------------- launch ----------------
extern "C" void kernel_launch(void* const* d_in, const int* in_sizes, int n_in,
                              void* d_out, int out_size)
{
    (void)in_sizes; (void)n_in; (void)out_size;
    const float* x     = (const float*)d_in[0];
    const unsigned char* mask = (const unsigned char*)d_in[1];
    const float* lnkw  = (const float*)d_in[2];
    const float* lnkb  = (const float*)d_in[3];
    const float* lnqw  = (const float*)d_in[4];
    const float* lnqb  = (const float*)d_in[5];
    const float* wk    = (const float*)d_in[6];
    const float* wv    = (const float*)d_in[7];
    const float* wq    = (const float*)d_in[8];
    const float* wo    = (const float*)d_in[9];
    const float* kcomp = (const float*)d_in[10];
    const float* vcomp = (const float*)d_in[11];
    const float* kdec  = (const float*)d_in[12];
    const float* vdec  = (const float*)d_in[13];
    float* out = (float*)d_out;

    static bool attr_done = false;
    if (!attr_done) {
        cudaFuncSetAttribute(k_flash, cudaFuncAttributeMaxDynamicSharedMemorySize, 76032);
        attr_done = true;
    }

    k_mask<<<1, 32>>>(mask);
    k_lnstats<<<NROWS/8, 256>>>(x);
    k_compgemm<<<dim3(Nn, 2, 8), 256>>>(kcomp, vcomp, wk, wv);
    k_foldM<<<Nn*128/8, 256>>>(lnkw, lnkb);
    k_foldQ<<<Nn*Dd/8, 256>>>(lnqw, lnqb, wq);
    k_sgemm<0><<<dim3(4, NROWS/128), 256>>>(x, nullptr, nullptr, nullptr);
    k_kvgemm<<<NROWS/64, 256>>>(x);
    k_transdec<<<128, 256>>>(kdec, vdec);
    k_decomp<<<dim3(BTc/16, 2), 256>>>();
    k_flash<<<dim3(Tt/64, Nn*Bb*Hh), 256, 76032>>>();
    k_sgemm<1><<<dim3(4, NROWS/128), 256>>>(nullptr, wo, x, out);
}

// round 3
// speedup vs baseline: 1.2072x; 1.2072x over previous
#include <cuda_runtime.h>
#include <cuda_bf16.h>
#include <cstdint>
#include <cstddef>

#define Nn 8
#define Bb 4
#define Tt 1024
#define Dd 512
#define Hh 4
#define HDc 128
#define Rr 64
#define BTc (Bb*Tt)
#define NROWS (Nn*BTc)
#define EPSV 1e-5f
#define INV_SQRT_HD 0.08838834764831845f
#define L2E 1.4426950408889634f

// ---------------- device scratch ----------------
__device__ float g_mu[NROWS];
__device__ float g_rs[NROWS];
__device__ float g_maskf[Nn];
__device__ float g_invna;
__device__ float g_Wq[Nn*Dd*Dd];
__device__ float g_Sq[Nn*Dd];
__device__ float g_Cq[Nn*Dd];
__device__ float g_M[Nn*128*Dd];   // rows 0-63: k_comp@w_k (folded), 64-127: v_comp@w_v
__device__ float g_SM[Nn*128];
__device__ float g_CM[Nn*128];
__device__ float g_kq[(size_t)NROWS*Rr];
__device__ float g_vq[(size_t)NROWS*Rr];
__device__ float g_kdecT[Rr*Dd];
__device__ float g_vdecT[Rr*Dd];
__device__ float g_K[(size_t)Bb*Hh*Tt*HDc];
__device__ float g_V[(size_t)Bb*Hh*Tt*HDc];
__device__ float g_Q[(size_t)NROWS*Dd];
__device__ float g_AO[(size_t)NROWS*Dd];

// ---------------- mma helpers ----------------
__device__ __forceinline__ uint32_t pk2(float x, float y)
{
    __nv_bfloat162 h = __float22bfloat162_rn(make_float2(x, y));
    return *reinterpret_cast<uint32_t*>(&h);
}

__device__ __forceinline__ void ldsm4(uint32_t* r, const __nv_bfloat16* p)
{
    uint32_t a = (uint32_t)__cvta_generic_to_shared((void*)p);
    asm volatile("ldmatrix.sync.aligned.m8n8.x4.shared.b16 {%0,%1,%2,%3}, [%4];\n"
                 : "=r"(r[0]), "=r"(r[1]), "=r"(r[2]), "=r"(r[3]) : "r"(a));
}

__device__ __forceinline__ void mmabf(float* d, const uint32_t* a, uint32_t b0, uint32_t b1)
{
    asm volatile("mma.sync.aligned.m16n8k16.row.col.f32.bf16.bf16.f32 "
                 "{%0,%1,%2,%3},{%4,%5,%6,%7},{%8,%9},{%0,%1,%2,%3};\n"
                 : "+f"(d[0]), "+f"(d[1]), "+f"(d[2]), "+f"(d[3])
                 : "r"(a[0]), "r"(a[1]), "r"(a[2]), "r"(a[3]), "r"(b0), "r"(b1));
}

// ---------------- mask decode (bool8 / int32 / float32) ----------------
__global__ void k_mask(const unsigned char* __restrict__ p)
{
    if (threadIdx.x == 0) {
        bool isF = (p[0]==0 && p[1]==0 && p[2]==0x80 && p[3]==0x3f);
        bool isI = (!isF && p[1]==0 && p[2]==0 && p[3]==0 && (p[4]!=0 || p[5]==0));
        float na = 0.f;
        for (int n = 0; n < Nn; n++) {
            bool bit;
            if (isF)      bit = (((const float*)p)[n] != 0.f);
            else if (isI) bit = (((const int*)p)[n]   != 0);
            else          bit = (p[n] != 0);
            g_maskf[n] = bit ? 1.f : 0.f;
            na += bit ? 1.f : 0.f;
        }
        g_invna = 1.f / fmaxf(na, 1.f);
    }
}

// ---------------- LN row stats: one warp per row ----------------
__global__ __launch_bounds__(256) void k_lnstats(const float* __restrict__ x)
{
    int row  = blockIdx.x * 8 + (threadIdx.x >> 5);
    int lane = threadIdx.x & 31;
    const float4* xp = (const float4*)(x + (size_t)row * Dd);
    float s = 0.f, sq = 0.f;
    #pragma unroll
    for (int i = 0; i < 4; i++) {
        float4 v = xp[lane + 32*i];
        s  += v.x + v.y + v.z + v.w;
        sq += v.x*v.x + v.y*v.y + v.z*v.z + v.w*v.w;
    }
    #pragma unroll
    for (int o = 16; o > 0; o >>= 1) {
        s  += __shfl_xor_sync(0xffffffffu, s,  o);
        sq += __shfl_xor_sync(0xffffffffu, sq, o);
    }
    if (lane == 0) {
        float mu  = s * (1.f / Dd);
        float var = sq * (1.f / Dd) - mu * mu;
        g_mu[row] = mu;
        g_rs[row] = rsqrtf(var + EPSV);
    }
}

// ---------------- M_raw[n] = comp @ w  ([64,512]@[512,512] per n, per half) ------
__global__ __launch_bounds__(256) void k_compgemm(
    const float* __restrict__ kcomp, const float* __restrict__ vcomp,
    const float* __restrict__ wk,    const float* __restrict__ wv)
{
    __shared__ float As[32*68];
    __shared__ float Bs[32*68];
    const int n    = blockIdx.x;
    const int half = blockIdx.y;
    const int i0   = blockIdx.z * 64;
    const float* comp = (half == 0 ? kcomp : vcomp) + (size_t)n * Rr * Dd;
    const float* w    = (half == 0 ? wk    : wv   ) + (size_t)n * Dd * Dd;
    const int tid = threadIdx.x, ty = tid >> 4, tx = tid & 15;
    const int arA = tid & 63, acA = (tid >> 6) * 8;
    const int arB = tid & 31, acB = (tid >> 5) * 8;

    float acc[4][4] = {};
    for (int k0 = 0; k0 < Dd; k0 += 32) {
        float4 a0 = *(const float4*)(comp + (size_t)arA*Dd + k0 + acA);
        float4 a1 = *(const float4*)(comp + (size_t)arA*Dd + k0 + acA + 4);
        float4 b0 = *(const float4*)(w + (size_t)(k0+arB)*Dd + i0 + acB);
        float4 b1 = *(const float4*)(w + (size_t)(k0+arB)*Dd + i0 + acB + 4);
        __syncthreads();
        As[(acA+0)*68+arA]=a0.x; As[(acA+1)*68+arA]=a0.y; As[(acA+2)*68+arA]=a0.z; As[(acA+3)*68+arA]=a0.w;
        As[(acA+4)*68+arA]=a1.x; As[(acA+5)*68+arA]=a1.y; As[(acA+6)*68+arA]=a1.z; As[(acA+7)*68+arA]=a1.w;
        *(float4*)&Bs[arB*68 + acB]     = b0;
        *(float4*)&Bs[arB*68 + acB + 4] = b1;
        __syncthreads();
        #pragma unroll
        for (int kk = 0; kk < 32; kk++) {
            float4 a  = *(const float4*)&As[kk*68 + ty*4];
            float4 bb = *(const float4*)&Bs[kk*68 + tx*4];
            float av[4] = {a.x,a.y,a.z,a.w};
            float bv[4] = {bb.x,bb.y,bb.z,bb.w};
            #pragma unroll
            for (int i = 0; i < 4; i++)
                #pragma unroll
                for (int j = 0; j < 4; j++)
                    acc[i][j] = fmaf(av[i], bv[j], acc[i][j]);
        }
    }
    #pragma unroll
    for (int i = 0; i < 4; i++) {
        int row = n*128 + half*64 + ty*4 + i;
        float4 o = make_float4(acc[i][0], acc[i][1], acc[i][2], acc[i][3]);
        *(float4*)(g_M + (size_t)row*Dd + i0 + tx*4) = o;
    }
}

// ---------------- fold LN(kv) into M; SM/CM ----------------
__global__ __launch_bounds__(256) void k_foldM(const float* __restrict__ lnw,
                                               const float* __restrict__ lnb)
{
    int row  = blockIdx.x * 8 + (threadIdx.x >> 5);
    int lane = threadIdx.x & 31;
    int n = row >> 7;
    const float* lw = lnw + n*Dd;
    const float* lb = lnb + n*Dd;
    float* Mrow = g_M + (size_t)row * Dd;
    float sm = 0.f, cm = 0.f;
    for (int i = lane; i < Dd; i += 32) {
        float m = Mrow[i], w = lw[i], b = lb[i];
        sm += w * m; cm += b * m;
        Mrow[i] = w * m;
    }
    #pragma unroll
    for (int o = 16; o > 0; o >>= 1) {
        sm += __shfl_xor_sync(0xffffffffu, sm, o);
        cm += __shfl_xor_sync(0xffffffffu, cm, o);
    }
    if (lane == 0) { g_SM[row] = sm; g_CM[row] = cm; }
}

// ---------------- fold LN(q) into w_q -> g_Wq; Sq/Cq ----------------
__global__ __launch_bounds__(256) void k_foldQ(const float* __restrict__ lnw,
                                               const float* __restrict__ lnb,
                                               const float* __restrict__ wq)
{
    int row  = blockIdx.x * 8 + (threadIdx.x >> 5);
    int lane = threadIdx.x & 31;
    int n = row >> 9;
    const float* lw = lnw + n*Dd;
    const float* lb = lnb + n*Dd;
    const float* wr = wq + (size_t)row * Dd;
    float* dst = g_Wq + (size_t)row * Dd;
    float sm = 0.f, cm = 0.f;
    for (int i = lane; i < Dd; i += 32) {
        float m = wr[i], w = lw[i], b = lb[i];
        sm += w * m; cm += b * m;
        dst[i] = w * m;
    }
    #pragma unroll
    for (int o = 16; o > 0; o >>= 1) {
        sm += __shfl_xor_sync(0xffffffffu, sm, o);
        cm += __shfl_xor_sync(0xffffffffu, cm, o);
    }
    if (lane == 0) { g_Sq[row] = sm; g_Cq[row] = cm; }
}

// ---------------- bf16 tensor-core GEMM 128x128xK512. MODE 0 = Q, 1 = O ---------
template<int MODE>
__global__ __launch_bounds__(256) void k_hgemm(
    const float* __restrict__ Ain, const float* __restrict__ Bw,
    const float* __restrict__ X, float* __restrict__ Out)
{
    __shared__ __nv_bfloat16 As[2][128*40];
    __shared__ __nv_bfloat16 Bs[2][128*40];
    const int m0 = blockIdx.y * 128;
    const int o0 = blockIdx.x * 128;
    const int n  = m0 >> 12;
    const float* A = (MODE == 1) ? (const float*)g_AO : Ain;
    const float* B = ((MODE == 0) ? (const float*)g_Wq : Bw) + (size_t)n * Dd * Dd;

    const int tid = threadIdx.x, lane = tid & 31, warp = tid >> 5;
    const int wm = warp & 3, wn = warp >> 2;

    // global->smem: thread t loads row = t>>1, 16 floats at kc = (t&1)*16
    const int lr = tid >> 1, lkc = (tid & 1) * 16;
    const float* Ag = A + (size_t)(m0 + lr) * Dd + lkc;
    const float* Bg = B + (size_t)(o0 + lr) * Dd + lkc;

    float4 fa[4], fb[4];
    #pragma unroll
    for (int i = 0; i < 4; i++) {
        fa[i] = *(const float4*)(Ag + i*4);
        fb[i] = *(const float4*)(Bg + i*4);
    }

    auto stg = [&](int st) {
        __nv_bfloat16* pa = &As[st][lr*40 + lkc];
        __nv_bfloat16* pb = &Bs[st][lr*40 + lkc];
        ((uint4*)pa)[0] = make_uint4(pk2(fa[0].x,fa[0].y), pk2(fa[0].z,fa[0].w),
                                     pk2(fa[1].x,fa[1].y), pk2(fa[1].z,fa[1].w));
        ((uint4*)pa)[1] = make_uint4(pk2(fa[2].x,fa[2].y), pk2(fa[2].z,fa[2].w),
                                     pk2(fa[3].x,fa[3].y), pk2(fa[3].z,fa[3].w));
        ((uint4*)pb)[0] = make_uint4(pk2(fb[0].x,fb[0].y), pk2(fb[0].z,fb[0].w),
                                     pk2(fb[1].x,fb[1].y), pk2(fb[1].z,fb[1].w));
        ((uint4*)pb)[1] = make_uint4(pk2(fb[2].x,fb[2].y), pk2(fb[2].z,fb[2].w),
                                     pk2(fb[3].x,fb[3].y), pk2(fb[3].z,fb[3].w));
    };

    stg(0);
    __syncthreads();

    float acc[2][8][4];
    #pragma unroll
    for (int i = 0; i < 2; i++)
        #pragma unroll
        for (int j = 0; j < 8; j++)
            #pragma unroll
            for (int k = 0; k < 4; k++) acc[i][j][k] = 0.f;

    // lane addressing for ldmatrix (element offsets, bf16 units, row stride 40)
    const int arow = wm*32 + (lane & 15);
    const int acol = ((lane >> 4) & 1) * 8;
    const int brow = wn*64 + (lane & 7) + ((lane >> 4) & 1) * 8;
    const int bcol = ((lane >> 3) & 1) * 8;

    for (int ks = 0; ks < 16; ks++) {
        int st = ks & 1;
        if (ks < 15) {
            #pragma unroll
            for (int i = 0; i < 4; i++) {
                fa[i] = *(const float4*)(Ag + (ks+1)*32 + i*4);
                fb[i] = *(const float4*)(Bg + (ks+1)*32 + i*4);
            }
        }
        const __nv_bfloat16* Asb = As[st];
        const __nv_bfloat16* Bsb = Bs[st];

        uint32_t af[2][2][4];
        #pragma unroll
        for (int mf = 0; mf < 2; mf++)
            #pragma unroll
            for (int kf = 0; kf < 2; kf++)
                ldsm4(af[mf][kf], Asb + (arow + mf*16)*40 + kf*16 + acol);

        #pragma unroll
        for (int ng = 0; ng < 4; ng++) {
            uint32_t bfr[2][4];
            #pragma unroll
            for (int kf = 0; kf < 2; kf++)
                ldsm4(bfr[kf], Bsb + (brow + ng*16)*40 + kf*16 + bcol);
            #pragma unroll
            for (int s = 0; s < 2; s++) {
                int nf = ng*2 + s;
                #pragma unroll
                for (int mf = 0; mf < 2; mf++) {
                    mmabf(acc[mf][nf], af[mf][0], bfr[0][2*s], bfr[0][2*s+1]);
                    mmabf(acc[mf][nf], af[mf][1], bfr[1][2*s], bfr[1][2*s+1]);
                }
            }
        }
        __syncthreads();
        if (ks < 15) { stg(st ^ 1); __syncthreads(); }
    }

    // epilogue
    const int mrow = m0 + wm*32 + (lane >> 2);
    const int ocol = o0 + wn*64 + (lane & 3)*2;
    if (MODE == 0) {
        #pragma unroll
        for (int mf = 0; mf < 2; mf++) {
            int r0 = mrow + mf*16, r1 = r0 + 8;
            float rs0 = g_rs[r0], mr0 = g_mu[r0]*rs0;
            float rs1 = g_rs[r1], mr1 = g_mu[r1]*rs1;
            #pragma unroll
            for (int nf = 0; nf < 8; nf++) {
                int c = ocol + nf*8;
                float sq0 = g_Sq[n*Dd + c], sq1 = g_Sq[n*Dd + c + 1];
                float cq0 = g_Cq[n*Dd + c], cq1 = g_Cq[n*Dd + c + 1];
                float* d = acc[mf][nf];
                *(float2*)(g_Q + (size_t)r0*Dd + c) =
                    make_float2(rs0*d[0] - mr0*sq0 + cq0, rs0*d[1] - mr0*sq1 + cq1);
                *(float2*)(g_Q + (size_t)r1*Dd + c) =
                    make_float2(rs1*d[2] - mr1*sq0 + cq0, rs1*d[3] - mr1*sq1 + cq1);
            }
        }
    } else {
        float mfv = g_maskf[n];
        #pragma unroll
        for (int mf = 0; mf < 2; mf++) {
            int r0 = mrow + mf*16, r1 = r0 + 8;
            #pragma unroll
            for (int nf = 0; nf < 8; nf++) {
                int c = ocol + nf*8;
                float* d = acc[mf][nf];
                float2 x0 = *(const float2*)(X + (size_t)r0*Dd + c);
                float2 x1 = *(const float2*)(X + (size_t)r1*Dd + c);
                *(float2*)(Out + (size_t)r0*Dd + c) =
                    make_float2(x0.x + mfv*d[0], x0.y + mfv*d[1]);
                *(float2*)(Out + (size_t)r1*Dd + c) =
                    make_float2(x1.x + mfv*d[2], x1.y + mfv*d[3]);
            }
        }
    }
}

// ---------------- fused kv-compress GEMM + LN + mask + int8 STE quant ------------
__global__ __launch_bounds__(256) void k_kvgemm(const float* __restrict__ A)
{
    __shared__ float As[16*68];
    __shared__ float Bs[16*132];
    const int m0 = blockIdx.x * 64;
    const int n  = m0 >> 12;
    const float* Bw = g_M + (size_t)n * 128 * Dd;
    const int tid = threadIdx.x;
    const int ty = tid >> 4, tx = tid & 15;

    const int lrA = tid & 63, lcA = (tid >> 6) * 4;
    const int lrB = tid >> 1, lcB = (tid & 1) * 8;
    const float* Ag = A  + (size_t)(m0 + lrA) * Dd + lcA;
    const float* Bg = Bw + (size_t)lrB * Dd + lcB;

    float acc[4][8];
    #pragma unroll
    for (int i = 0; i < 4; i++)
        #pragma unroll
        for (int j = 0; j < 8; j++) acc[i][j] = 0.f;

    for (int k0 = 0; k0 < Dd; k0 += 16) {
        float4 a0 = *(const float4*)(Ag + k0);
        float4 b0 = *(const float4*)(Bg + k0);
        float4 b1 = *(const float4*)(Bg + k0 + 4);
        __syncthreads();
        As[(lcA+0)*68+lrA]=a0.x; As[(lcA+1)*68+lrA]=a0.y; As[(lcA+2)*68+lrA]=a0.z; As[(lcA+3)*68+lrA]=a0.w;
        Bs[(lcB+0)*132+lrB]=b0.x; Bs[(lcB+1)*132+lrB]=b0.y; Bs[(lcB+2)*132+lrB]=b0.z; Bs[(lcB+3)*132+lrB]=b0.w;
        Bs[(lcB+4)*132+lrB]=b1.x; Bs[(lcB+5)*132+lrB]=b1.y; Bs[(lcB+6)*132+lrB]=b1.z; Bs[(lcB+7)*132+lrB]=b1.w;
        __syncthreads();
        #pragma unroll
        for (int kk = 0; kk < 16; kk++) {
            float av[4], bv[8];
            *(float4*)&av[0] = *(const float4*)&As[kk*68 + ty*4];
            *(float4*)&bv[0] = *(const float4*)&Bs[kk*132 + tx*8];
            *(float4*)&bv[4] = *(const float4*)&Bs[kk*132 + tx*8 + 4];
            #pragma unroll
            for (int i = 0; i < 4; i++)
                #pragma unroll
                for (int j = 0; j < 8; j++)
                    acc[i][j] = fmaf(av[i], bv[j], acc[i][j]);
        }
    }

    const float mf = g_maskf[n];
    float sm[8], cm[8];
    #pragma unroll
    for (int j = 0; j < 8; j++) {
        int o = tx*8 + j;
        sm[j] = g_SM[n*128 + o]; cm[j] = g_CM[n*128 + o];
    }
    float* dst = (tx < 8) ? g_kq : g_vq;
    int col = (tx & 7) * 8;
    #pragma unroll
    for (int i = 0; i < 4; i++) {
        int m = m0 + ty*4 + i;
        float rsv = g_rs[m], murs = g_mu[m] * rsv;
        float v[8]; float am = 0.f;
        #pragma unroll
        for (int j = 0; j < 8; j++) {
            v[j] = (rsv*acc[i][j] - murs*sm[j] + cm[j]) * mf;
            am = fmaxf(am, fabsf(v[j]));
        }
        am = fmaxf(am, __shfl_xor_sync(0xffffffffu, am, 1));
        am = fmaxf(am, __shfl_xor_sync(0xffffffffu, am, 2));
        am = fmaxf(am, __shfl_xor_sync(0xffffffffu, am, 4));
        am = fmaxf(am, 1e-8f);
        float scq = 127.f / am;
        float inv = am * (1.f / 127.f);
        float q[8];
        #pragma unroll
        for (int j = 0; j < 8; j++) q[j] = rintf(v[j] * scq) * inv;
        *(float4*)(dst + (size_t)m*64 + col)     = make_float4(q[0],q[1],q[2],q[3]);
        *(float4*)(dst + (size_t)m*64 + col + 4) = make_float4(q[4],q[5],q[6],q[7]);
    }
}

// ---------------- transpose decoders ----------------
__global__ void k_transdec(const float* __restrict__ kd, const float* __restrict__ vd)
{
    int idx = blockIdx.x * 256 + threadIdx.x;
    int d = idx >> 6, r = idx & 63;
    g_kdecT[r*Dd + d] = kd[idx];
    g_vdecT[r*Dd + d] = vd[idx];
}

// ---------------- average over n + decompress -> K/V [B,H,T,HD] -----------------
__global__ __launch_bounds__(256) void k_decomp()
{
    __shared__ float avg[16][64];
    int bt0 = blockIdx.x * 16;
    int isv = blockIdx.y;
    const float* src = isv ? g_vq : g_kq;
    const float* dec = isv ? g_vdecT : g_kdecT;
    float* dstb = isv ? g_V : g_K;
    float invna = g_invna;
    int tid = threadIdx.x;
    #pragma unroll
    for (int j = 0; j < 4; j++) {
        int p = j*256 + tid;
        int row = p >> 6, r = p & 63;
        float s = 0.f;
        #pragma unroll
        for (int n = 0; n < Nn; n++)
            s += src[((size_t)(n*BTc + bt0 + row))*64 + r];
        avg[row][r] = s * invna;
    }
    __syncthreads();
    int d0 = tid * 2;
    float2 acc[16];
    #pragma unroll
    for (int row = 0; row < 16; row++) { acc[row].x = 0.f; acc[row].y = 0.f; }
    for (int r = 0; r < 64; r++) {
        float2 kd = *(const float2*)(dec + r*Dd + d0);
        #pragma unroll
        for (int row = 0; row < 16; row++) {
            float a = avg[row][r];
            acc[row].x = fmaf(a, kd.x, acc[row].x);
            acc[row].y = fmaf(a, kd.y, acc[row].y);
        }
    }
    float sc = isv ? 1.f : INV_SQRT_HD;
    int h = d0 >> 7, hd = d0 & 127;
    #pragma unroll
    for (int row = 0; row < 16; row++) {
        int bt = bt0 + row;
        int b = bt >> 10, t = bt & 1023;
        float* dst = dstb + (((size_t)(b*Hh+h)*Tt + t)*HDc + hd);
        dst[0] = acc[row].x * sc;
        dst[1] = acc[row].y * sc;
    }
}

// ---------------- causal flash attention (fp32, unchanged) ----------------
__global__ __launch_bounds__(256) void k_flash()
{
    extern __shared__ float smem[];
    float* Qs = smem;               // [64][132]
    float* Ks = Qs + 64*132;        // [32][132]
    float* Vs = Ks + 32*132;        // [32][132]
    float* Ps = Vs + 32*132;        // [64][33]
    int nbh = blockIdx.y;
    int n = nbh >> 4, b = (nbh >> 2) & 3, h = nbh & 3;
    int qt = blockIdx.x;
    int tid = threadIdx.x;
    int qp = tid >> 3, kg = tid & 7;
    int q0 = qt * 64;
    size_t qbase  = ((size_t)(n*Bb + b)*Tt + q0) * Dd + h*HDc;
    size_t kvbase = (size_t)(b*Hh + h) * Tt * HDc;

    for (int idx = tid; idx < 64*32; idx += 256) {
        int r = idx >> 5, c = idx & 31;
        *(float4*)&Qs[r*132 + c*4] = *(const float4*)(g_Q + qbase + (size_t)r*Dd + c*4);
    }

    float accO[2][16];
    #pragma unroll
    for (int i = 0; i < 2; i++)
        #pragma unroll
        for (int j = 0; j < 16; j++) accO[i][j] = 0.f;
    float mrow[2] = {-1e30f, -1e30f};
    float lrow[2] = {0.f, 0.f};

    int ntiles = 2*qt + 2;
    for (int kt = 0; kt < ntiles; kt++) {
        int k0 = kt * 32;
        __syncthreads();
        for (int idx = tid; idx < 32*32; idx += 256) {
            int r = idx >> 5, c = idx & 31;
            *(float4*)&Ks[r*132 + c*4] = *(const float4*)(g_K + kvbase + (size_t)(k0+r)*HDc + c*4);
            *(float4*)&Vs[r*132 + c*4] = *(const float4*)(g_V + kvbase + (size_t)(k0+r)*HDc + c*4);
        }
        __syncthreads();

        float s[2][4];
        #pragma unroll
        for (int i = 0; i < 2; i++)
            #pragma unroll
            for (int j = 0; j < 4; j++) s[i][j] = 0.f;
        #pragma unroll 8
        for (int c = 0; c < 32; c++) {
            float4 qa = *(const float4*)&Qs[(2*qp)*132 + c*4];
            float4 qb = *(const float4*)&Qs[(2*qp+1)*132 + c*4];
            #pragma unroll
            for (int j = 0; j < 4; j++) {
                float4 kv = *(const float4*)&Ks[(kg + 8*j)*132 + c*4];
                s[0][j] = fmaf(qa.x, kv.x, s[0][j]); s[0][j] = fmaf(qa.y, kv.y, s[0][j]);
                s[0][j] = fmaf(qa.z, kv.z, s[0][j]); s[0][j] = fmaf(qa.w, kv.w, s[0][j]);
                s[1][j] = fmaf(qb.x, kv.x, s[1][j]); s[1][j] = fmaf(qb.y, kv.y, s[1][j]);
                s[1][j] = fmaf(qb.z, kv.z, s[1][j]); s[1][j] = fmaf(qb.w, kv.w, s[1][j]);
            }
        }
        #pragma unroll
        for (int qi = 0; qi < 2; qi++) {
            int qg = q0 + 2*qp + qi;
            float tm = -1e30f;
            #pragma unroll
            for (int j = 0; j < 4; j++) {
                int kgi = k0 + kg + 8*j;
                if (kgi > qg) s[qi][j] = -1e30f;
                tm = fmaxf(tm, s[qi][j]);
            }
            tm = fmaxf(tm, __shfl_xor_sync(0xffffffffu, tm, 1));
            tm = fmaxf(tm, __shfl_xor_sync(0xffffffffu, tm, 2));
            tm = fmaxf(tm, __shfl_xor_sync(0xffffffffu, tm, 4));
            float mnew = fmaxf(mrow[qi], tm);
            float scale = exp2f((mrow[qi] - mnew) * L2E);
            float psum = 0.f;
            #pragma unroll
            for (int j = 0; j < 4; j++) {
                float p = exp2f((s[qi][j] - mnew) * L2E);
                Ps[(2*qp + qi)*33 + kg + 8*j] = p;
                psum += p;
            }
            psum += __shfl_xor_sync(0xffffffffu, psum, 1);
            psum += __shfl_xor_sync(0xffffffffu, psum, 2);
            psum += __shfl_xor_sync(0xffffffffu, psum, 4);
            lrow[qi] = lrow[qi] * scale + psum;
            mrow[qi] = mnew;
            #pragma unroll
            for (int j = 0; j < 16; j++) accO[qi][j] *= scale;
        }
        __syncthreads();
        #pragma unroll 4
        for (int k = 0; k < 32; k++) {
            float p0 = Ps[(2*qp)*33 + k];
            float p1 = Ps[(2*qp+1)*33 + k];
            #pragma unroll
            for (int u = 0; u < 4; u++) {
                float4 vv = *(const float4*)&Vs[k*132 + kg*16 + u*4];
                accO[0][u*4+0] = fmaf(p0, vv.x, accO[0][u*4+0]);
                accO[0][u*4+1] = fmaf(p0, vv.y, accO[0][u*4+1]);
                accO[0][u*4+2] = fmaf(p0, vv.z, accO[0][u*4+2]);
                accO[0][u*4+3] = fmaf(p0, vv.w, accO[0][u*4+3]);
                accO[1][u*4+0] = fmaf(p1, vv.x, accO[1][u*4+0]);
                accO[1][u*4+1] = fmaf(p1, vv.y, accO[1][u*4+1]);
                accO[1][u*4+2] = fmaf(p1, vv.z, accO[1][u*4+2]);
                accO[1][u*4+3] = fmaf(p1, vv.w, accO[1][u*4+3]);
            }
        }
    }

    #pragma unroll
    for (int qi = 0; qi < 2; qi++) {
        float inv = 1.f / lrow[qi];
        size_t row = (size_t)(n*Bb + b)*Tt + q0 + 2*qp + qi;
        float* dst = g_AO + row*Dd + h*HDc + kg*16;
        #pragma unroll
        for (int u = 0; u < 4; u++) {
            float4 o = make_float4(accO[qi][u*4+0]*inv, accO[qi][u*4+1]*inv,
                                   accO[qi][u*4+2]*inv, accO[qi][u*4+3]*inv);
            *(float4*)(dst + u*4) = o;
        }
    }
}

// ---------------- launch ----------------
extern "C" void kernel_launch(void* const* d_in, const int* in_sizes, int n_in,
                              void* d_out, int out_size)
{
    (void)in_sizes; (void)n_in; (void)out_size;
    const float* x     = (const float*)d_in[0];
    const unsigned char* mask = (const unsigned char*)d_in[1];
    const float* lnkw  = (const float*)d_in[2];
    const float* lnkb  = (const float*)d_in[3];
    const float* lnqw  = (const float*)d_in[4];
    const float* lnqb  = (const float*)d_in[5];
    const float* wk    = (const float*)d_in[6];
    const float* wv    = (const float*)d_in[7];
    const float* wq    = (const float*)d_in[8];
    const float* wo    = (const float*)d_in[9];
    const float* kcomp = (const float*)d_in[10];
    const float* vcomp = (const float*)d_in[11];
    const float* kdec  = (const float*)d_in[12];
    const float* vdec  = (const float*)d_in[13];
    float* out = (float*)d_out;

    static bool attr_done = false;
    if (!attr_done) {
        cudaFuncSetAttribute(k_flash, cudaFuncAttributeMaxDynamicSharedMemorySize, 76032);
        attr_done = true;
    }

    k_mask<<<1, 32>>>(mask);
    k_lnstats<<<NROWS/8, 256>>>(x);
    k_compgemm<<<dim3(Nn, 2, 8), 256>>>(kcomp, vcomp, wk, wv);
    k_foldM<<<Nn*128/8, 256>>>(lnkw, lnkb);
    k_foldQ<<<Nn*Dd/8, 256>>>(lnqw, lnqb, wq);
    k_hgemm<0><<<dim3(4, NROWS/128), 256>>>(x, nullptr, nullptr, nullptr);
    k_kvgemm<<<NROWS/64, 256>>>(x);
    k_transdec<<<128, 256>>>(kdec, vdec);
    k_decomp<<<dim3(BTc/16, 2), 256>>>();
    k_flash<<<dim3(Tt/64, Nn*Bb*Hh), 256, 76032>>>();
    k_hgemm<1><<<dim3(4, NROWS/128), 256>>>(nullptr, wo, x, out);
}

// round 4
// speedup vs baseline: 5.4925x; 4.5496x over previous
#include <cuda_runtime.h>
#include <cuda_bf16.h>
#include <cstdint>
#include <cstddef>

#define Nn 8
#define Bb 4
#define Tt 1024
#define Dd 512
#define Hh 4
#define HDc 128
#define Rr 64
#define BTc (Bb*Tt)
#define NROWS (Nn*BTc)
#define EPSV 1e-5f
#define INV_SQRT_HD 0.08838834764831845f
#define L2E 1.4426950408889634f
#define FSTR 136

// ---------------- device scratch ----------------
__device__ float g_mu[NROWS];
__device__ float g_rs[NROWS];
__device__ float g_maskf[Nn];
__device__ float g_invna;
__device__ float g_Wq[Nn*Dd*Dd];
__device__ float g_Sq[Nn*Dd];
__device__ float g_Cq[Nn*Dd];
__device__ float g_M[Nn*128*Dd];
__device__ float g_SM[Nn*128];
__device__ float g_CM[Nn*128];
__device__ float g_kq[(size_t)NROWS*Rr];
__device__ float g_vq[(size_t)NROWS*Rr];
__device__ float g_kdecT[Rr*Dd];
__device__ float g_vdecT[Rr*Dd];
__device__ __nv_bfloat16 g_Kh[(size_t)Bb*Hh*Tt*HDc];
__device__ __nv_bfloat16 g_Vh[(size_t)Bb*Hh*Tt*HDc];
__device__ __nv_bfloat16 g_Qh[(size_t)NROWS*Dd];
__device__ float g_AO[(size_t)NROWS*Dd];

// ---------------- mma helpers ----------------
__device__ __forceinline__ uint32_t pk2(float x, float y)
{
    __nv_bfloat162 h = __float22bfloat162_rn(make_float2(x, y));
    return *reinterpret_cast<uint32_t*>(&h);
}

__device__ __forceinline__ void ldsm4(uint32_t* r, const __nv_bfloat16* p)
{
    uint32_t a = (uint32_t)__cvta_generic_to_shared((void*)p);
    asm volatile("ldmatrix.sync.aligned.m8n8.x4.shared.b16 {%0,%1,%2,%3}, [%4];\n"
                 : "=r"(r[0]), "=r"(r[1]), "=r"(r[2]), "=r"(r[3]) : "r"(a));
}

__device__ __forceinline__ void ldsm4t(uint32_t* r, const __nv_bfloat16* p)
{
    uint32_t a = (uint32_t)__cvta_generic_to_shared((void*)p);
    asm volatile("ldmatrix.sync.aligned.m8n8.x4.trans.shared.b16 {%0,%1,%2,%3}, [%4];\n"
                 : "=r"(r[0]), "=r"(r[1]), "=r"(r[2]), "=r"(r[3]) : "r"(a));
}

__device__ __forceinline__ void mmabf(float* d, const uint32_t* a, uint32_t b0, uint32_t b1)
{
    asm volatile("mma.sync.aligned.m16n8k16.row.col.f32.bf16.bf16.f32 "
                 "{%0,%1,%2,%3},{%4,%5,%6,%7},{%8,%9},{%0,%1,%2,%3};\n"
                 : "+f"(d[0]), "+f"(d[1]), "+f"(d[2]), "+f"(d[3])
                 : "r"(a[0]), "r"(a[1]), "r"(a[2]), "r"(a[3]), "r"(b0), "r"(b1));
}

// ---------------- mask decode ----------------
__global__ void k_mask(const unsigned char* __restrict__ p)
{
    if (threadIdx.x == 0) {
        bool isF = (p[0]==0 && p[1]==0 && p[2]==0x80 && p[3]==0x3f);
        bool isI = (!isF && p[1]==0 && p[2]==0 && p[3]==0 && (p[4]!=0 || p[5]==0));
        float na = 0.f;
        for (int n = 0; n < Nn; n++) {
            bool bit;
            if (isF)      bit = (((const float*)p)[n] != 0.f);
            else if (isI) bit = (((const int*)p)[n]   != 0);
            else          bit = (p[n] != 0);
            g_maskf[n] = bit ? 1.f : 0.f;
            na += bit ? 1.f : 0.f;
        }
        g_invna = 1.f / fmaxf(na, 1.f);
    }
}

// ---------------- LN row stats ----------------
__global__ __launch_bounds__(256) void k_lnstats(const float* __restrict__ x)
{
    int row  = blockIdx.x * 8 + (threadIdx.x >> 5);
    int lane = threadIdx.x & 31;
    const float4* xp = (const float4*)(x + (size_t)row * Dd);
    float s = 0.f, sq = 0.f;
    #pragma unroll
    for (int i = 0; i < 4; i++) {
        float4 v = xp[lane + 32*i];
        s  += v.x + v.y + v.z + v.w;
        sq += v.x*v.x + v.y*v.y + v.z*v.z + v.w*v.w;
    }
    #pragma unroll
    for (int o = 16; o > 0; o >>= 1) {
        s  += __shfl_xor_sync(0xffffffffu, s,  o);
        sq += __shfl_xor_sync(0xffffffffu, sq, o);
    }
    if (lane == 0) {
        float mu  = s * (1.f / Dd);
        float var = sq * (1.f / Dd) - mu * mu;
        g_mu[row] = mu;
        g_rs[row] = rsqrtf(var + EPSV);
    }
}

// ---------------- M_raw[n] = comp @ w ----------------
__global__ __launch_bounds__(256) void k_compgemm(
    const float* __restrict__ kcomp, const float* __restrict__ vcomp,
    const float* __restrict__ wk,    const float* __restrict__ wv)
{
    __shared__ float As[32*68];
    __shared__ float Bs[32*68];
    const int n    = blockIdx.x;
    const int half = blockIdx.y;
    const int i0   = blockIdx.z * 64;
    const float* comp = (half == 0 ? kcomp : vcomp) + (size_t)n * Rr * Dd;
    const float* w    = (half == 0 ? wk    : wv   ) + (size_t)n * Dd * Dd;
    const int tid = threadIdx.x, ty = tid >> 4, tx = tid & 15;
    const int arA = tid & 63, acA = (tid >> 6) * 8;
    const int arB = tid & 31, acB = (tid >> 5) * 8;

    float acc[4][4] = {};
    for (int k0 = 0; k0 < Dd; k0 += 32) {
        float4 a0 = *(const float4*)(comp + (size_t)arA*Dd + k0 + acA);
        float4 a1 = *(const float4*)(comp + (size_t)arA*Dd + k0 + acA + 4);
        float4 b0 = *(const float4*)(w + (size_t)(k0+arB)*Dd + i0 + acB);
        float4 b1 = *(const float4*)(w + (size_t)(k0+arB)*Dd + i0 + acB + 4);
        __syncthreads();
        As[(acA+0)*68+arA]=a0.x; As[(acA+1)*68+arA]=a0.y; As[(acA+2)*68+arA]=a0.z; As[(acA+3)*68+arA]=a0.w;
        As[(acA+4)*68+arA]=a1.x; As[(acA+5)*68+arA]=a1.y; As[(acA+6)*68+arA]=a1.z; As[(acA+7)*68+arA]=a1.w;
        *(float4*)&Bs[arB*68 + acB]     = b0;
        *(float4*)&Bs[arB*68 + acB + 4] = b1;
        __syncthreads();
        #pragma unroll
        for (int kk = 0; kk < 32; kk++) {
            float4 a  = *(const float4*)&As[kk*68 + ty*4];
            float4 bb = *(const float4*)&Bs[kk*68 + tx*4];
            float av[4] = {a.x,a.y,a.z,a.w};
            float bv[4] = {bb.x,bb.y,bb.z,bb.w};
            #pragma unroll
            for (int i = 0; i < 4; i++)
                #pragma unroll
                for (int j = 0; j < 4; j++)
                    acc[i][j] = fmaf(av[i], bv[j], acc[i][j]);
        }
    }
    #pragma unroll
    for (int i = 0; i < 4; i++) {
        int row = n*128 + half*64 + ty*4 + i;
        float4 o = make_float4(acc[i][0], acc[i][1], acc[i][2], acc[i][3]);
        *(float4*)(g_M + (size_t)row*Dd + i0 + tx*4) = o;
    }
}

// ---------------- fold LN(kv) into M ----------------
__global__ __launch_bounds__(256) void k_foldM(const float* __restrict__ lnw,
                                               const float* __restrict__ lnb)
{
    int row  = blockIdx.x * 8 + (threadIdx.x >> 5);
    int lane = threadIdx.x & 31;
    int n = row >> 7;
    const float* lw = lnw + n*Dd;
    const float* lb = lnb + n*Dd;
    float* Mrow = g_M + (size_t)row * Dd;
    float sm = 0.f, cm = 0.f;
    for (int i = lane; i < Dd; i += 32) {
        float m = Mrow[i], w = lw[i], b = lb[i];
        sm += w * m; cm += b * m;
        Mrow[i] = w * m;
    }
    #pragma unroll
    for (int o = 16; o > 0; o >>= 1) {
        sm += __shfl_xor_sync(0xffffffffu, sm, o);
        cm += __shfl_xor_sync(0xffffffffu, cm, o);
    }
    if (lane == 0) { g_SM[row] = sm; g_CM[row] = cm; }
}

// ---------------- fold LN(q) into w_q ----------------
__global__ __launch_bounds__(256) void k_foldQ(const float* __restrict__ lnw,
                                               const float* __restrict__ lnb,
                                               const float* __restrict__ wq)
{
    int row  = blockIdx.x * 8 + (threadIdx.x >> 5);
    int lane = threadIdx.x & 31;
    int n = row >> 9;
    const float* lw = lnw + n*Dd;
    const float* lb = lnb + n*Dd;
    const float* wr = wq + (size_t)row * Dd;
    float* dst = g_Wq + (size_t)row * Dd;
    float sm = 0.f, cm = 0.f;
    for (int i = lane; i < Dd; i += 32) {
        float m = wr[i], w = lw[i], b = lb[i];
        sm += w * m; cm += b * m;
        dst[i] = w * m;
    }
    #pragma unroll
    for (int o = 16; o > 0; o >>= 1) {
        sm += __shfl_xor_sync(0xffffffffu, sm, o);
        cm += __shfl_xor_sync(0xffffffffu, cm, o);
    }
    if (lane == 0) { g_Sq[row] = sm; g_Cq[row] = cm; }
}

// ---------------- bf16 tensor-core GEMM 128x128xK512. MODE 0 = Q, 1 = O ---------
template<int MODE>
__global__ __launch_bounds__(256) void k_hgemm(
    const float* __restrict__ Ain, const float* __restrict__ Bw,
    const float* __restrict__ X, float* __restrict__ Out)
{
    __shared__ __nv_bfloat16 As[2][128*40];
    __shared__ __nv_bfloat16 Bs[2][128*40];
    const int m0 = blockIdx.y * 128;
    const int o0 = blockIdx.x * 128;
    const int n  = m0 >> 12;
    const float* A = (MODE == 1) ? (const float*)g_AO : Ain;
    const float* B = ((MODE == 0) ? (const float*)g_Wq : Bw) + (size_t)n * Dd * Dd;

    const int tid = threadIdx.x, lane = tid & 31, warp = tid >> 5;
    const int wm = warp & 3, wn = warp >> 2;

    const int lr = tid >> 1, lkc = (tid & 1) * 16;
    const float* Ag = A + (size_t)(m0 + lr) * Dd + lkc;
    const float* Bg = B + (size_t)(o0 + lr) * Dd + lkc;

    float4 fa[4], fb[4];
    #pragma unroll
    for (int i = 0; i < 4; i++) {
        fa[i] = *(const float4*)(Ag + i*4);
        fb[i] = *(const float4*)(Bg + i*4);
    }

    auto stg = [&](int st) {
        __nv_bfloat16* pa = &As[st][lr*40 + lkc];
        __nv_bfloat16* pb = &Bs[st][lr*40 + lkc];
        ((uint4*)pa)[0] = make_uint4(pk2(fa[0].x,fa[0].y), pk2(fa[0].z,fa[0].w),
                                     pk2(fa[1].x,fa[1].y), pk2(fa[1].z,fa[1].w));
        ((uint4*)pa)[1] = make_uint4(pk2(fa[2].x,fa[2].y), pk2(fa[2].z,fa[2].w),
                                     pk2(fa[3].x,fa[3].y), pk2(fa[3].z,fa[3].w));
        ((uint4*)pb)[0] = make_uint4(pk2(fb[0].x,fb[0].y), pk2(fb[0].z,fb[0].w),
                                     pk2(fb[1].x,fb[1].y), pk2(fb[1].z,fb[1].w));
        ((uint4*)pb)[1] = make_uint4(pk2(fb[2].x,fb[2].y), pk2(fb[2].z,fb[2].w),
                                     pk2(fb[3].x,fb[3].y), pk2(fb[3].z,fb[3].w));
    };

    stg(0);
    __syncthreads();

    float acc[2][8][4];
    #pragma unroll
    for (int i = 0; i < 2; i++)
        #pragma unroll
        for (int j = 0; j < 8; j++)
            #pragma unroll
            for (int k = 0; k < 4; k++) acc[i][j][k] = 0.f;

    const int arow = wm*32 + (lane & 15);
    const int acol = ((lane >> 4) & 1) * 8;
    const int brow = wn*64 + (lane & 7) + ((lane >> 4) & 1) * 8;
    const int bcol = ((lane >> 3) & 1) * 8;

    for (int ks = 0; ks < 16; ks++) {
        int st = ks & 1;
        if (ks < 15) {
            #pragma unroll
            for (int i = 0; i < 4; i++) {
                fa[i] = *(const float4*)(Ag + (ks+1)*32 + i*4);
                fb[i] = *(const float4*)(Bg + (ks+1)*32 + i*4);
            }
        }
        const __nv_bfloat16* Asb = As[st];
        const __nv_bfloat16* Bsb = Bs[st];

        uint32_t af[2][2][4];
        #pragma unroll
        for (int mf = 0; mf < 2; mf++)
            #pragma unroll
            for (int kf = 0; kf < 2; kf++)
                ldsm4(af[mf][kf], Asb + (arow + mf*16)*40 + kf*16 + acol);

        #pragma unroll
        for (int ng = 0; ng < 4; ng++) {
            uint32_t bfr[2][4];
            #pragma unroll
            for (int kf = 0; kf < 2; kf++)
                ldsm4(bfr[kf], Bsb + (brow + ng*16)*40 + kf*16 + bcol);
            #pragma unroll
            for (int s = 0; s < 2; s++) {
                int nf = ng*2 + s;
                #pragma unroll
                for (int mf = 0; mf < 2; mf++) {
                    mmabf(acc[mf][nf], af[mf][0], bfr[0][2*s], bfr[0][2*s+1]);
                    mmabf(acc[mf][nf], af[mf][1], bfr[1][2*s], bfr[1][2*s+1]);
                }
            }
        }
        __syncthreads();
        if (ks < 15) { stg(st ^ 1); __syncthreads(); }
    }

    const int mrow = m0 + wm*32 + (lane >> 2);
    const int ocol = o0 + wn*64 + (lane & 3)*2;
    if (MODE == 0) {
        #pragma unroll
        for (int mf = 0; mf < 2; mf++) {
            int r0 = mrow + mf*16, r1 = r0 + 8;
            float rs0 = g_rs[r0], mr0 = g_mu[r0]*rs0;
            float rs1 = g_rs[r1], mr1 = g_mu[r1]*rs1;
            #pragma unroll
            for (int nf = 0; nf < 8; nf++) {
                int c = ocol + nf*8;
                float sq0 = g_Sq[n*Dd + c], sq1 = g_Sq[n*Dd + c + 1];
                float cq0 = g_Cq[n*Dd + c], cq1 = g_Cq[n*Dd + c + 1];
                float* d = acc[mf][nf];
                *(uint32_t*)(g_Qh + (size_t)r0*Dd + c) =
                    pk2(rs0*d[0] - mr0*sq0 + cq0, rs0*d[1] - mr0*sq1 + cq1);
                *(uint32_t*)(g_Qh + (size_t)r1*Dd + c) =
                    pk2(rs1*d[2] - mr1*sq0 + cq0, rs1*d[3] - mr1*sq1 + cq1);
            }
        }
    } else {
        float mfv = g_maskf[n];
        #pragma unroll
        for (int mf = 0; mf < 2; mf++) {
            int r0 = mrow + mf*16, r1 = r0 + 8;
            #pragma unroll
            for (int nf = 0; nf < 8; nf++) {
                int c = ocol + nf*8;
                float* d = acc[mf][nf];
                float2 x0 = *(const float2*)(X + (size_t)r0*Dd + c);
                float2 x1 = *(const float2*)(X + (size_t)r1*Dd + c);
                *(float2*)(Out + (size_t)r0*Dd + c) =
                    make_float2(x0.x + mfv*d[0], x0.y + mfv*d[1]);
                *(float2*)(Out + (size_t)r1*Dd + c) =
                    make_float2(x1.x + mfv*d[2], x1.y + mfv*d[3]);
            }
        }
    }
}

// ---------------- fused kv-compress GEMM + LN + mask + int8 STE quant ------------
__global__ __launch_bounds__(256) void k_kvgemm(const float* __restrict__ A)
{
    __shared__ float As[16*68];
    __shared__ float Bs[16*132];
    const int m0 = blockIdx.x * 64;
    const int n  = m0 >> 12;
    const float* Bw = g_M + (size_t)n * 128 * Dd;
    const int tid = threadIdx.x;
    const int ty = tid >> 4, tx = tid & 15;

    const int lrA = tid & 63, lcA = (tid >> 6) * 4;
    const int lrB = tid >> 1, lcB = (tid & 1) * 8;
    const float* Ag = A  + (size_t)(m0 + lrA) * Dd + lcA;
    const float* Bg = Bw + (size_t)lrB * Dd + lcB;

    float acc[4][8];
    #pragma unroll
    for (int i = 0; i < 4; i++)
        #pragma unroll
        for (int j = 0; j < 8; j++) acc[i][j] = 0.f;

    for (int k0 = 0; k0 < Dd; k0 += 16) {
        float4 a0 = *(const float4*)(Ag + k0);
        float4 b0 = *(const float4*)(Bg + k0);
        float4 b1 = *(const float4*)(Bg + k0 + 4);
        __syncthreads();
        As[(lcA+0)*68+lrA]=a0.x; As[(lcA+1)*68+lrA]=a0.y; As[(lcA+2)*68+lrA]=a0.z; As[(lcA+3)*68+lrA]=a0.w;
        Bs[(lcB+0)*132+lrB]=b0.x; Bs[(lcB+1)*132+lrB]=b0.y; Bs[(lcB+2)*132+lrB]=b0.z; Bs[(lcB+3)*132+lrB]=b0.w;
        Bs[(lcB+4)*132+lrB]=b1.x; Bs[(lcB+5)*132+lrB]=b1.y; Bs[(lcB+6)*132+lrB]=b1.z; Bs[(lcB+7)*132+lrB]=b1.w;
        __syncthreads();
        #pragma unroll
        for (int kk = 0; kk < 16; kk++) {
            float av[4], bv[8];
            *(float4*)&av[0] = *(const float4*)&As[kk*68 + ty*4];
            *(float4*)&bv[0] = *(const float4*)&Bs[kk*132 + tx*8];
            *(float4*)&bv[4] = *(const float4*)&Bs[kk*132 + tx*8 + 4];
            #pragma unroll
            for (int i = 0; i < 4; i++)
                #pragma unroll
                for (int j = 0; j < 8; j++)
                    acc[i][j] = fmaf(av[i], bv[j], acc[i][j]);
        }
    }

    const float mf = g_maskf[n];
    float sm[8], cm[8];
    #pragma unroll
    for (int j = 0; j < 8; j++) {
        int o = tx*8 + j;
        sm[j] = g_SM[n*128 + o]; cm[j] = g_CM[n*128 + o];
    }
    float* dst = (tx < 8) ? g_kq : g_vq;
    int col = (tx & 7) * 8;
    #pragma unroll
    for (int i = 0; i < 4; i++) {
        int m = m0 + ty*4 + i;
        float rsv = g_rs[m], murs = g_mu[m] * rsv;
        float v[8]; float am = 0.f;
        #pragma unroll
        for (int j = 0; j < 8; j++) {
            v[j] = (rsv*acc[i][j] - murs*sm[j] + cm[j]) * mf;
            am = fmaxf(am, fabsf(v[j]));
        }
        am = fmaxf(am, __shfl_xor_sync(0xffffffffu, am, 1));
        am = fmaxf(am, __shfl_xor_sync(0xffffffffu, am, 2));
        am = fmaxf(am, __shfl_xor_sync(0xffffffffu, am, 4));
        am = fmaxf(am, 1e-8f);
        float scq = 127.f / am;
        float inv = am * (1.f / 127.f);
        float q[8];
        #pragma unroll
        for (int j = 0; j < 8; j++) q[j] = rintf(v[j] * scq) * inv;
        *(float4*)(dst + (size_t)m*64 + col)     = make_float4(q[0],q[1],q[2],q[3]);
        *(float4*)(dst + (size_t)m*64 + col + 4) = make_float4(q[4],q[5],q[6],q[7]);
    }
}

// ---------------- transpose decoders ----------------
__global__ void k_transdec(const float* __restrict__ kd, const float* __restrict__ vd)
{
    int idx = blockIdx.x * 256 + threadIdx.x;
    int d = idx >> 6, r = idx & 63;
    g_kdecT[r*Dd + d] = kd[idx];
    g_vdecT[r*Dd + d] = vd[idx];
}

// ---------------- average over n + decompress -> bf16 K/V [B,H,T,HD] ------------
__global__ __launch_bounds__(256) void k_decomp()
{
    __shared__ float avg[16][64];
    int bt0 = blockIdx.x * 16;
    int isv = blockIdx.y;
    const float* src = isv ? g_vq : g_kq;
    const float* dec = isv ? g_vdecT : g_kdecT;
    __nv_bfloat16* dstb = isv ? g_Vh : g_Kh;
    float invna = g_invna;
    int tid = threadIdx.x;
    #pragma unroll
    for (int j = 0; j < 4; j++) {
        int p = j*256 + tid;
        int row = p >> 6, r = p & 63;
        float s = 0.f;
        #pragma unroll
        for (int n = 0; n < Nn; n++)
            s += src[((size_t)(n*BTc + bt0 + row))*64 + r];
        avg[row][r] = s * invna;
    }
    __syncthreads();
    int d0 = tid * 2;
    float2 acc[16];
    #pragma unroll
    for (int row = 0; row < 16; row++) { acc[row].x = 0.f; acc[row].y = 0.f; }
    for (int r = 0; r < 64; r++) {
        float2 kd = *(const float2*)(dec + r*Dd + d0);
        #pragma unroll
        for (int row = 0; row < 16; row++) {
            float a = avg[row][r];
            acc[row].x = fmaf(a, kd.x, acc[row].x);
            acc[row].y = fmaf(a, kd.y, acc[row].y);
        }
    }
    float sc = isv ? 1.f : INV_SQRT_HD;
    int h = d0 >> 7, hd = d0 & 127;
    #pragma unroll
    for (int row = 0; row < 16; row++) {
        int bt = bt0 + row;
        int b = bt >> 10, t = bt & 1023;
        __nv_bfloat16* dst = dstb + (((size_t)(b*Hh+h)*Tt + t)*HDc + hd);
        *(uint32_t*)dst = pk2(acc[row].x * sc, acc[row].y * sc);
    }
}

// ---------------- causal flash attention: bf16 mma, 64q x 64kv tiles -------------
__global__ __launch_bounds__(128) void k_flash()
{
    extern __shared__ __nv_bfloat16 smb[];
    __nv_bfloat16* Qs = smb;                 // [64][FSTR]
    __nv_bfloat16* Ks = Qs + 64*FSTR;
    __nv_bfloat16* Vs = Ks + 64*FSTR;
    const int nbh = blockIdx.y;
    const int n = nbh >> 4, b = (nbh >> 2) & 3, h = nbh & 3;
    const int qt = blockIdx.x;
    const int q0 = qt * 64;
    const int tid = threadIdx.x, lane = tid & 31, warp = tid >> 5;

    const size_t qbase  = ((size_t)(n*Bb + b)*Tt + q0) * Dd + h*HDc;
    const size_t kvbase = (size_t)(b*Hh + h) * Tt * HDc;

    #pragma unroll
    for (int i = 0; i < 8; i++) {
        int idx = tid + i*128;
        int r = idx >> 4, c = (idx & 15) * 8;
        *(uint4*)&Qs[r*FSTR + c] = *(const uint4*)(g_Qh + qbase + (size_t)r*Dd + c);
    }
    __syncthreads();

    uint32_t qf[8][4];
    {
        const __nv_bfloat16* qp = Qs + (warp*16 + (lane & 15))*FSTR + (lane >> 4)*8;
        #pragma unroll
        for (int kf = 0; kf < 8; kf++) ldsm4(qf[kf], qp + kf*16);
    }

    float accO[16][4];
    #pragma unroll
    for (int i = 0; i < 16; i++)
        #pragma unroll
        for (int j = 0; j < 4; j++) accO[i][j] = 0.f;
    float mrow[2] = {-1e30f, -1e30f};
    float lrow[2] = {0.f, 0.f};

    const int r0q = warp*16 + (lane >> 2);
    const int c0q = (lane & 3) * 2;

    for (int kt = 0; kt <= qt; kt++) {
        const int k0 = kt * 64;
        __syncthreads();
        #pragma unroll
        for (int i = 0; i < 8; i++) {
            int idx = tid + i*128;
            int r = idx >> 4, c = (idx & 15)*8;
            size_t src = kvbase + (size_t)(k0 + r)*HDc + c;
            *(uint4*)&Ks[r*FSTR + c] = *(const uint4*)(g_Kh + src);
            *(uint4*)&Vs[r*FSTR + c] = *(const uint4*)(g_Vh + src);
        }
        __syncthreads();

        float sfr[8][4];
        #pragma unroll
        for (int i = 0; i < 8; i++)
            #pragma unroll
            for (int j = 0; j < 4; j++) sfr[i][j] = 0.f;

        {
            const __nv_bfloat16* kp = Ks + ((lane & 7) + ((lane >> 4) & 1)*8)*FSTR
                                         + ((lane >> 3) & 1)*8;
            #pragma unroll
            for (int ng = 0; ng < 4; ng++) {
                #pragma unroll
                for (int kf = 0; kf < 8; kf++) {
                    uint32_t bf[4];
                    ldsm4(bf, kp + ng*16*FSTR + kf*16);
                    mmabf(sfr[2*ng],   qf[kf], bf[0], bf[1]);
                    mmabf(sfr[2*ng+1], qf[kf], bf[2], bf[3]);
                }
            }
        }

        if (kt == qt) {
            #pragma unroll
            for (int j = 0; j < 8; j++) {
                int cj = 8*j + c0q;
                #pragma unroll
                for (int rr = 0; rr < 2; rr++) {
                    int ri = r0q + 8*rr;
                    if (cj     > ri) sfr[j][2*rr]   = -1e30f;
                    if (cj + 1 > ri) sfr[j][2*rr+1] = -1e30f;
                }
            }
        }

        #pragma unroll
        for (int rr = 0; rr < 2; rr++) {
            float tm = -1e30f;
            #pragma unroll
            for (int j = 0; j < 8; j++)
                tm = fmaxf(tm, fmaxf(sfr[j][2*rr], sfr[j][2*rr+1]));
            tm = fmaxf(tm, __shfl_xor_sync(0xffffffffu, tm, 1));
            tm = fmaxf(tm, __shfl_xor_sync(0xffffffffu, tm, 2));
            float mnew = fmaxf(mrow[rr], tm);
            float scl = exp2f((mrow[rr] - mnew) * L2E);
            float ps = 0.f;
            #pragma unroll
            for (int j = 0; j < 8; j++) {
                float e0 = exp2f((sfr[j][2*rr]   - mnew) * L2E);
                float e1 = exp2f((sfr[j][2*rr+1] - mnew) * L2E);
                sfr[j][2*rr] = e0; sfr[j][2*rr+1] = e1;
                ps += e0 + e1;
            }
            ps += __shfl_xor_sync(0xffffffffu, ps, 1);
            ps += __shfl_xor_sync(0xffffffffu, ps, 2);
            lrow[rr] = lrow[rr]*scl + ps;
            mrow[rr] = mnew;
            #pragma unroll
            for (int nf = 0; nf < 16; nf++) {
                accO[nf][2*rr]   *= scl;
                accO[nf][2*rr+1] *= scl;
            }
        }

        uint32_t pa[4][4];
        #pragma unroll
        for (int kg = 0; kg < 4; kg++) {
            pa[kg][0] = pk2(sfr[2*kg][0],   sfr[2*kg][1]);
            pa[kg][1] = pk2(sfr[2*kg][2],   sfr[2*kg][3]);
            pa[kg][2] = pk2(sfr[2*kg+1][0], sfr[2*kg+1][1]);
            pa[kg][3] = pk2(sfr[2*kg+1][2], sfr[2*kg+1][3]);
        }

        {
            const __nv_bfloat16* vp = Vs + (lane & 15)*FSTR + (lane >> 4)*8;
            #pragma unroll
            for (int dg = 0; dg < 8; dg++) {
                #pragma unroll
                for (int kg = 0; kg < 4; kg++) {
                    uint32_t vb[4];
                    ldsm4t(vb, vp + kg*16*FSTR + dg*16);
                    mmabf(accO[2*dg],   pa[kg], vb[0], vb[1]);
                    mmabf(accO[2*dg+1], pa[kg], vb[2], vb[3]);
                }
            }
        }
    }

    #pragma unroll
    for (int rr = 0; rr < 2; rr++) {
        float inv = 1.f / lrow[rr];
        size_t row = (size_t)(n*Bb + b)*Tt + q0 + r0q + 8*rr;
        float* dst = g_AO + row*Dd + h*HDc;
        #pragma unroll
        for (int nf = 0; nf < 16; nf++) {
            *(float2*)(dst + 8*nf + c0q) =
                make_float2(accO[nf][2*rr]*inv, accO[nf][2*rr+1]*inv);
        }
    }
}

// ---------------- launch ----------------
extern "C" void kernel_launch(void* const* d_in, const int* in_sizes, int n_in,
                              void* d_out, int out_size)
{
    (void)in_sizes; (void)n_in; (void)out_size;
    const float* x     = (const float*)d_in[0];
    const unsigned char* mask = (const unsigned char*)d_in[1];
    const float* lnkw  = (const float*)d_in[2];
    const float* lnkb  = (const float*)d_in[3];
    const float* lnqw  = (const float*)d_in[4];
    const float* lnqb  = (const float*)d_in[5];
    const float* wk    = (const float*)d_in[6];
    const float* wv    = (const float*)d_in[7];
    const float* wq    = (const float*)d_in[8];
    const float* wo    = (const float*)d_in[9];
    const float* kcomp = (const float*)d_in[10];
    const float* vcomp = (const float*)d_in[11];
    const float* kdec  = (const float*)d_in[12];
    const float* vdec  = (const float*)d_in[13];
    float* out = (float*)d_out;

    static bool attr_done = false;
    if (!attr_done) {
        cudaFuncSetAttribute(k_flash, cudaFuncAttributeMaxDynamicSharedMemorySize,
                             3*64*FSTR*2);
        attr_done = true;
    }

    k_mask<<<1, 32>>>(mask);
    k_lnstats<<<NROWS/8, 256>>>(x);
    k_compgemm<<<dim3(Nn, 2, 8), 256>>>(kcomp, vcomp, wk, wv);
    k_foldM<<<Nn*128/8, 256>>>(lnkw, lnkb);
    k_foldQ<<<Nn*Dd/8, 256>>>(lnqw, lnqb, wq);
    k_hgemm<0><<<dim3(4, NROWS/128), 256>>>(x, nullptr, nullptr, nullptr);
    k_kvgemm<<<NROWS/64, 256>>>(x);
    k_transdec<<<128, 256>>>(kdec, vdec);
    k_decomp<<<dim3(BTc/16, 2), 256>>>();
    k_flash<<<dim3(Tt/64, Nn*Bb*Hh), 128, 3*64*FSTR*2>>>();
    k_hgemm<1><<<dim3(4, NROWS/128), 256>>>(nullptr, wo, x, out);
}

// round 5
// speedup vs baseline: 7.0125x; 1.2767x over previous
#include <cuda_runtime.h>
#include <cuda_bf16.h>
#include <cstdint>
#include <cstddef>

#define Nn 8
#define Bb 4
#define Tt 1024
#define Dd 512
#define Hh 4
#define HDc 128
#define Rr 64
#define BTc (Bb*Tt)
#define NROWS (Nn*BTc)
#define EPSV 1e-5f
#define INV_SQRT_HD 0.08838834764831845f
#define L2E 1.4426950408889634f
#define FSTR 136

// ---------------- device scratch ----------------
__device__ float g_mu[NROWS];
__device__ float g_rs[NROWS];
__device__ float g_maskf[Nn];
__device__ float g_invna;
__device__ float g_Wq[Nn*Dd*Dd];
__device__ float g_Sq[Nn*Dd];
__device__ float g_Cq[Nn*Dd];
__device__ float g_M[Nn*128*Dd];
__device__ __nv_bfloat16 g_Mbh[Nn*128*Dd];
__device__ __nv_bfloat16 g_Mbl[Nn*128*Dd];
__device__ float g_SM[Nn*128];
__device__ float g_CM[Nn*128];
__device__ float g_kq[(size_t)NROWS*Rr];
__device__ float g_vq[(size_t)NROWS*Rr];
__device__ float g_kdecT[Rr*Dd];
__device__ float g_vdecT[Rr*Dd];
__device__ __nv_bfloat16 g_Kh[(size_t)Bb*Hh*Tt*HDc];
__device__ __nv_bfloat16 g_Vh[(size_t)Bb*Hh*Tt*HDc];
__device__ __nv_bfloat16 g_Qh[(size_t)NROWS*Dd];
__device__ float g_AO[(size_t)NROWS*Dd];

// ---------------- mma helpers ----------------
__device__ __forceinline__ uint32_t pk2(float x, float y)
{
    __nv_bfloat162 h = __float22bfloat162_rn(make_float2(x, y));
    return *reinterpret_cast<uint32_t*>(&h);
}

__device__ __forceinline__ void ldsm4(uint32_t* r, const __nv_bfloat16* p)
{
    uint32_t a = (uint32_t)__cvta_generic_to_shared((void*)p);
    asm volatile("ldmatrix.sync.aligned.m8n8.x4.shared.b16 {%0,%1,%2,%3}, [%4];\n"
                 : "=r"(r[0]), "=r"(r[1]), "=r"(r[2]), "=r"(r[3]) : "r"(a));
}

__device__ __forceinline__ void ldsm4t(uint32_t* r, const __nv_bfloat16* p)
{
    uint32_t a = (uint32_t)__cvta_generic_to_shared((void*)p);
    asm volatile("ldmatrix.sync.aligned.m8n8.x4.trans.shared.b16 {%0,%1,%2,%3}, [%4];\n"
                 : "=r"(r[0]), "=r"(r[1]), "=r"(r[2]), "=r"(r[3]) : "r"(a));
}

__device__ __forceinline__ void mmabf(float* d, const uint32_t* a, uint32_t b0, uint32_t b1)
{
    asm volatile("mma.sync.aligned.m16n8k16.row.col.f32.bf16.bf16.f32 "
                 "{%0,%1,%2,%3},{%4,%5,%6,%7},{%8,%9},{%0,%1,%2,%3};\n"
                 : "+f"(d[0]), "+f"(d[1]), "+f"(d[2]), "+f"(d[3])
                 : "r"(a[0]), "r"(a[1]), "r"(a[2]), "r"(a[3]), "r"(b0), "r"(b1));
}

// ---------------- mask decode ----------------
__global__ void k_mask(const unsigned char* __restrict__ p)
{
    if (threadIdx.x == 0) {
        bool isF = (p[0]==0 && p[1]==0 && p[2]==0x80 && p[3]==0x3f);
        bool isI = (!isF && p[1]==0 && p[2]==0 && p[3]==0 && (p[4]!=0 || p[5]==0));
        float na = 0.f;
        for (int n = 0; n < Nn; n++) {
            bool bit;
            if (isF)      bit = (((const float*)p)[n] != 0.f);
            else if (isI) bit = (((const int*)p)[n]   != 0);
            else          bit = (p[n] != 0);
            g_maskf[n] = bit ? 1.f : 0.f;
            na += bit ? 1.f : 0.f;
        }
        g_invna = 1.f / fmaxf(na, 1.f);
    }
}

// ---------------- LN row stats ----------------
__global__ __launch_bounds__(256) void k_lnstats(const float* __restrict__ x)
{
    int row  = blockIdx.x * 8 + (threadIdx.x >> 5);
    int lane = threadIdx.x & 31;
    const float4* xp = (const float4*)(x + (size_t)row * Dd);
    float s = 0.f, sq = 0.f;
    #pragma unroll
    for (int i = 0; i < 4; i++) {
        float4 v = xp[lane + 32*i];
        s  += v.x + v.y + v.z + v.w;
        sq += v.x*v.x + v.y*v.y + v.z*v.z + v.w*v.w;
    }
    #pragma unroll
    for (int o = 16; o > 0; o >>= 1) {
        s  += __shfl_xor_sync(0xffffffffu, s,  o);
        sq += __shfl_xor_sync(0xffffffffu, sq, o);
    }
    if (lane == 0) {
        float mu  = s * (1.f / Dd);
        float var = sq * (1.f / Dd) - mu * mu;
        g_mu[row] = mu;
        g_rs[row] = rsqrtf(var + EPSV);
    }
}

// ---------------- M_raw[n] = comp @ w ----------------
__global__ __launch_bounds__(256) void k_compgemm(
    const float* __restrict__ kcomp, const float* __restrict__ vcomp,
    const float* __restrict__ wk,    const float* __restrict__ wv)
{
    __shared__ float As[32*68];
    __shared__ float Bs[32*68];
    const int n    = blockIdx.x;
    const int half = blockIdx.y;
    const int i0   = blockIdx.z * 64;
    const float* comp = (half == 0 ? kcomp : vcomp) + (size_t)n * Rr * Dd;
    const float* w    = (half == 0 ? wk    : wv   ) + (size_t)n * Dd * Dd;
    const int tid = threadIdx.x, ty = tid >> 4, tx = tid & 15;
    const int arA = tid & 63, acA = (tid >> 6) * 8;
    const int arB = tid & 31, acB = (tid >> 5) * 8;

    float acc[4][4] = {};
    for (int k0 = 0; k0 < Dd; k0 += 32) {
        float4 a0 = *(const float4*)(comp + (size_t)arA*Dd + k0 + acA);
        float4 a1 = *(const float4*)(comp + (size_t)arA*Dd + k0 + acA + 4);
        float4 b0 = *(const float4*)(w + (size_t)(k0+arB)*Dd + i0 + acB);
        float4 b1 = *(const float4*)(w + (size_t)(k0+arB)*Dd + i0 + acB + 4);
        __syncthreads();
        As[(acA+0)*68+arA]=a0.x; As[(acA+1)*68+arA]=a0.y; As[(acA+2)*68+arA]=a0.z; As[(acA+3)*68+arA]=a0.w;
        As[(acA+4)*68+arA]=a1.x; As[(acA+5)*68+arA]=a1.y; As[(acA+6)*68+arA]=a1.z; As[(acA+7)*68+arA]=a1.w;
        *(float4*)&Bs[arB*68 + acB]     = b0;
        *(float4*)&Bs[arB*68 + acB + 4] = b1;
        __syncthreads();
        #pragma unroll
        for (int kk = 0; kk < 32; kk++) {
            float4 a  = *(const float4*)&As[kk*68 + ty*4];
            float4 bb = *(const float4*)&Bs[kk*68 + tx*4];
            float av[4] = {a.x,a.y,a.z,a.w};
            float bv[4] = {bb.x,bb.y,bb.z,bb.w};
            #pragma unroll
            for (int i = 0; i < 4; i++)
                #pragma unroll
                for (int j = 0; j < 4; j++)
                    acc[i][j] = fmaf(av[i], bv[j], acc[i][j]);
        }
    }
    #pragma unroll
    for (int i = 0; i < 4; i++) {
        int row = n*128 + half*64 + ty*4 + i;
        float4 o = make_float4(acc[i][0], acc[i][1], acc[i][2], acc[i][3]);
        *(float4*)(g_M + (size_t)row*Dd + i0 + tx*4) = o;
    }
}

// ---------------- fold LN(kv) into M -> bf16 hi/lo; SM/CM ----------------
__global__ __launch_bounds__(256) void k_foldM(const float* __restrict__ lnw,
                                               const float* __restrict__ lnb)
{
    int row  = blockIdx.x * 8 + (threadIdx.x >> 5);
    int lane = threadIdx.x & 31;
    int n = row >> 7;
    const float* lw = lnw + n*Dd;
    const float* lb = lnb + n*Dd;
    const float* Mrow = g_M + (size_t)row * Dd;
    float sm = 0.f, cm = 0.f;
    for (int i = lane; i < Dd; i += 32) {
        float m = Mrow[i], w = lw[i], b = lb[i];
        float p = w * m;
        sm += p; cm += b * m;
        __nv_bfloat16 hb = __float2bfloat16(p);
        g_Mbh[(size_t)row*Dd + i] = hb;
        g_Mbl[(size_t)row*Dd + i] = __float2bfloat16(p - __bfloat162float(hb));
    }
    #pragma unroll
    for (int o = 16; o > 0; o >>= 1) {
        sm += __shfl_xor_sync(0xffffffffu, sm, o);
        cm += __shfl_xor_sync(0xffffffffu, cm, o);
    }
    if (lane == 0) { g_SM[row] = sm; g_CM[row] = cm; }
}

// ---------------- fold LN(q) into w_q ----------------
__global__ __launch_bounds__(256) void k_foldQ(const float* __restrict__ lnw,
                                               const float* __restrict__ lnb,
                                               const float* __restrict__ wq)
{
    int row  = blockIdx.x * 8 + (threadIdx.x >> 5);
    int lane = threadIdx.x & 31;
    int n = row >> 9;
    const float* lw = lnw + n*Dd;
    const float* lb = lnb + n*Dd;
    const float* wr = wq + (size_t)row * Dd;
    float* dst = g_Wq + (size_t)row * Dd;
    float sm = 0.f, cm = 0.f;
    for (int i = lane; i < Dd; i += 32) {
        float m = wr[i], w = lw[i], b = lb[i];
        sm += w * m; cm += b * m;
        dst[i] = w * m;
    }
    #pragma unroll
    for (int o = 16; o > 0; o >>= 1) {
        sm += __shfl_xor_sync(0xffffffffu, sm, o);
        cm += __shfl_xor_sync(0xffffffffu, cm, o);
    }
    if (lane == 0) { g_Sq[row] = sm; g_Cq[row] = cm; }
}

// ---------------- bf16 tensor-core GEMM 128x128xK512. MODE 0 = Q, 1 = O ---------
template<int MODE>
__global__ __launch_bounds__(256) void k_hgemm(
    const float* __restrict__ Ain, const float* __restrict__ Bw,
    const float* __restrict__ X, float* __restrict__ Out)
{
    __shared__ __nv_bfloat16 As[2][128*40];
    __shared__ __nv_bfloat16 Bs[2][128*40];
    const int m0 = blockIdx.y * 128;
    const int o0 = blockIdx.x * 128;
    const int n  = m0 >> 12;
    const float* A = (MODE == 1) ? (const float*)g_AO : Ain;
    const float* B = ((MODE == 0) ? (const float*)g_Wq : Bw) + (size_t)n * Dd * Dd;

    const int tid = threadIdx.x, lane = tid & 31, warp = tid >> 5;
    const int wm = warp & 3, wn = warp >> 2;

    const int lr = tid >> 1, lkc = (tid & 1) * 16;
    const float* Ag = A + (size_t)(m0 + lr) * Dd + lkc;
    const float* Bg = B + (size_t)(o0 + lr) * Dd + lkc;

    float4 fa[4], fb[4];
    #pragma unroll
    for (int i = 0; i < 4; i++) {
        fa[i] = *(const float4*)(Ag + i*4);
        fb[i] = *(const float4*)(Bg + i*4);
    }

    auto stg = [&](int st) {
        __nv_bfloat16* pa = &As[st][lr*40 + lkc];
        __nv_bfloat16* pb = &Bs[st][lr*40 + lkc];
        ((uint4*)pa)[0] = make_uint4(pk2(fa[0].x,fa[0].y), pk2(fa[0].z,fa[0].w),
                                     pk2(fa[1].x,fa[1].y), pk2(fa[1].z,fa[1].w));
        ((uint4*)pa)[1] = make_uint4(pk2(fa[2].x,fa[2].y), pk2(fa[2].z,fa[2].w),
                                     pk2(fa[3].x,fa[3].y), pk2(fa[3].z,fa[3].w));
        ((uint4*)pb)[0] = make_uint4(pk2(fb[0].x,fb[0].y), pk2(fb[0].z,fb[0].w),
                                     pk2(fb[1].x,fb[1].y), pk2(fb[1].z,fb[1].w));
        ((uint4*)pb)[1] = make_uint4(pk2(fb[2].x,fb[2].y), pk2(fb[2].z,fb[2].w),
                                     pk2(fb[3].x,fb[3].y), pk2(fb[3].z,fb[3].w));
    };

    stg(0);
    __syncthreads();

    float acc[2][8][4];
    #pragma unroll
    for (int i = 0; i < 2; i++)
        #pragma unroll
        for (int j = 0; j < 8; j++)
            #pragma unroll
            for (int k = 0; k < 4; k++) acc[i][j][k] = 0.f;

    const int arow = wm*32 + (lane & 15);
    const int acol = ((lane >> 4) & 1) * 8;
    const int brow = wn*64 + (lane & 7) + ((lane >> 4) & 1) * 8;
    const int bcol = ((lane >> 3) & 1) * 8;

    for (int ks = 0; ks < 16; ks++) {
        int st = ks & 1;
        if (ks < 15) {
            #pragma unroll
            for (int i = 0; i < 4; i++) {
                fa[i] = *(const float4*)(Ag + (ks+1)*32 + i*4);
                fb[i] = *(const float4*)(Bg + (ks+1)*32 + i*4);
            }
        }
        const __nv_bfloat16* Asb = As[st];
        const __nv_bfloat16* Bsb = Bs[st];

        uint32_t af[2][2][4];
        #pragma unroll
        for (int mf = 0; mf < 2; mf++)
            #pragma unroll
            for (int kf = 0; kf < 2; kf++)
                ldsm4(af[mf][kf], Asb + (arow + mf*16)*40 + kf*16 + acol);

        #pragma unroll
        for (int ng = 0; ng < 4; ng++) {
            uint32_t bfr[2][4];
            #pragma unroll
            for (int kf = 0; kf < 2; kf++)
                ldsm4(bfr[kf], Bsb + (brow + ng*16)*40 + kf*16 + bcol);
            #pragma unroll
            for (int s = 0; s < 2; s++) {
                int nf = ng*2 + s;
                #pragma unroll
                for (int mf = 0; mf < 2; mf++) {
                    mmabf(acc[mf][nf], af[mf][0], bfr[0][2*s], bfr[0][2*s+1]);
                    mmabf(acc[mf][nf], af[mf][1], bfr[1][2*s], bfr[1][2*s+1]);
                }
            }
        }
        __syncthreads();
        if (ks < 15) { stg(st ^ 1); __syncthreads(); }
    }

    const int mrow = m0 + wm*32 + (lane >> 2);
    const int ocol = o0 + wn*64 + (lane & 3)*2;
    if (MODE == 0) {
        #pragma unroll
        for (int mf = 0; mf < 2; mf++) {
            int r0 = mrow + mf*16, r1 = r0 + 8;
            float rs0 = g_rs[r0], mr0 = g_mu[r0]*rs0;
            float rs1 = g_rs[r1], mr1 = g_mu[r1]*rs1;
            #pragma unroll
            for (int nf = 0; nf < 8; nf++) {
                int c = ocol + nf*8;
                float sq0 = g_Sq[n*Dd + c], sq1 = g_Sq[n*Dd + c + 1];
                float cq0 = g_Cq[n*Dd + c], cq1 = g_Cq[n*Dd + c + 1];
                float* d = acc[mf][nf];
                *(uint32_t*)(g_Qh + (size_t)r0*Dd + c) =
                    pk2(rs0*d[0] - mr0*sq0 + cq0, rs0*d[1] - mr0*sq1 + cq1);
                *(uint32_t*)(g_Qh + (size_t)r1*Dd + c) =
                    pk2(rs1*d[2] - mr1*sq0 + cq0, rs1*d[3] - mr1*sq1 + cq1);
            }
        }
    } else {
        float mfv = g_maskf[n];
        #pragma unroll
        for (int mf = 0; mf < 2; mf++) {
            int r0 = mrow + mf*16, r1 = r0 + 8;
            #pragma unroll
            for (int nf = 0; nf < 8; nf++) {
                int c = ocol + nf*8;
                float* d = acc[mf][nf];
                float2 x0 = *(const float2*)(X + (size_t)r0*Dd + c);
                float2 x1 = *(const float2*)(X + (size_t)r1*Dd + c);
                *(float2*)(Out + (size_t)r0*Dd + c) =
                    make_float2(x0.x + mfv*d[0], x0.y + mfv*d[1]);
                *(float2*)(Out + (size_t)r1*Dd + c) =
                    make_float2(x1.x + mfv*d[2], x1.y + mfv*d[3]);
            }
        }
    }
}

// ------- kv-compress via bf16x3 tensor cores + LN + mask + int8 STE quant --------
// C[128rows x 128cols] per block; cols 0-63 -> k, 64-127 -> v.
__global__ __launch_bounds__(256) void k_kvmma(const float* __restrict__ Ain)
{
    __shared__ __nv_bfloat16 Ah[128*40];
    __shared__ __nv_bfloat16 Al[128*40];
    __shared__ __nv_bfloat16 Bh[128*40];
    __shared__ __nv_bfloat16 Bl[128*40];
    const int m0 = blockIdx.x * 128;
    const int n  = m0 >> 12;
    const int tid = threadIdx.x, lane = tid & 31, warp = tid >> 5;
    const int wm = warp & 3, wn = warp >> 2;

    const int lr = tid >> 1, lkc = (tid & 1) * 16;
    const float* Ag = Ain + (size_t)(m0 + lr) * Dd + lkc;
    const __nv_bfloat16* Bgh = g_Mbh + ((size_t)(n*128 + lr))*Dd + lkc;
    const __nv_bfloat16* Bgl = g_Mbl + ((size_t)(n*128 + lr))*Dd + lkc;

    float fa[16];
    uint4 pbh[2], pbl[2];
    #pragma unroll
    for (int i = 0; i < 4; i++) *(float4*)&fa[i*4] = *(const float4*)(Ag + i*4);
    pbh[0] = ((const uint4*)Bgh)[0]; pbh[1] = ((const uint4*)Bgh)[1];
    pbl[0] = ((const uint4*)Bgl)[0]; pbl[1] = ((const uint4*)Bgl)[1];

    auto stg = [&]() {
        uint32_t hi[8], lo[8];
        #pragma unroll
        for (int j = 0; j < 8; j++) {
            float a = fa[2*j], b = fa[2*j+1];
            __nv_bfloat16 ha = __float2bfloat16(a);
            __nv_bfloat16 hb = __float2bfloat16(b);
            __nv_bfloat162 hp; hp.x = ha; hp.y = hb;
            hi[j] = *reinterpret_cast<uint32_t*>(&hp);
            lo[j] = pk2(a - __bfloat162float(ha), b - __bfloat162float(hb));
        }
        __nv_bfloat16* pah = &Ah[lr*40 + lkc];
        __nv_bfloat16* pal = &Al[lr*40 + lkc];
        ((uint4*)pah)[0] = make_uint4(hi[0],hi[1],hi[2],hi[3]);
        ((uint4*)pah)[1] = make_uint4(hi[4],hi[5],hi[6],hi[7]);
        ((uint4*)pal)[0] = make_uint4(lo[0],lo[1],lo[2],lo[3]);
        ((uint4*)pal)[1] = make_uint4(lo[4],lo[5],lo[6],lo[7]);
        ((uint4*)&Bh[lr*40 + lkc])[0] = pbh[0];
        ((uint4*)&Bh[lr*40 + lkc])[1] = pbh[1];
        ((uint4*)&Bl[lr*40 + lkc])[0] = pbl[0];
        ((uint4*)&Bl[lr*40 + lkc])[1] = pbl[1];
    };

    float acc[2][8][4];
    #pragma unroll
    for (int i = 0; i < 2; i++)
        #pragma unroll
        for (int j = 0; j < 8; j++)
            #pragma unroll
            for (int k = 0; k < 4; k++) acc[i][j][k] = 0.f;

    const int arow = wm*32 + (lane & 15);
    const int acol = ((lane >> 4) & 1) * 8;
    const int brow = wn*64 + (lane & 7) + ((lane >> 4) & 1) * 8;
    const int bcol = ((lane >> 3) & 1) * 8;

    for (int ks = 0; ks < 16; ks++) {
        __syncthreads();
        stg();
        __syncthreads();
        if (ks < 15) {
            #pragma unroll
            for (int i = 0; i < 4; i++)
                *(float4*)&fa[i*4] = *(const float4*)(Ag + (ks+1)*32 + i*4);
            pbh[0] = ((const uint4*)(Bgh + (ks+1)*32))[0];
            pbh[1] = ((const uint4*)(Bgh + (ks+1)*32))[1];
            pbl[0] = ((const uint4*)(Bgl + (ks+1)*32))[0];
            pbl[1] = ((const uint4*)(Bgl + (ks+1)*32))[1];
        }

        uint32_t ah[2][2][4], al[2][2][4];
        #pragma unroll
        for (int mf = 0; mf < 2; mf++)
            #pragma unroll
            for (int kf = 0; kf < 2; kf++) {
                ldsm4(ah[mf][kf], Ah + (arow + mf*16)*40 + kf*16 + acol);
                ldsm4(al[mf][kf], Al + (arow + mf*16)*40 + kf*16 + acol);
            }

        #pragma unroll
        for (int ng = 0; ng < 4; ng++) {
            uint32_t bh[2][4], bl[2][4];
            #pragma unroll
            for (int kf = 0; kf < 2; kf++) {
                ldsm4(bh[kf], Bh + (brow + ng*16)*40 + kf*16 + bcol);
                ldsm4(bl[kf], Bl + (brow + ng*16)*40 + kf*16 + bcol);
            }
            #pragma unroll
            for (int s = 0; s < 2; s++) {
                int nf = ng*2 + s;
                #pragma unroll
                for (int mf = 0; mf < 2; mf++) {
                    mmabf(acc[mf][nf], ah[mf][0], bh[0][2*s], bh[0][2*s+1]);
                    mmabf(acc[mf][nf], ah[mf][1], bh[1][2*s], bh[1][2*s+1]);
                    mmabf(acc[mf][nf], ah[mf][0], bl[0][2*s], bl[0][2*s+1]);
                    mmabf(acc[mf][nf], ah[mf][1], bl[1][2*s], bl[1][2*s+1]);
                    mmabf(acc[mf][nf], al[mf][0], bh[0][2*s], bh[0][2*s+1]);
                    mmabf(acc[mf][nf], al[mf][1], bh[1][2*s], bh[1][2*s+1]);
                }
            }
        }
    }

    // epilogue: LN affine + mask + per-(row,half) absmax + int8 STE quant
    const float mfv = g_maskf[n];
    const int mrow = m0 + wm*32 + (lane >> 2);
    float smv[16], cmv[16];
    #pragma unroll
    for (int nf = 0; nf < 8; nf++) {
        int o = wn*64 + nf*8 + (lane & 3)*2;
        smv[2*nf]   = g_SM[n*128 + o];   smv[2*nf+1] = g_SM[n*128 + o + 1];
        cmv[2*nf]   = g_CM[n*128 + o];   cmv[2*nf+1] = g_CM[n*128 + o + 1];
    }
    float* dstb = (wn == 0) ? g_kq : g_vq;
    #pragma unroll
    for (int mf2 = 0; mf2 < 2; mf2++) {
        #pragma unroll
        for (int rr = 0; rr < 2; rr++) {
            int r = mrow + mf2*16 + rr*8;
            float rsv = g_rs[r], murs = g_mu[r]*rsv;
            float v[16]; float am = 0.f;
            #pragma unroll
            for (int nf = 0; nf < 8; nf++) {
                #pragma unroll
                for (int t = 0; t < 2; t++) {
                    float val = (rsv*acc[mf2][nf][2*rr+t] - murs*smv[2*nf+t] + cmv[2*nf+t]) * mfv;
                    v[2*nf+t] = val;
                    am = fmaxf(am, fabsf(val));
                }
            }
            am = fmaxf(am, __shfl_xor_sync(0xffffffffu, am, 1));
            am = fmaxf(am, __shfl_xor_sync(0xffffffffu, am, 2));
            am = fmaxf(am, 1e-8f);
            float scq = 127.f / am;
            float inv = am * (1.f / 127.f);
            #pragma unroll
            for (int nf = 0; nf < 8; nf++) {
                float q0 = rintf(v[2*nf]   * scq) * inv;
                float q1 = rintf(v[2*nf+1] * scq) * inv;
                *(float2*)(dstb + (size_t)r*64 + nf*8 + (lane & 3)*2) = make_float2(q0, q1);
            }
        }
    }
}

// ---------------- transpose decoders ----------------
__global__ void k_transdec(const float* __restrict__ kd, const float* __restrict__ vd)
{
    int idx = blockIdx.x * 256 + threadIdx.x;
    int d = idx >> 6, r = idx & 63;
    g_kdecT[r*Dd + d] = kd[idx];
    g_vdecT[r*Dd + d] = vd[idx];
}

// ---------------- average over n + decompress -> bf16 K/V [B,H,T,HD] ------------
__global__ __launch_bounds__(256) void k_decomp()
{
    __shared__ float avg[16][64];
    int bt0 = blockIdx.x * 16;
    int isv = blockIdx.y;
    const float* src = isv ? g_vq : g_kq;
    const float* dec = isv ? g_vdecT : g_kdecT;
    __nv_bfloat16* dstb = isv ? g_Vh : g_Kh;
    float invna = g_invna;
    int tid = threadIdx.x;
    #pragma unroll
    for (int j = 0; j < 4; j++) {
        int p = j*256 + tid;
        int row = p >> 6, r = p & 63;
        float s = 0.f;
        #pragma unroll
        for (int n = 0; n < Nn; n++)
            s += src[((size_t)(n*BTc + bt0 + row))*64 + r];
        avg[row][r] = s * invna;
    }
    __syncthreads();
    int d0 = tid * 2;
    float2 acc[16];
    #pragma unroll
    for (int row = 0; row < 16; row++) { acc[row].x = 0.f; acc[row].y = 0.f; }
    for (int r = 0; r < 64; r++) {
        float2 kd = *(const float2*)(dec + r*Dd + d0);
        #pragma unroll
        for (int row = 0; row < 16; row++) {
            float a = avg[row][r];
            acc[row].x = fmaf(a, kd.x, acc[row].x);
            acc[row].y = fmaf(a, kd.y, acc[row].y);
        }
    }
    float sc = isv ? 1.f : INV_SQRT_HD;
    int h = d0 >> 7, hd = d0 & 127;
    #pragma unroll
    for (int row = 0; row < 16; row++) {
        int bt = bt0 + row;
        int b = bt >> 10, t = bt & 1023;
        __nv_bfloat16* dst = dstb + (((size_t)(b*Hh+h)*Tt + t)*HDc + hd);
        *(uint32_t*)dst = pk2(acc[row].x * sc, acc[row].y * sc);
    }
}

// ---------------- causal flash attention: bf16 mma, 64q x 64kv tiles -------------
__global__ __launch_bounds__(128) void k_flash()
{
    extern __shared__ __nv_bfloat16 smb[];
    __nv_bfloat16* Qs = smb;
    __nv_bfloat16* Ks = Qs + 64*FSTR;
    __nv_bfloat16* Vs = Ks + 64*FSTR;
    const int nbh = blockIdx.y;
    const int n = nbh >> 4, b = (nbh >> 2) & 3, h = nbh & 3;
    const int qt = blockIdx.x;
    const int q0 = qt * 64;
    const int tid = threadIdx.x, lane = tid & 31, warp = tid >> 5;

    const size_t qbase  = ((size_t)(n*Bb + b)*Tt + q0) * Dd + h*HDc;
    const size_t kvbase = (size_t)(b*Hh + h) * Tt * HDc;

    #pragma unroll
    for (int i = 0; i < 8; i++) {
        int idx = tid + i*128;
        int r = idx >> 4, c = (idx & 15) * 8;
        *(uint4*)&Qs[r*FSTR + c] = *(const uint4*)(g_Qh + qbase + (size_t)r*Dd + c);
    }
    __syncthreads();

    uint32_t qf[8][4];
    {
        const __nv_bfloat16* qp = Qs + (warp*16 + (lane & 15))*FSTR + (lane >> 4)*8;
        #pragma unroll
        for (int kf = 0; kf < 8; kf++) ldsm4(qf[kf], qp + kf*16);
    }

    float accO[16][4];
    #pragma unroll
    for (int i = 0; i < 16; i++)
        #pragma unroll
        for (int j = 0; j < 4; j++) accO[i][j] = 0.f;
    float mrow[2] = {-1e30f, -1e30f};
    float lrow[2] = {0.f, 0.f};

    const int r0q = warp*16 + (lane >> 2);
    const int c0q = (lane & 3) * 2;

    for (int kt = 0; kt <= qt; kt++) {
        const int k0 = kt * 64;
        __syncthreads();
        #pragma unroll
        for (int i = 0; i < 8; i++) {
            int idx = tid + i*128;
            int r = idx >> 4, c = (idx & 15)*8;
            size_t src = kvbase + (size_t)(k0 + r)*HDc + c;
            *(uint4*)&Ks[r*FSTR + c] = *(const uint4*)(g_Kh + src);
            *(uint4*)&Vs[r*FSTR + c] = *(const uint4*)(g_Vh + src);
        }
        __syncthreads();

        float sfr[8][4];
        #pragma unroll
        for (int i = 0; i < 8; i++)
            #pragma unroll
            for (int j = 0; j < 4; j++) sfr[i][j] = 0.f;

        {
            const __nv_bfloat16* kp = Ks + ((lane & 7) + ((lane >> 4) & 1)*8)*FSTR
                                         + ((lane >> 3) & 1)*8;
            #pragma unroll
            for (int ng = 0; ng < 4; ng++) {
                #pragma unroll
                for (int kf = 0; kf < 8; kf++) {
                    uint32_t bf[4];
                    ldsm4(bf, kp + ng*16*FSTR + kf*16);
                    mmabf(sfr[2*ng],   qf[kf], bf[0], bf[1]);
                    mmabf(sfr[2*ng+1], qf[kf], bf[2], bf[3]);
                }
            }
        }

        if (kt == qt) {
            #pragma unroll
            for (int j = 0; j < 8; j++) {
                int cj = 8*j + c0q;
                #pragma unroll
                for (int rr = 0; rr < 2; rr++) {
                    int ri = r0q + 8*rr;
                    if (cj     > ri) sfr[j][2*rr]   = -1e30f;
                    if (cj + 1 > ri) sfr[j][2*rr+1] = -1e30f;
                }
            }
        }

        #pragma unroll
        for (int rr = 0; rr < 2; rr++) {
            float tm = -1e30f;
            #pragma unroll
            for (int j = 0; j < 8; j++)
                tm = fmaxf(tm, fmaxf(sfr[j][2*rr], sfr[j][2*rr+1]));
            tm = fmaxf(tm, __shfl_xor_sync(0xffffffffu, tm, 1));
            tm = fmaxf(tm, __shfl_xor_sync(0xffffffffu, tm, 2));
            float mnew = fmaxf(mrow[rr], tm);
            float scl = exp2f((mrow[rr] - mnew) * L2E);
            float ps = 0.f;
            #pragma unroll
            for (int j = 0; j < 8; j++) {
                float e0 = exp2f((sfr[j][2*rr]   - mnew) * L2E);
                float e1 = exp2f((sfr[j][2*rr+1] - mnew) * L2E);
                sfr[j][2*rr] = e0; sfr[j][2*rr+1] = e1;
                ps += e0 + e1;
            }
            ps += __shfl_xor_sync(0xffffffffu, ps, 1);
            ps += __shfl_xor_sync(0xffffffffu, ps, 2);
            lrow[rr] = lrow[rr]*scl + ps;
            mrow[rr] = mnew;
            #pragma unroll
            for (int nf = 0; nf < 16; nf++) {
                accO[nf][2*rr]   *= scl;
                accO[nf][2*rr+1] *= scl;
            }
        }

        uint32_t pa[4][4];
        #pragma unroll
        for (int kg = 0; kg < 4; kg++) {
            pa[kg][0] = pk2(sfr[2*kg][0],   sfr[2*kg][1]);
            pa[kg][1] = pk2(sfr[2*kg][2],   sfr[2*kg][3]);
            pa[kg][2] = pk2(sfr[2*kg+1][0], sfr[2*kg+1][1]);
            pa[kg][3] = pk2(sfr[2*kg+1][2], sfr[2*kg+1][3]);
        }

        {
            const __nv_bfloat16* vp = Vs + (lane & 15)*FSTR + (lane >> 4)*8;
            #pragma unroll
            for (int dg = 0; dg < 8; dg++) {
                #pragma unroll
                for (int kg = 0; kg < 4; kg++) {
                    uint32_t vb[4];
                    ldsm4t(vb, vp + kg*16*FSTR + dg*16);
                    mmabf(accO[2*dg],   pa[kg], vb[0], vb[1]);
                    mmabf(accO[2*dg+1], pa[kg], vb[2], vb[3]);
                }
            }
        }
    }

    #pragma unroll
    for (int rr = 0; rr < 2; rr++) {
        float inv = 1.f / lrow[rr];
        size_t row = (size_t)(n*Bb + b)*Tt + q0 + r0q + 8*rr;
        float* dst = g_AO + row*Dd + h*HDc;
        #pragma unroll
        for (int nf = 0; nf < 16; nf++) {
            *(float2*)(dst + 8*nf + c0q) =
                make_float2(accO[nf][2*rr]*inv, accO[nf][2*rr+1]*inv);
        }
    }
}

// ---------------- launch (forked streams inside graph capture) ----------------
extern "C" void kernel_launch(void* const* d_in, const int* in_sizes, int n_in,
                              void* d_out, int out_size)
{
    (void)in_sizes; (void)n_in; (void)out_size;
    const float* x     = (const float*)d_in[0];
    const unsigned char* mask = (const unsigned char*)d_in[1];
    const float* lnkw  = (const float*)d_in[2];
    const float* lnkb  = (const float*)d_in[3];
    const float* lnqw  = (const float*)d_in[4];
    const float* lnqb  = (const float*)d_in[5];
    const float* wk    = (const float*)d_in[6];
    const float* wv    = (const float*)d_in[7];
    const float* wq    = (const float*)d_in[8];
    const float* wo    = (const float*)d_in[9];
    const float* kcomp = (const float*)d_in[10];
    const float* vcomp = (const float*)d_in[11];
    const float* kdec  = (const float*)d_in[12];
    const float* vdec  = (const float*)d_in[13];
    float* out = (float*)d_out;

    static cudaStream_t s1 = nullptr, s2 = nullptr;
    static cudaEvent_t eRoot, eLn, eTd, eH0;
    static bool init_done = false;
    if (!init_done) {
        cudaStreamCreateWithFlags(&s1, cudaStreamNonBlocking);
        cudaStreamCreateWithFlags(&s2, cudaStreamNonBlocking);
        cudaEventCreateWithFlags(&eRoot, cudaEventDisableTiming);
        cudaEventCreateWithFlags(&eLn,   cudaEventDisableTiming);
        cudaEventCreateWithFlags(&eTd,   cudaEventDisableTiming);
        cudaEventCreateWithFlags(&eH0,   cudaEventDisableTiming);
        cudaFuncSetAttribute(k_flash, cudaFuncAttributeMaxDynamicSharedMemorySize,
                             3*64*FSTR*2);
        init_done = true;
    }

    // fork
    cudaEventRecord(eRoot, 0);
    cudaStreamWaitEvent(s1, eRoot, 0);
    cudaStreamWaitEvent(s2, eRoot, 0);

    // s1: LN stats + decoder transpose
    k_lnstats<<<NROWS/8, 256, 0, s1>>>(x);
    cudaEventRecord(eLn, s1);
    k_transdec<<<128, 256, 0, s1>>>(kdec, vdec);
    cudaEventRecord(eTd, s1);

    // s2: Q-branch fold + Q projection
    k_foldQ<<<Nn*Dd/8, 256, 0, s2>>>(lnqw, lnqb, wq);
    cudaStreamWaitEvent(s2, eLn, 0);
    k_hgemm<0><<<dim3(4, NROWS/128), 256, 0, s2>>>(x, nullptr, nullptr, nullptr);
    cudaEventRecord(eH0, s2);

    // s0 (capture origin): KV chain
    k_mask<<<1, 32>>>(mask);
    k_compgemm<<<dim3(Nn, 2, 8), 256>>>(kcomp, vcomp, wk, wv);
    k_foldM<<<Nn*128/8, 256>>>(lnkw, lnkb);
    cudaStreamWaitEvent(0, eLn, 0);
    k_kvmma<<<NROWS/128, 256>>>(x);
    cudaStreamWaitEvent(0, eTd, 0);
    k_decomp<<<dim3(BTc/16, 2), 256>>>();
    cudaStreamWaitEvent(0, eH0, 0);
    k_flash<<<dim3(Tt/64, Nn*Bb*Hh), 128, 3*64*FSTR*2>>>();
    k_hgemm<1><<<dim3(4, NROWS/128), 256>>>(nullptr, wo, x, out);
}

// round 6
// speedup vs baseline: 9.2753x; 1.3227x over previous
#include <cuda_runtime.h>
#include <cuda_bf16.h>
#include <cstdint>
#include <cstddef>

#define Nn 8
#define Bb 4
#define Tt 1024
#define Dd 512
#define Hh 4
#define HDc 128
#define Rr 64
#define BTc (Bb*Tt)
#define NROWS (Nn*BTc)
#define EPSV 1e-5f
#define INV_SQRT_HD 0.08838834764831845f
#define L2E 1.4426950408889634f
#define FSTR 136

// ---------------- device scratch ----------------
__device__ float g_mu[NROWS];
__device__ float g_rs[NROWS];
__device__ float g_maskf[Nn];
__device__ float g_invna;
__device__ __nv_bfloat16 g_xh[(size_t)NROWS*Dd];
__device__ __nv_bfloat16 g_xl[(size_t)NROWS*Dd];
__device__ __nv_bfloat16 g_Wqh[Nn*Dd*Dd];
__device__ __nv_bfloat16 g_Woh[Nn*Dd*Dd];
__device__ float g_Sq[Nn*Dd];
__device__ float g_Cq[Nn*Dd];
__device__ float g_M[Nn*128*Dd];
__device__ __nv_bfloat16 g_Mbh[Nn*128*Dd];
__device__ __nv_bfloat16 g_Mbl[Nn*128*Dd];
__device__ float g_SM[Nn*128];
__device__ float g_CM[Nn*128];
__device__ float g_kq[(size_t)NROWS*Rr];
__device__ float g_vq[(size_t)NROWS*Rr];
__device__ float g_kdecT[Rr*Dd];
__device__ float g_vdecT[Rr*Dd];
__device__ __nv_bfloat16 g_Kh[(size_t)Bb*Hh*Tt*HDc];
__device__ __nv_bfloat16 g_Vh[(size_t)Bb*Hh*Tt*HDc];
__device__ __nv_bfloat16 g_Qh[(size_t)NROWS*Dd];
__device__ __nv_bfloat16 g_AOh[(size_t)NROWS*Dd];

// ---------------- helpers ----------------
__device__ __forceinline__ uint32_t pk2(float x, float y)
{
    __nv_bfloat162 h = __float22bfloat162_rn(make_float2(x, y));
    return *reinterpret_cast<uint32_t*>(&h);
}

__device__ __forceinline__ void ldsm4(uint32_t* r, const __nv_bfloat16* p)
{
    uint32_t a = (uint32_t)__cvta_generic_to_shared((void*)p);
    asm volatile("ldmatrix.sync.aligned.m8n8.x4.shared.b16 {%0,%1,%2,%3}, [%4];\n"
                 : "=r"(r[0]), "=r"(r[1]), "=r"(r[2]), "=r"(r[3]) : "r"(a));
}

__device__ __forceinline__ void ldsm4t(uint32_t* r, const __nv_bfloat16* p)
{
    uint32_t a = (uint32_t)__cvta_generic_to_shared((void*)p);
    asm volatile("ldmatrix.sync.aligned.m8n8.x4.trans.shared.b16 {%0,%1,%2,%3}, [%4];\n"
                 : "=r"(r[0]), "=r"(r[1]), "=r"(r[2]), "=r"(r[3]) : "r"(a));
}

__device__ __forceinline__ void mmabf(float* d, const uint32_t* a, uint32_t b0, uint32_t b1)
{
    asm volatile("mma.sync.aligned.m16n8k16.row.col.f32.bf16.bf16.f32 "
                 "{%0,%1,%2,%3},{%4,%5,%6,%7},{%8,%9},{%0,%1,%2,%3};\n"
                 : "+f"(d[0]), "+f"(d[1]), "+f"(d[2]), "+f"(d[3])
                 : "r"(a[0]), "r"(a[1]), "r"(a[2]), "r"(a[3]), "r"(b0), "r"(b1));
}

__device__ __forceinline__ void cpa16(const __nv_bfloat16* smem_dst, const __nv_bfloat16* gsrc)
{
    uint32_t ds = (uint32_t)__cvta_generic_to_shared((void*)smem_dst);
    asm volatile("cp.async.cg.shared.global [%0], [%1], 16;\n" :: "r"(ds), "l"(gsrc));
}
#define CPCOMMIT() asm volatile("cp.async.commit_group;\n" ::: "memory")
#define CPWAIT0()  asm volatile("cp.async.wait_group 0;\n" ::: "memory")

// ---------------- mask decode ----------------
__global__ void k_mask(const unsigned char* __restrict__ p)
{
    if (threadIdx.x == 0) {
        bool isF = (p[0]==0 && p[1]==0 && p[2]==0x80 && p[3]==0x3f);
        bool isI = (!isF && p[1]==0 && p[2]==0 && p[3]==0 && (p[4]!=0 || p[5]==0));
        float na = 0.f;
        for (int n = 0; n < Nn; n++) {
            bool bit;
            if (isF)      bit = (((const float*)p)[n] != 0.f);
            else if (isI) bit = (((const int*)p)[n]   != 0);
            else          bit = (p[n] != 0);
            g_maskf[n] = bit ? 1.f : 0.f;
            na += bit ? 1.f : 0.f;
        }
        g_invna = 1.f / fmaxf(na, 1.f);
    }
}

// ---------------- LN row stats + bf16 hi/lo copy of x ----------------
__global__ __launch_bounds__(256) void k_lnstats(const float* __restrict__ x)
{
    int row  = blockIdx.x * 8 + (threadIdx.x >> 5);
    int lane = threadIdx.x & 31;
    const float4* xp = (const float4*)(x + (size_t)row * Dd);
    float s = 0.f, sq = 0.f;
    #pragma unroll
    for (int i = 0; i < 4; i++) {
        int j = lane + 32*i;
        float4 v = xp[j];
        s  += v.x + v.y + v.z + v.w;
        sq += v.x*v.x + v.y*v.y + v.z*v.z + v.w*v.w;
        __nv_bfloat16 bx = __float2bfloat16(v.x);
        __nv_bfloat16 by = __float2bfloat16(v.y);
        __nv_bfloat16 bz = __float2bfloat16(v.z);
        __nv_bfloat16 bw = __float2bfloat16(v.w);
        __nv_bfloat162 h01; h01.x = bx; h01.y = by;
        __nv_bfloat162 h23; h23.x = bz; h23.y = bw;
        uint2 uh = make_uint2(*(uint32_t*)&h01, *(uint32_t*)&h23);
        uint2 ul = make_uint2(pk2(v.x - __bfloat162float(bx), v.y - __bfloat162float(by)),
                              pk2(v.z - __bfloat162float(bz), v.w - __bfloat162float(bw)));
        *(uint2*)(g_xh + (size_t)row*Dd + 4*j) = uh;
        *(uint2*)(g_xl + (size_t)row*Dd + 4*j) = ul;
    }
    #pragma unroll
    for (int o = 16; o > 0; o >>= 1) {
        s  += __shfl_xor_sync(0xffffffffu, s,  o);
        sq += __shfl_xor_sync(0xffffffffu, sq, o);
    }
    if (lane == 0) {
        float mu  = s * (1.f / Dd);
        float var = sq * (1.f / Dd) - mu * mu;
        g_mu[row] = mu;
        g_rs[row] = rsqrtf(var + EPSV);
    }
}

// ---------------- w_o -> bf16 ----------------
__global__ __launch_bounds__(256) void k_convwo(const float* __restrict__ wo)
{
    int idx = blockIdx.x * 256 + threadIdx.x;   // Nn*Dd*Dd/4 = 524288
    float4 v = ((const float4*)wo)[idx];
    ((uint2*)g_Woh)[idx] = make_uint2(pk2(v.x, v.y), pk2(v.z, v.w));
}

// ---------------- M_raw[n] = comp @ w ----------------
__global__ __launch_bounds__(256) void k_compgemm(
    const float* __restrict__ kcomp, const float* __restrict__ vcomp,
    const float* __restrict__ wk,    const float* __restrict__ wv)
{
    __shared__ float As[32*68];
    __shared__ float Bs[32*68];
    const int n    = blockIdx.x;
    const int half = blockIdx.y;
    const int i0   = blockIdx.z * 64;
    const float* comp = (half == 0 ? kcomp : vcomp) + (size_t)n * Rr * Dd;
    const float* w    = (half == 0 ? wk    : wv   ) + (size_t)n * Dd * Dd;
    const int tid = threadIdx.x, ty = tid >> 4, tx = tid & 15;
    const int arA = tid & 63, acA = (tid >> 6) * 8;
    const int arB = tid & 31, acB = (tid >> 5) * 8;

    float acc[4][4] = {};
    for (int k0 = 0; k0 < Dd; k0 += 32) {
        float4 a0 = *(const float4*)(comp + (size_t)arA*Dd + k0 + acA);
        float4 a1 = *(const float4*)(comp + (size_t)arA*Dd + k0 + acA + 4);
        float4 b0 = *(const float4*)(w + (size_t)(k0+arB)*Dd + i0 + acB);
        float4 b1 = *(const float4*)(w + (size_t)(k0+arB)*Dd + i0 + acB + 4);
        __syncthreads();
        As[(acA+0)*68+arA]=a0.x; As[(acA+1)*68+arA]=a0.y; As[(acA+2)*68+arA]=a0.z; As[(acA+3)*68+arA]=a0.w;
        As[(acA+4)*68+arA]=a1.x; As[(acA+5)*68+arA]=a1.y; As[(acA+6)*68+arA]=a1.z; As[(acA+7)*68+arA]=a1.w;
        *(float4*)&Bs[arB*68 + acB]     = b0;
        *(float4*)&Bs[arB*68 + acB + 4] = b1;
        __syncthreads();
        #pragma unroll
        for (int kk = 0; kk < 32; kk++) {
            float4 a  = *(const float4*)&As[kk*68 + ty*4];
            float4 bb = *(const float4*)&Bs[kk*68 + tx*4];
            float av[4] = {a.x,a.y,a.z,a.w};
            float bv[4] = {bb.x,bb.y,bb.z,bb.w};
            #pragma unroll
            for (int i = 0; i < 4; i++)
                #pragma unroll
                for (int j = 0; j < 4; j++)
                    acc[i][j] = fmaf(av[i], bv[j], acc[i][j]);
        }
    }
    #pragma unroll
    for (int i = 0; i < 4; i++) {
        int row = n*128 + half*64 + ty*4 + i;
        float4 o = make_float4(acc[i][0], acc[i][1], acc[i][2], acc[i][3]);
        *(float4*)(g_M + (size_t)row*Dd + i0 + tx*4) = o;
    }
}

// ---------------- fold LN(kv) into M -> bf16 hi/lo; SM/CM ----------------
__global__ __launch_bounds__(256) void k_foldM(const float* __restrict__ lnw,
                                               const float* __restrict__ lnb)
{
    int row  = blockIdx.x * 8 + (threadIdx.x >> 5);
    int lane = threadIdx.x & 31;
    int n = row >> 7;
    const float* lw = lnw + n*Dd;
    const float* lb = lnb + n*Dd;
    const float* Mrow = g_M + (size_t)row * Dd;
    float sm = 0.f, cm = 0.f;
    for (int i = lane; i < Dd; i += 32) {
        float m = Mrow[i], w = lw[i], b = lb[i];
        float p = w * m;
        sm += p; cm += b * m;
        __nv_bfloat16 hb = __float2bfloat16(p);
        g_Mbh[(size_t)row*Dd + i] = hb;
        g_Mbl[(size_t)row*Dd + i] = __float2bfloat16(p - __bfloat162float(hb));
    }
    #pragma unroll
    for (int o = 16; o > 0; o >>= 1) {
        sm += __shfl_xor_sync(0xffffffffu, sm, o);
        cm += __shfl_xor_sync(0xffffffffu, cm, o);
    }
    if (lane == 0) { g_SM[row] = sm; g_CM[row] = cm; }
}

// ---------------- fold LN(q) into w_q -> bf16 ----------------
__global__ __launch_bounds__(256) void k_foldQ(const float* __restrict__ lnw,
                                               const float* __restrict__ lnb,
                                               const float* __restrict__ wq)
{
    int row  = blockIdx.x * 8 + (threadIdx.x >> 5);
    int lane = threadIdx.x & 31;
    int n = row >> 9;
    const float* lw = lnw + n*Dd;
    const float* lb = lnb + n*Dd;
    const float* wr = wq + (size_t)row * Dd;
    float sm = 0.f, cm = 0.f;
    for (int i = lane; i < Dd; i += 32) {
        float m = wr[i], w = lw[i], b = lb[i];
        float p = w * m;
        sm += p; cm += b * m;
        g_Wqh[(size_t)row*Dd + i] = __float2bfloat16(p);
    }
    #pragma unroll
    for (int o = 16; o > 0; o >>= 1) {
        sm += __shfl_xor_sync(0xffffffffu, sm, o);
        cm += __shfl_xor_sync(0xffffffffu, cm, o);
    }
    if (lane == 0) { g_Sq[row] = sm; g_Cq[row] = cm; }
}

// ------- bf16 GEMM 128x128xK512 with cp.async pipeline. MODE 0 = Q, 1 = O -------
template<int MODE>
__global__ __launch_bounds__(256) void k_hgemm(const float* __restrict__ X,
                                               float* __restrict__ Out)
{
    __shared__ __nv_bfloat16 As[2][128*40];
    __shared__ __nv_bfloat16 Bs[2][128*40];
    const int m0 = blockIdx.y * 128;
    const int o0 = blockIdx.x * 128;
    const int n  = m0 >> 12;
    const __nv_bfloat16* A = (MODE == 0) ? g_xh : g_AOh;
    const __nv_bfloat16* B = ((MODE == 0) ? g_Wqh : g_Woh) + (size_t)n * Dd * Dd;

    const int tid = threadIdx.x, lane = tid & 31, warp = tid >> 5;
    const int wm = warp & 3, wn = warp >> 2;

    auto copyAB = [&](int st, int k0) {
        #pragma unroll
        for (int i = 0; i < 2; i++) {
            int idx = tid + i*256;
            int r = idx >> 2, c = (idx & 3) * 8;
            cpa16(&As[st][r*40 + c], A + (size_t)(m0 + r)*Dd + k0 + c);
            cpa16(&Bs[st][r*40 + c], B + (size_t)(o0 + r)*Dd + k0 + c);
        }
    };

    copyAB(0, 0);
    CPCOMMIT();

    float acc[2][8][4];
    #pragma unroll
    for (int i = 0; i < 2; i++)
        #pragma unroll
        for (int j = 0; j < 8; j++)
            #pragma unroll
            for (int k = 0; k < 4; k++) acc[i][j][k] = 0.f;

    const int arow = wm*32 + (lane & 15);
    const int acol = ((lane >> 4) & 1) * 8;
    const int brow = wn*64 + (lane & 7) + ((lane >> 4) & 1) * 8;
    const int bcol = ((lane >> 3) & 1) * 8;

    for (int ks = 0; ks < 16; ks++) {
        int st = ks & 1;
        CPWAIT0();
        __syncthreads();
        if (ks < 15) { copyAB(st ^ 1, (ks+1)*32); CPCOMMIT(); }

        const __nv_bfloat16* Asb = As[st];
        const __nv_bfloat16* Bsb = Bs[st];

        uint32_t af[2][2][4];
        #pragma unroll
        for (int mf = 0; mf < 2; mf++)
            #pragma unroll
            for (int kf = 0; kf < 2; kf++)
                ldsm4(af[mf][kf], Asb + (arow + mf*16)*40 + kf*16 + acol);

        #pragma unroll
        for (int ng = 0; ng < 4; ng++) {
            uint32_t bfr[2][4];
            #pragma unroll
            for (int kf = 0; kf < 2; kf++)
                ldsm4(bfr[kf], Bsb + (brow + ng*16)*40 + kf*16 + bcol);
            #pragma unroll
            for (int s = 0; s < 2; s++) {
                int nf = ng*2 + s;
                #pragma unroll
                for (int mf = 0; mf < 2; mf++) {
                    mmabf(acc[mf][nf], af[mf][0], bfr[0][2*s], bfr[0][2*s+1]);
                    mmabf(acc[mf][nf], af[mf][1], bfr[1][2*s], bfr[1][2*s+1]);
                }
            }
        }
        __syncthreads();
    }

    const int mrow = m0 + wm*32 + (lane >> 2);
    const int ocol = o0 + wn*64 + (lane & 3)*2;
    if (MODE == 0) {
        #pragma unroll
        for (int mf = 0; mf < 2; mf++) {
            int r0 = mrow + mf*16, r1 = r0 + 8;
            float rs0 = g_rs[r0], mr0 = g_mu[r0]*rs0;
            float rs1 = g_rs[r1], mr1 = g_mu[r1]*rs1;
            #pragma unroll
            for (int nf = 0; nf < 8; nf++) {
                int c = ocol + nf*8;
                float sq0 = g_Sq[n*Dd + c], sq1 = g_Sq[n*Dd + c + 1];
                float cq0 = g_Cq[n*Dd + c], cq1 = g_Cq[n*Dd + c + 1];
                float* d = acc[mf][nf];
                *(uint32_t*)(g_Qh + (size_t)r0*Dd + c) =
                    pk2(rs0*d[0] - mr0*sq0 + cq0, rs0*d[1] - mr0*sq1 + cq1);
                *(uint32_t*)(g_Qh + (size_t)r1*Dd + c) =
                    pk2(rs1*d[2] - mr1*sq0 + cq0, rs1*d[3] - mr1*sq1 + cq1);
            }
        }
    } else {
        float mfv = g_maskf[n];
        #pragma unroll
        for (int mf = 0; mf < 2; mf++) {
            int r0 = mrow + mf*16, r1 = r0 + 8;
            #pragma unroll
            for (int nf = 0; nf < 8; nf++) {
                int c = ocol + nf*8;
                float* d = acc[mf][nf];
                float2 x0 = *(const float2*)(X + (size_t)r0*Dd + c);
                float2 x1 = *(const float2*)(X + (size_t)r1*Dd + c);
                *(float2*)(Out + (size_t)r0*Dd + c) =
                    make_float2(x0.x + mfv*d[0], x0.y + mfv*d[1]);
                *(float2*)(Out + (size_t)r1*Dd + c) =
                    make_float2(x1.x + mfv*d[2], x1.y + mfv*d[3]);
            }
        }
    }
}

// ------- kv-compress: bf16x3 tensor cores, cp.async, + LN + mask + quant --------
__global__ __launch_bounds__(256) void k_kvmma()
{
    extern __shared__ __nv_bfloat16 kvs[];   // 2 stages x 4 operands x 128*40
    const int m0 = blockIdx.x * 128;
    const int n  = m0 >> 12;
    const int tid = threadIdx.x, lane = tid & 31, warp = tid >> 5;
    const int wm = warp & 3, wn = warp >> 2;

    const __nv_bfloat16* srcs[4] = {
        g_xh + (size_t)m0*Dd, g_xl + (size_t)m0*Dd,
        g_Mbh + (size_t)(n*128)*Dd, g_Mbl + (size_t)(n*128)*Dd };

    auto copyS = [&](int st, int k0) {
        __nv_bfloat16* base = kvs + (size_t)st*4*5120;
        #pragma unroll
        for (int op = 0; op < 4; op++) {
            #pragma unroll
            for (int i = 0; i < 2; i++) {
                int idx = tid + i*256;
                int r = idx >> 2, c = (idx & 3) * 8;
                cpa16(base + op*5120 + r*40 + c, srcs[op] + (size_t)r*Dd + k0 + c);
            }
        }
    };

    copyS(0, 0);
    CPCOMMIT();

    float acc[2][8][4];
    #pragma unroll
    for (int i = 0; i < 2; i++)
        #pragma unroll
        for (int j = 0; j < 8; j++)
            #pragma unroll
            for (int k = 0; k < 4; k++) acc[i][j][k] = 0.f;

    const int arow = wm*32 + (lane & 15);
    const int acol = ((lane >> 4) & 1) * 8;
    const int brow = wn*64 + (lane & 7) + ((lane >> 4) & 1) * 8;
    const int bcol = ((lane >> 3) & 1) * 8;

    for (int ks = 0; ks < 16; ks++) {
        int st = ks & 1;
        CPWAIT0();
        __syncthreads();
        if (ks < 15) { copyS(st ^ 1, (ks+1)*32); CPCOMMIT(); }

        const __nv_bfloat16* Ahs = kvs + (size_t)st*4*5120;
        const __nv_bfloat16* Als = Ahs + 5120;
        const __nv_bfloat16* Bhs = Ahs + 2*5120;
        const __nv_bfloat16* Bls = Ahs + 3*5120;

        uint32_t ah[2][2][4], al[2][2][4];
        #pragma unroll
        for (int mf = 0; mf < 2; mf++)
            #pragma unroll
            for (int kf = 0; kf < 2; kf++) {
                ldsm4(ah[mf][kf], Ahs + (arow + mf*16)*40 + kf*16 + acol);
                ldsm4(al[mf][kf], Als + (arow + mf*16)*40 + kf*16 + acol);
            }

        #pragma unroll
        for (int ng = 0; ng < 4; ng++) {
            uint32_t bh[2][4], bl[2][4];
            #pragma unroll
            for (int kf = 0; kf < 2; kf++) {
                ldsm4(bh[kf], Bhs + (brow + ng*16)*40 + kf*16 + bcol);
                ldsm4(bl[kf], Bls + (brow + ng*16)*40 + kf*16 + bcol);
            }
            #pragma unroll
            for (int s = 0; s < 2; s++) {
                int nf = ng*2 + s;
                #pragma unroll
                for (int mf = 0; mf < 2; mf++) {
                    mmabf(acc[mf][nf], ah[mf][0], bh[0][2*s], bh[0][2*s+1]);
                    mmabf(acc[mf][nf], ah[mf][1], bh[1][2*s], bh[1][2*s+1]);
                    mmabf(acc[mf][nf], ah[mf][0], bl[0][2*s], bl[0][2*s+1]);
                    mmabf(acc[mf][nf], ah[mf][1], bl[1][2*s], bl[1][2*s+1]);
                    mmabf(acc[mf][nf], al[mf][0], bh[0][2*s], bh[0][2*s+1]);
                    mmabf(acc[mf][nf], al[mf][1], bh[1][2*s], bh[1][2*s+1]);
                }
            }
        }
        __syncthreads();
    }

    const float mfv = g_maskf[n];
    const int mrow = m0 + wm*32 + (lane >> 2);
    float smv[16], cmv[16];
    #pragma unroll
    for (int nf = 0; nf < 8; nf++) {
        int o = wn*64 + nf*8 + (lane & 3)*2;
        smv[2*nf]   = g_SM[n*128 + o];   smv[2*nf+1] = g_SM[n*128 + o + 1];
        cmv[2*nf]   = g_CM[n*128 + o];   cmv[2*nf+1] = g_CM[n*128 + o + 1];
    }
    float* dstb = (wn == 0) ? g_kq : g_vq;
    #pragma unroll
    for (int mf2 = 0; mf2 < 2; mf2++) {
        #pragma unroll
        for (int rr = 0; rr < 2; rr++) {
            int r = mrow + mf2*16 + rr*8;
            float rsv = g_rs[r], murs = g_mu[r]*rsv;
            float v[16]; float am = 0.f;
            #pragma unroll
            for (int nf = 0; nf < 8; nf++) {
                #pragma unroll
                for (int t = 0; t < 2; t++) {
                    float val = (rsv*acc[mf2][nf][2*rr+t] - murs*smv[2*nf+t] + cmv[2*nf+t]) * mfv;
                    v[2*nf+t] = val;
                    am = fmaxf(am, fabsf(val));
                }
            }
            am = fmaxf(am, __shfl_xor_sync(0xffffffffu, am, 1));
            am = fmaxf(am, __shfl_xor_sync(0xffffffffu, am, 2));
            am = fmaxf(am, 1e-8f);
            float scq = 127.f / am;
            float inv = am * (1.f / 127.f);
            #pragma unroll
            for (int nf = 0; nf < 8; nf++) {
                float q0 = rintf(v[2*nf]   * scq) * inv;
                float q1 = rintf(v[2*nf+1] * scq) * inv;
                *(float2*)(dstb + (size_t)r*64 + nf*8 + (lane & 3)*2) = make_float2(q0, q1);
            }
        }
    }
}

// ---------------- transpose decoders ----------------
__global__ void k_transdec(const float* __restrict__ kd, const float* __restrict__ vd)
{
    int idx = blockIdx.x * 256 + threadIdx.x;
    int d = idx >> 6, r = idx & 63;
    g_kdecT[r*Dd + d] = kd[idx];
    g_vdecT[r*Dd + d] = vd[idx];
}

// ---------------- average over n + decompress -> bf16 K/V ----------------
__global__ __launch_bounds__(256) void k_decomp()
{
    __shared__ float avg[16][64];
    int bt0 = blockIdx.x * 16;
    int isv = blockIdx.y;
    const float* src = isv ? g_vq : g_kq;
    const float* dec = isv ? g_vdecT : g_kdecT;
    __nv_bfloat16* dstb = isv ? g_Vh : g_Kh;
    float invna = g_invna;
    int tid = threadIdx.x;
    #pragma unroll
    for (int j = 0; j < 4; j++) {
        int p = j*256 + tid;
        int row = p >> 6, r = p & 63;
        float s = 0.f;
        #pragma unroll
        for (int n = 0; n < Nn; n++)
            s += src[((size_t)(n*BTc + bt0 + row))*64 + r];
        avg[row][r] = s * invna;
    }
    __syncthreads();
    int d0 = tid * 2;
    float2 acc[16];
    #pragma unroll
    for (int row = 0; row < 16; row++) { acc[row].x = 0.f; acc[row].y = 0.f; }
    for (int r = 0; r < 64; r++) {
        float2 kd = *(const float2*)(dec + r*Dd + d0);
        #pragma unroll
        for (int row = 0; row < 16; row++) {
            float a = avg[row][r];
            acc[row].x = fmaf(a, kd.x, acc[row].x);
            acc[row].y = fmaf(a, kd.y, acc[row].y);
        }
    }
    float sc = isv ? 1.f : INV_SQRT_HD;
    int h = d0 >> 7, hd = d0 & 127;
    #pragma unroll
    for (int row = 0; row < 16; row++) {
        int bt = bt0 + row;
        int b = bt >> 10, t = bt & 1023;
        __nv_bfloat16* dst = dstb + (((size_t)(b*Hh+h)*Tt + t)*HDc + hd);
        *(uint32_t*)dst = pk2(acc[row].x * sc, acc[row].y * sc);
    }
}

// ---------------- causal flash attention: bf16 mma + cp.async KV pipeline --------
__global__ __launch_bounds__(128) void k_flash()
{
    extern __shared__ __nv_bfloat16 smb[];
    __nv_bfloat16* Qs = smb;                       // [64][FSTR]
    __nv_bfloat16* KV = Qs + 64*FSTR;              // 2 bufs x (K + V)
    const int nbh = blockIdx.y;
    const int n = nbh >> 4, b = (nbh >> 2) & 3, h = nbh & 3;
    const int qt = blockIdx.x;
    const int q0 = qt * 64;
    const int tid = threadIdx.x, lane = tid & 31, warp = tid >> 5;

    const size_t qbase  = ((size_t)(n*Bb + b)*Tt + q0) * Dd + h*HDc;
    const size_t kvbase = (size_t)(b*Hh + h) * Tt * HDc;

    #pragma unroll
    for (int i = 0; i < 8; i++) {
        int idx = tid + i*128;
        int r = idx >> 4, c = (idx & 15) * 8;
        cpa16(&Qs[r*FSTR + c], g_Qh + qbase + (size_t)r*Dd + c);
    }
    CPCOMMIT();

    auto copyKV = [&](int buf, int k0) {
        __nv_bfloat16* Kb = KV + (size_t)buf * 2*64*FSTR;
        __nv_bfloat16* Vb = Kb + 64*FSTR;
        #pragma unroll
        for (int i = 0; i < 8; i++) {
            int idx = tid + i*128;
            int r = idx >> 4, c = (idx & 15)*8;
            size_t src = kvbase + (size_t)(k0 + r)*HDc + c;
            cpa16(&Kb[r*FSTR + c], g_Kh + src);
            cpa16(&Vb[r*FSTR + c], g_Vh + src);
        }
    };

    copyKV(0, 0);
    CPCOMMIT();

    // wait for Q (and first KV), load Q fragments once
    CPWAIT0();
    __syncthreads();

    uint32_t qf[8][4];
    {
        const __nv_bfloat16* qp = Qs + (warp*16 + (lane & 15))*FSTR + (lane >> 4)*8;
        #pragma unroll
        for (int kf = 0; kf < 8; kf++) ldsm4(qf[kf], qp + kf*16);
    }

    float accO[16][4];
    #pragma unroll
    for (int i = 0; i < 16; i++)
        #pragma unroll
        for (int j = 0; j < 4; j++) accO[i][j] = 0.f;
    float mrow[2] = {-1e30f, -1e30f};
    float lrow[2] = {0.f, 0.f};

    const int r0q = warp*16 + (lane >> 2);
    const int c0q = (lane & 3) * 2;

    for (int kt = 0; kt <= qt; kt++) {
        if (kt > 0) { CPWAIT0(); __syncthreads(); }
        if (kt < qt) { copyKV((kt+1) & 1, (kt+1)*64); CPCOMMIT(); }

        const __nv_bfloat16* Kb = KV + (size_t)(kt & 1) * 2*64*FSTR;
        const __nv_bfloat16* Vb = Kb + 64*FSTR;

        float sfr[8][4];
        #pragma unroll
        for (int i = 0; i < 8; i++)
            #pragma unroll
            for (int j = 0; j < 4; j++) sfr[i][j] = 0.f;

        {
            const __nv_bfloat16* kp = Kb + ((lane & 7) + ((lane >> 4) & 1)*8)*FSTR
                                         + ((lane >> 3) & 1)*8;
            #pragma unroll
            for (int ng = 0; ng < 4; ng++) {
                #pragma unroll
                for (int kf = 0; kf < 8; kf++) {
                    uint32_t bf[4];
                    ldsm4(bf, kp + ng*16*FSTR + kf*16);
                    mmabf(sfr[2*ng],   qf[kf], bf[0], bf[1]);
                    mmabf(sfr[2*ng+1], qf[kf], bf[2], bf[3]);
                }
            }
        }

        if (kt == qt) {
            #pragma unroll
            for (int j = 0; j < 8; j++) {
                int cj = 8*j + c0q;
                #pragma unroll
                for (int rr = 0; rr < 2; rr++) {
                    int ri = r0q + 8*rr;
                    if (cj     > ri) sfr[j][2*rr]   = -1e30f;
                    if (cj + 1 > ri) sfr[j][2*rr+1] = -1e30f;
                }
            }
        }

        #pragma unroll
        for (int rr = 0; rr < 2; rr++) {
            float tm = -1e30f;
            #pragma unroll
            for (int j = 0; j < 8; j++)
                tm = fmaxf(tm, fmaxf(sfr[j][2*rr], sfr[j][2*rr+1]));
            tm = fmaxf(tm, __shfl_xor_sync(0xffffffffu, tm, 1));
            tm = fmaxf(tm, __shfl_xor_sync(0xffffffffu, tm, 2));
            float mnew = fmaxf(mrow[rr], tm);
            float scl = exp2f((mrow[rr] - mnew) * L2E);
            float ps = 0.f;
            #pragma unroll
            for (int j = 0; j < 8; j++) {
                float e0 = exp2f((sfr[j][2*rr]   - mnew) * L2E);
                float e1 = exp2f((sfr[j][2*rr+1] - mnew) * L2E);
                sfr[j][2*rr] = e0; sfr[j][2*rr+1] = e1;
                ps += e0 + e1;
            }
            ps += __shfl_xor_sync(0xffffffffu, ps, 1);
            ps += __shfl_xor_sync(0xffffffffu, ps, 2);
            lrow[rr] = lrow[rr]*scl + ps;
            mrow[rr] = mnew;
            #pragma unroll
            for (int nf = 0; nf < 16; nf++) {
                accO[nf][2*rr]   *= scl;
                accO[nf][2*rr+1] *= scl;
            }
        }

        uint32_t pa[4][4];
        #pragma unroll
        for (int kg = 0; kg < 4; kg++) {
            pa[kg][0] = pk2(sfr[2*kg][0],   sfr[2*kg][1]);
            pa[kg][1] = pk2(sfr[2*kg][2],   sfr[2*kg][3]);
            pa[kg][2] = pk2(sfr[2*kg+1][0], sfr[2*kg+1][1]);
            pa[kg][3] = pk2(sfr[2*kg+1][2], sfr[2*kg+1][3]);
        }

        {
            const __nv_bfloat16* vp = Vb + (lane & 15)*FSTR + (lane >> 4)*8;
            #pragma unroll
            for (int dg = 0; dg < 8; dg++) {
                #pragma unroll
                for (int kg = 0; kg < 4; kg++) {
                    uint32_t vb[4];
                    ldsm4t(vb, vp + kg*16*FSTR + dg*16);
                    mmabf(accO[2*dg],   pa[kg], vb[0], vb[1]);
                    mmabf(accO[2*dg+1], pa[kg], vb[2], vb[3]);
                }
            }
        }
    }

    #pragma unroll
    for (int rr = 0; rr < 2; rr++) {
        float inv = 1.f / lrow[rr];
        size_t row = (size_t)(n*Bb + b)*Tt + q0 + r0q + 8*rr;
        __nv_bfloat16* dst = g_AOh + row*Dd + h*HDc;
        #pragma unroll
        for (int nf = 0; nf < 16; nf++) {
            *(uint32_t*)(dst + 8*nf + c0q) =
                pk2(accO[nf][2*rr]*inv, accO[nf][2*rr+1]*inv);
        }
    }
}

// ---------------- launch ----------------
extern "C" void kernel_launch(void* const* d_in, const int* in_sizes, int n_in,
                              void* d_out, int out_size)
{
    (void)in_sizes; (void)n_in; (void)out_size;
    const float* x     = (const float*)d_in[0];
    const unsigned char* mask = (const unsigned char*)d_in[1];
    const float* lnkw  = (const float*)d_in[2];
    const float* lnkb  = (const float*)d_in[3];
    const float* lnqw  = (const float*)d_in[4];
    const float* lnqb  = (const float*)d_in[5];
    const float* wk    = (const float*)d_in[6];
    const float* wv    = (const float*)d_in[7];
    const float* wq    = (const float*)d_in[8];
    const float* wo    = (const float*)d_in[9];
    const float* kcomp = (const float*)d_in[10];
    const float* vcomp = (const float*)d_in[11];
    const float* kdec  = (const float*)d_in[12];
    const float* vdec  = (const float*)d_in[13];
    float* out = (float*)d_out;

    static cudaStream_t s1 = nullptr, s2 = nullptr;
    static cudaEvent_t eRoot, eLn, eTd, eH0;
    static bool init_done = false;
    if (!init_done) {
        cudaStreamCreateWithFlags(&s1, cudaStreamNonBlocking);
        cudaStreamCreateWithFlags(&s2, cudaStreamNonBlocking);
        cudaEventCreateWithFlags(&eRoot, cudaEventDisableTiming);
        cudaEventCreateWithFlags(&eLn,   cudaEventDisableTiming);
        cudaEventCreateWithFlags(&eTd,   cudaEventDisableTiming);
        cudaEventCreateWithFlags(&eH0,   cudaEventDisableTiming);
        cudaFuncSetAttribute(k_flash, cudaFuncAttributeMaxDynamicSharedMemorySize,
                             5*64*FSTR*2);
        cudaFuncSetAttribute(k_kvmma, cudaFuncAttributeMaxDynamicSharedMemorySize,
                             2*4*5120*2);
        init_done = true;
    }

    // fork
    cudaEventRecord(eRoot, 0);
    cudaStreamWaitEvent(s1, eRoot, 0);
    cudaStreamWaitEvent(s2, eRoot, 0);

    // s1: LN stats + x bf16 split, then decoder transpose + w_o convert
    k_lnstats<<<NROWS/8, 256, 0, s1>>>(x);
    cudaEventRecord(eLn, s1);
    k_transdec<<<128, 256, 0, s1>>>(kdec, vdec);
    k_convwo<<<Nn*Dd*Dd/4/256, 256, 0, s1>>>(wo);
    cudaEventRecord(eTd, s1);

    // s2: Q-branch fold + Q projection
    k_foldQ<<<Nn*Dd/8, 256, 0, s2>>>(lnqw, lnqb, wq);
    cudaStreamWaitEvent(s2, eLn, 0);
    k_hgemm<0><<<dim3(4, NROWS/128), 256, 0, s2>>>(nullptr, nullptr);
    cudaEventRecord(eH0, s2);

    // s0: KV chain
    k_mask<<<1, 32>>>(mask);
    k_compgemm<<<dim3(Nn, 2, 8), 256>>>(kcomp, vcomp, wk, wv);
    k_foldM<<<Nn*128/8, 256>>>(lnkw, lnkb);
    cudaStreamWaitEvent(0, eLn, 0);
    k_kvmma<<<NROWS/128, 256, 2*4*5120*2>>>();
    cudaStreamWaitEvent(0, eTd, 0);
    k_decomp<<<dim3(BTc/16, 2), 256>>>();
    cudaStreamWaitEvent(0, eH0, 0);
    k_flash<<<dim3(Tt/64, Nn*Bb*Hh), 128, 5*64*FSTR*2>>>();
    k_hgemm<1><<<dim3(4, NROWS/128), 256>>>(x, out);
}

// round 7
// speedup vs baseline: 9.8242x; 1.0592x over previous
#include <cuda_runtime.h>
#include <cuda_bf16.h>
#include <cstdint>
#include <cstddef>

#define Nn 8
#define Bb 4
#define Tt 1024
#define Dd 512
#define Hh 4
#define HDc 128
#define Rr 64
#define BTc (Bb*Tt)
#define NROWS (Nn*BTc)
#define EPSV 1e-5f
#define INV_SQRT_HD 0.08838834764831845f
#define L2E 1.4426950408889634f
#define FSTR 136
#define NT (Tt/64)

// ---------------- device scratch ----------------
__device__ float g_mu[NROWS];
__device__ float g_rs[NROWS];
__device__ float g_maskf[Nn];
__device__ float g_invna;
__device__ __nv_bfloat16 g_xh[(size_t)NROWS*Dd];
__device__ __nv_bfloat16 g_xl[(size_t)NROWS*Dd];
__device__ __nv_bfloat16 g_Wqh[Nn*Dd*Dd];
__device__ __nv_bfloat16 g_Woh[Nn*Dd*Dd];
__device__ float g_Sq[Nn*Dd];
__device__ float g_Cq[Nn*Dd];
__device__ float g_M[Nn*128*Dd];
__device__ __nv_bfloat16 g_Mbh[Nn*128*Dd];
__device__ __nv_bfloat16 g_Mbl[Nn*128*Dd];
__device__ float g_SM[Nn*128];
__device__ float g_CM[Nn*128];
__device__ float g_kq[(size_t)NROWS*Rr];
__device__ float g_vq[(size_t)NROWS*Rr];
__device__ float g_kdecT[Rr*Dd];
__device__ float g_vdecT[Rr*Dd];
__device__ __nv_bfloat16 g_Kh[(size_t)Bb*Hh*Tt*HDc];
__device__ __nv_bfloat16 g_Vh[(size_t)Bb*Hh*Tt*HDc];
__device__ __nv_bfloat16 g_Qh[(size_t)NROWS*Dd];
__device__ __nv_bfloat16 g_AOh[(size_t)NROWS*Dd];

// ---------------- helpers ----------------
__device__ __forceinline__ uint32_t pk2(float x, float y)
{
    __nv_bfloat162 h = __float22bfloat162_rn(make_float2(x, y));
    return *reinterpret_cast<uint32_t*>(&h);
}

__device__ __forceinline__ void ldsm4(uint32_t* r, const __nv_bfloat16* p)
{
    uint32_t a = (uint32_t)__cvta_generic_to_shared((void*)p);
    asm volatile("ldmatrix.sync.aligned.m8n8.x4.shared.b16 {%0,%1,%2,%3}, [%4];\n"
                 : "=r"(r[0]), "=r"(r[1]), "=r"(r[2]), "=r"(r[3]) : "r"(a));
}

__device__ __forceinline__ void ldsm4t(uint32_t* r, const __nv_bfloat16* p)
{
    uint32_t a = (uint32_t)__cvta_generic_to_shared((void*)p);
    asm volatile("ldmatrix.sync.aligned.m8n8.x4.trans.shared.b16 {%0,%1,%2,%3}, [%4];\n"
                 : "=r"(r[0]), "=r"(r[1]), "=r"(r[2]), "=r"(r[3]) : "r"(a));
}

__device__ __forceinline__ void mmabf(float* d, const uint32_t* a, uint32_t b0, uint32_t b1)
{
    asm volatile("mma.sync.aligned.m16n8k16.row.col.f32.bf16.bf16.f32 "
                 "{%0,%1,%2,%3},{%4,%5,%6,%7},{%8,%9},{%0,%1,%2,%3};\n"
                 : "+f"(d[0]), "+f"(d[1]), "+f"(d[2]), "+f"(d[3])
                 : "r"(a[0]), "r"(a[1]), "r"(a[2]), "r"(a[3]), "r"(b0), "r"(b1));
}

__device__ __forceinline__ void cpa16(const __nv_bfloat16* smem_dst, const __nv_bfloat16* gsrc)
{
    uint32_t ds = (uint32_t)__cvta_generic_to_shared((void*)smem_dst);
    asm volatile("cp.async.cg.shared.global [%0], [%1], 16;\n" :: "r"(ds), "l"(gsrc));
}
#define CPCOMMIT() asm volatile("cp.async.commit_group;\n" ::: "memory")
#define CPWAIT0()  asm volatile("cp.async.wait_group 0;\n" ::: "memory")

// ---------------- mask decode ----------------
__global__ void k_mask(const unsigned char* __restrict__ p)
{
    if (threadIdx.x == 0) {
        bool isF = (p[0]==0 && p[1]==0 && p[2]==0x80 && p[3]==0x3f);
        bool isI = (!isF && p[1]==0 && p[2]==0 && p[3]==0 && (p[4]!=0 || p[5]==0));
        float na = 0.f;
        for (int n = 0; n < Nn; n++) {
            bool bit;
            if (isF)      bit = (((const float*)p)[n] != 0.f);
            else if (isI) bit = (((const int*)p)[n]   != 0);
            else          bit = (p[n] != 0);
            g_maskf[n] = bit ? 1.f : 0.f;
            na += bit ? 1.f : 0.f;
        }
        g_invna = 1.f / fmaxf(na, 1.f);
    }
}

// ---------------- LN row stats + bf16 hi/lo copy of x ----------------
__global__ __launch_bounds__(256) void k_lnstats(const float* __restrict__ x)
{
    int row  = blockIdx.x * 8 + (threadIdx.x >> 5);
    int lane = threadIdx.x & 31;
    const float4* xp = (const float4*)(x + (size_t)row * Dd);
    float s = 0.f, sq = 0.f;
    #pragma unroll
    for (int i = 0; i < 4; i++) {
        int j = lane + 32*i;
        float4 v = xp[j];
        s  += v.x + v.y + v.z + v.w;
        sq += v.x*v.x + v.y*v.y + v.z*v.z + v.w*v.w;
        __nv_bfloat16 bx = __float2bfloat16(v.x);
        __nv_bfloat16 by = __float2bfloat16(v.y);
        __nv_bfloat16 bz = __float2bfloat16(v.z);
        __nv_bfloat16 bw = __float2bfloat16(v.w);
        __nv_bfloat162 h01; h01.x = bx; h01.y = by;
        __nv_bfloat162 h23; h23.x = bz; h23.y = bw;
        uint2 uh = make_uint2(*(uint32_t*)&h01, *(uint32_t*)&h23);
        uint2 ul = make_uint2(pk2(v.x - __bfloat162float(bx), v.y - __bfloat162float(by)),
                              pk2(v.z - __bfloat162float(bz), v.w - __bfloat162float(bw)));
        *(uint2*)(g_xh + (size_t)row*Dd + 4*j) = uh;
        *(uint2*)(g_xl + (size_t)row*Dd + 4*j) = ul;
    }
    #pragma unroll
    for (int o = 16; o > 0; o >>= 1) {
        s  += __shfl_xor_sync(0xffffffffu, s,  o);
        sq += __shfl_xor_sync(0xffffffffu, sq, o);
    }
    if (lane == 0) {
        float mu  = s * (1.f / Dd);
        float var = sq * (1.f / Dd) - mu * mu;
        g_mu[row] = mu;
        g_rs[row] = rsqrtf(var + EPSV);
    }
}

// ---------------- w_o -> bf16 ----------------
__global__ __launch_bounds__(256) void k_convwo(const float* __restrict__ wo)
{
    int idx = blockIdx.x * 256 + threadIdx.x;
    float4 v = ((const float4*)wo)[idx];
    ((uint2*)g_Woh)[idx] = make_uint2(pk2(v.x, v.y), pk2(v.z, v.w));
}

// ---------------- M_raw[n] = comp @ w ----------------
__global__ __launch_bounds__(256) void k_compgemm(
    const float* __restrict__ kcomp, const float* __restrict__ vcomp,
    const float* __restrict__ wk,    const float* __restrict__ wv)
{
    __shared__ float As[32*68];
    __shared__ float Bs[32*68];
    const int n    = blockIdx.x;
    const int half = blockIdx.y;
    const int i0   = blockIdx.z * 64;
    const float* comp = (half == 0 ? kcomp : vcomp) + (size_t)n * Rr * Dd;
    const float* w    = (half == 0 ? wk    : wv   ) + (size_t)n * Dd * Dd;
    const int tid = threadIdx.x, ty = tid >> 4, tx = tid & 15;
    const int arA = tid & 63, acA = (tid >> 6) * 8;
    const int arB = tid & 31, acB = (tid >> 5) * 8;

    float acc[4][4] = {};
    for (int k0 = 0; k0 < Dd; k0 += 32) {
        float4 a0 = *(const float4*)(comp + (size_t)arA*Dd + k0 + acA);
        float4 a1 = *(const float4*)(comp + (size_t)arA*Dd + k0 + acA + 4);
        float4 b0 = *(const float4*)(w + (size_t)(k0+arB)*Dd + i0 + acB);
        float4 b1 = *(const float4*)(w + (size_t)(k0+arB)*Dd + i0 + acB + 4);
        __syncthreads();
        As[(acA+0)*68+arA]=a0.x; As[(acA+1)*68+arA]=a0.y; As[(acA+2)*68+arA]=a0.z; As[(acA+3)*68+arA]=a0.w;
        As[(acA+4)*68+arA]=a1.x; As[(acA+5)*68+arA]=a1.y; As[(acA+6)*68+arA]=a1.z; As[(acA+7)*68+arA]=a1.w;
        *(float4*)&Bs[arB*68 + acB]     = b0;
        *(float4*)&Bs[arB*68 + acB + 4] = b1;
        __syncthreads();
        #pragma unroll
        for (int kk = 0; kk < 32; kk++) {
            float4 a  = *(const float4*)&As[kk*68 + ty*4];
            float4 bb = *(const float4*)&Bs[kk*68 + tx*4];
            float av[4] = {a.x,a.y,a.z,a.w};
            float bv[4] = {bb.x,bb.y,bb.z,bb.w};
            #pragma unroll
            for (int i = 0; i < 4; i++)
                #pragma unroll
                for (int j = 0; j < 4; j++)
                    acc[i][j] = fmaf(av[i], bv[j], acc[i][j]);
        }
    }
    #pragma unroll
    for (int i = 0; i < 4; i++) {
        int row = n*128 + half*64 + ty*4 + i;
        float4 o = make_float4(acc[i][0], acc[i][1], acc[i][2], acc[i][3]);
        *(float4*)(g_M + (size_t)row*Dd + i0 + tx*4) = o;
    }
}

// ---------------- fold LN(kv) into M -> bf16 hi/lo; SM/CM ----------------
__global__ __launch_bounds__(256) void k_foldM(const float* __restrict__ lnw,
                                               const float* __restrict__ lnb)
{
    int row  = blockIdx.x * 8 + (threadIdx.x >> 5);
    int lane = threadIdx.x & 31;
    int n = row >> 7;
    const float* lw = lnw + n*Dd;
    const float* lb = lnb + n*Dd;
    const float* Mrow = g_M + (size_t)row * Dd;
    float sm = 0.f, cm = 0.f;
    for (int i = lane; i < Dd; i += 32) {
        float m = Mrow[i], w = lw[i], b = lb[i];
        float p = w * m;
        sm += p; cm += b * m;
        __nv_bfloat16 hb = __float2bfloat16(p);
        g_Mbh[(size_t)row*Dd + i] = hb;
        g_Mbl[(size_t)row*Dd + i] = __float2bfloat16(p - __bfloat162float(hb));
    }
    #pragma unroll
    for (int o = 16; o > 0; o >>= 1) {
        sm += __shfl_xor_sync(0xffffffffu, sm, o);
        cm += __shfl_xor_sync(0xffffffffu, cm, o);
    }
    if (lane == 0) { g_SM[row] = sm; g_CM[row] = cm; }
}

// ---------------- fold LN(q) into w_q -> bf16 ----------------
__global__ __launch_bounds__(256) void k_foldQ(const float* __restrict__ lnw,
                                               const float* __restrict__ lnb,
                                               const float* __restrict__ wq)
{
    int row  = blockIdx.x * 8 + (threadIdx.x >> 5);
    int lane = threadIdx.x & 31;
    int n = row >> 9;
    const float* lw = lnw + n*Dd;
    const float* lb = lnb + n*Dd;
    const float* wr = wq + (size_t)row * Dd;
    float sm = 0.f, cm = 0.f;
    for (int i = lane; i < Dd; i += 32) {
        float m = wr[i], w = lw[i], b = lb[i];
        float p = w * m;
        sm += p; cm += b * m;
        g_Wqh[(size_t)row*Dd + i] = __float2bfloat16(p);
    }
    #pragma unroll
    for (int o = 16; o > 0; o >>= 1) {
        sm += __shfl_xor_sync(0xffffffffu, sm, o);
        cm += __shfl_xor_sync(0xffffffffu, cm, o);
    }
    if (lane == 0) { g_Sq[row] = sm; g_Cq[row] = cm; }
}

// ------- bf16 GEMM 128x128xK512 with cp.async pipeline. MODE 0 = Q, 1 = O -------
template<int MODE>
__global__ __launch_bounds__(256, 2) void k_hgemm(const float* __restrict__ X,
                                                  float* __restrict__ Out)
{
    __shared__ __nv_bfloat16 As[2][128*40];
    __shared__ __nv_bfloat16 Bs[2][128*40];
    const int m0 = blockIdx.y * 128;
    const int o0 = blockIdx.x * 128;
    const int n  = m0 >> 12;
    const __nv_bfloat16* A = (MODE == 0) ? g_xh : g_AOh;
    const __nv_bfloat16* B = ((MODE == 0) ? g_Wqh : g_Woh) + (size_t)n * Dd * Dd;

    const int tid = threadIdx.x, lane = tid & 31, warp = tid >> 5;
    const int wm = warp & 3, wn = warp >> 2;

    auto copyAB = [&](int st, int k0) {
        #pragma unroll
        for (int i = 0; i < 2; i++) {
            int idx = tid + i*256;
            int r = idx >> 2, c = (idx & 3) * 8;
            cpa16(&As[st][r*40 + c], A + (size_t)(m0 + r)*Dd + k0 + c);
            cpa16(&Bs[st][r*40 + c], B + (size_t)(o0 + r)*Dd + k0 + c);
        }
    };

    copyAB(0, 0);
    CPCOMMIT();

    float acc[2][8][4];
    #pragma unroll
    for (int i = 0; i < 2; i++)
        #pragma unroll
        for (int j = 0; j < 8; j++)
            #pragma unroll
            for (int k = 0; k < 4; k++) acc[i][j][k] = 0.f;

    const int arow = wm*32 + (lane & 15);
    const int acol = ((lane >> 4) & 1) * 8;
    const int brow = wn*64 + (lane & 7) + ((lane >> 4) & 1) * 8;
    const int bcol = ((lane >> 3) & 1) * 8;

    for (int ks = 0; ks < 16; ks++) {
        int st = ks & 1;
        CPWAIT0();
        __syncthreads();
        if (ks < 15) { copyAB(st ^ 1, (ks+1)*32); CPCOMMIT(); }

        const __nv_bfloat16* Asb = As[st];
        const __nv_bfloat16* Bsb = Bs[st];

        uint32_t af[2][2][4];
        #pragma unroll
        for (int mf = 0; mf < 2; mf++)
            #pragma unroll
            for (int kf = 0; kf < 2; kf++)
                ldsm4(af[mf][kf], Asb + (arow + mf*16)*40 + kf*16 + acol);

        #pragma unroll
        for (int ng = 0; ng < 4; ng++) {
            uint32_t bfr[2][4];
            #pragma unroll
            for (int kf = 0; kf < 2; kf++)
                ldsm4(bfr[kf], Bsb + (brow + ng*16)*40 + kf*16 + bcol);
            #pragma unroll
            for (int s = 0; s < 2; s++) {
                int nf = ng*2 + s;
                #pragma unroll
                for (int mf = 0; mf < 2; mf++) {
                    mmabf(acc[mf][nf], af[mf][0], bfr[0][2*s], bfr[0][2*s+1]);
                    mmabf(acc[mf][nf], af[mf][1], bfr[1][2*s], bfr[1][2*s+1]);
                }
            }
        }
    }

    const int mrow = m0 + wm*32 + (lane >> 2);
    const int ocol = o0 + wn*64 + (lane & 3)*2;
    if (MODE == 0) {
        #pragma unroll
        for (int mf = 0; mf < 2; mf++) {
            int r0 = mrow + mf*16, r1 = r0 + 8;
            float rs0 = g_rs[r0], mr0 = g_mu[r0]*rs0;
            float rs1 = g_rs[r1], mr1 = g_mu[r1]*rs1;
            #pragma unroll
            for (int nf = 0; nf < 8; nf++) {
                int c = ocol + nf*8;
                float sq0 = g_Sq[n*Dd + c], sq1 = g_Sq[n*Dd + c + 1];
                float cq0 = g_Cq[n*Dd + c], cq1 = g_Cq[n*Dd + c + 1];
                float* d = acc[mf][nf];
                *(uint32_t*)(g_Qh + (size_t)r0*Dd + c) =
                    pk2(rs0*d[0] - mr0*sq0 + cq0, rs0*d[1] - mr0*sq1 + cq1);
                *(uint32_t*)(g_Qh + (size_t)r1*Dd + c) =
                    pk2(rs1*d[2] - mr1*sq0 + cq0, rs1*d[3] - mr1*sq1 + cq1);
            }
        }
    } else {
        float mfv = g_maskf[n];
        #pragma unroll
        for (int mf = 0; mf < 2; mf++) {
            int r0 = mrow + mf*16, r1 = r0 + 8;
            #pragma unroll
            for (int nf = 0; nf < 8; nf++) {
                int c = ocol + nf*8;
                float* d = acc[mf][nf];
                float2 x0 = *(const float2*)(X + (size_t)r0*Dd + c);
                float2 x1 = *(const float2*)(X + (size_t)r1*Dd + c);
                *(float2*)(Out + (size_t)r0*Dd + c) =
                    make_float2(x0.x + mfv*d[0], x0.y + mfv*d[1]);
                *(float2*)(Out + (size_t)r1*Dd + c) =
                    make_float2(x1.x + mfv*d[2], x1.y + mfv*d[3]);
            }
        }
    }
}

// ------- kv-compress: bf16x3 tensor cores, cp.async, + LN + mask + quant --------
__global__ __launch_bounds__(256) void k_kvmma()
{
    extern __shared__ __nv_bfloat16 kvs[];
    const int m0 = blockIdx.x * 128;
    const int n  = m0 >> 12;
    const int tid = threadIdx.x, lane = tid & 31, warp = tid >> 5;
    const int wm = warp & 3, wn = warp >> 2;

    const __nv_bfloat16* srcs[4] = {
        g_xh + (size_t)m0*Dd, g_xl + (size_t)m0*Dd,
        g_Mbh + (size_t)(n*128)*Dd, g_Mbl + (size_t)(n*128)*Dd };

    auto copyS = [&](int st, int k0) {
        __nv_bfloat16* base = kvs + (size_t)st*4*5120;
        #pragma unroll
        for (int op = 0; op < 4; op++) {
            #pragma unroll
            for (int i = 0; i < 2; i++) {
                int idx = tid + i*256;
                int r = idx >> 2, c = (idx & 3) * 8;
                cpa16(base + op*5120 + r*40 + c, srcs[op] + (size_t)r*Dd + k0 + c);
            }
        }
    };

    copyS(0, 0);
    CPCOMMIT();

    float acc[2][8][4];
    #pragma unroll
    for (int i = 0; i < 2; i++)
        #pragma unroll
        for (int j = 0; j < 8; j++)
            #pragma unroll
            for (int k = 0; k < 4; k++) acc[i][j][k] = 0.f;

    const int arow = wm*32 + (lane & 15);
    const int acol = ((lane >> 4) & 1) * 8;
    const int brow = wn*64 + (lane & 7) + ((lane >> 4) & 1) * 8;
    const int bcol = ((lane >> 3) & 1) * 8;

    for (int ks = 0; ks < 16; ks++) {
        int st = ks & 1;
        CPWAIT0();
        __syncthreads();
        if (ks < 15) { copyS(st ^ 1, (ks+1)*32); CPCOMMIT(); }

        const __nv_bfloat16* Ahs = kvs + (size_t)st*4*5120;
        const __nv_bfloat16* Als = Ahs + 5120;
        const __nv_bfloat16* Bhs = Ahs + 2*5120;
        const __nv_bfloat16* Bls = Ahs + 3*5120;

        uint32_t ah[2][2][4], al[2][2][4];
        #pragma unroll
        for (int mf = 0; mf < 2; mf++)
            #pragma unroll
            for (int kf = 0; kf < 2; kf++) {
                ldsm4(ah[mf][kf], Ahs + (arow + mf*16)*40 + kf*16 + acol);
                ldsm4(al[mf][kf], Als + (arow + mf*16)*40 + kf*16 + acol);
            }

        #pragma unroll
        for (int ng = 0; ng < 4; ng++) {
            uint32_t bh[2][4], bl[2][4];
            #pragma unroll
            for (int kf = 0; kf < 2; kf++) {
                ldsm4(bh[kf], Bhs + (brow + ng*16)*40 + kf*16 + bcol);
                ldsm4(bl[kf], Bls + (brow + ng*16)*40 + kf*16 + bcol);
            }
            #pragma unroll
            for (int s = 0; s < 2; s++) {
                int nf = ng*2 + s;
                #pragma unroll
                for (int mf = 0; mf < 2; mf++) {
                    mmabf(acc[mf][nf], ah[mf][0], bh[0][2*s], bh[0][2*s+1]);
                    mmabf(acc[mf][nf], ah[mf][1], bh[1][2*s], bh[1][2*s+1]);
                    mmabf(acc[mf][nf], ah[mf][0], bl[0][2*s], bl[0][2*s+1]);
                    mmabf(acc[mf][nf], ah[mf][1], bl[1][2*s], bl[1][2*s+1]);
                    mmabf(acc[mf][nf], al[mf][0], bh[0][2*s], bh[0][2*s+1]);
                    mmabf(acc[mf][nf], al[mf][1], bh[1][2*s], bh[1][2*s+1]);
                }
            }
        }
    }

    const float mfv = g_maskf[n];
    const int mrow = m0 + wm*32 + (lane >> 2);
    float smv[16], cmv[16];
    #pragma unroll
    for (int nf = 0; nf < 8; nf++) {
        int o = wn*64 + nf*8 + (lane & 3)*2;
        smv[2*nf]   = g_SM[n*128 + o];   smv[2*nf+1] = g_SM[n*128 + o + 1];
        cmv[2*nf]   = g_CM[n*128 + o];   cmv[2*nf+1] = g_CM[n*128 + o + 1];
    }
    float* dstb = (wn == 0) ? g_kq : g_vq;
    #pragma unroll
    for (int mf2 = 0; mf2 < 2; mf2++) {
        #pragma unroll
        for (int rr = 0; rr < 2; rr++) {
            int r = mrow + mf2*16 + rr*8;
            float rsv = g_rs[r], murs = g_mu[r]*rsv;
            float v[16]; float am = 0.f;
            #pragma unroll
            for (int nf = 0; nf < 8; nf++) {
                #pragma unroll
                for (int t = 0; t < 2; t++) {
                    float val = (rsv*acc[mf2][nf][2*rr+t] - murs*smv[2*nf+t] + cmv[2*nf+t]) * mfv;
                    v[2*nf+t] = val;
                    am = fmaxf(am, fabsf(val));
                }
            }
            am = fmaxf(am, __shfl_xor_sync(0xffffffffu, am, 1));
            am = fmaxf(am, __shfl_xor_sync(0xffffffffu, am, 2));
            am = fmaxf(am, 1e-8f);
            float scq = 127.f / am;
            float inv = am * (1.f / 127.f);
            #pragma unroll
            for (int nf = 0; nf < 8; nf++) {
                float q0 = rintf(v[2*nf]   * scq) * inv;
                float q1 = rintf(v[2*nf+1] * scq) * inv;
                *(float2*)(dstb + (size_t)r*64 + nf*8 + (lane & 3)*2) = make_float2(q0, q1);
            }
        }
    }
}

// ---------------- transpose decoders ----------------
__global__ void k_transdec(const float* __restrict__ kd, const float* __restrict__ vd)
{
    int idx = blockIdx.x * 256 + threadIdx.x;
    int d = idx >> 6, r = idx & 63;
    g_kdecT[r*Dd + d] = kd[idx];
    g_vdecT[r*Dd + d] = vd[idx];
}

// ---------------- average over n + decompress -> bf16 K/V ----------------
__global__ __launch_bounds__(256) void k_decomp()
{
    __shared__ float avg[16][64];
    int bt0 = blockIdx.x * 16;
    int isv = blockIdx.y;
    const float* src = isv ? g_vq : g_kq;
    const float* dec = isv ? g_vdecT : g_kdecT;
    __nv_bfloat16* dstb = isv ? g_Vh : g_Kh;
    float invna = g_invna;
    int tid = threadIdx.x;
    #pragma unroll
    for (int j = 0; j < 4; j++) {
        int p = j*256 + tid;
        int row = p >> 6, r = p & 63;
        float s = 0.f;
        #pragma unroll
        for (int n = 0; n < Nn; n++)
            s += src[((size_t)(n*BTc + bt0 + row))*64 + r];
        avg[row][r] = s * invna;
    }
    __syncthreads();
    int d0 = tid * 2;
    float2 acc[16];
    #pragma unroll
    for (int row = 0; row < 16; row++) { acc[row].x = 0.f; acc[row].y = 0.f; }
    for (int r = 0; r < 64; r++) {
        float2 kd = *(const float2*)(dec + r*Dd + d0);
        #pragma unroll
        for (int row = 0; row < 16; row++) {
            float a = avg[row][r];
            acc[row].x = fmaf(a, kd.x, acc[row].x);
            acc[row].y = fmaf(a, kd.y, acc[row].y);
        }
    }
    float sc = isv ? 1.f : INV_SQRT_HD;
    int h = d0 >> 7, hd = d0 & 127;
    #pragma unroll
    for (int row = 0; row < 16; row++) {
        int bt = bt0 + row;
        int b = bt >> 10, t = bt & 1023;
        __nv_bfloat16* dst = dstb + (((size_t)(b*Hh+h)*Tt + t)*HDc + hd);
        *(uint32_t*)dst = pk2(acc[row].x * sc, acc[row].y * sc);
    }
}

// -------- causal flash attention: bf16 mma, paired q-tiles for load balance -----
__global__ __launch_bounds__(128) void k_flash()
{
    extern __shared__ __nv_bfloat16 smb[];
    __nv_bfloat16* Qs = smb;                       // [64][FSTR]
    __nv_bfloat16* KV = Qs + 64*FSTR;              // 2 bufs x (K + V)
    const int nbh = blockIdx.y;
    const int n = nbh >> 4, b = (nbh >> 2) & 3, h = nbh & 3;
    const int tid = threadIdx.x, lane = tid & 31, warp = tid >> 5;

    const size_t kvbase = (size_t)(b*Hh + h) * Tt * HDc;
    const int r0q = warp*16 + (lane >> 2);
    const int c0q = (lane & 3) * 2;

    auto copyKV = [&](int buf, int k0) {
        __nv_bfloat16* Kb = KV + (size_t)buf * 2*64*FSTR;
        __nv_bfloat16* Vb = Kb + 64*FSTR;
        #pragma unroll
        for (int i = 0; i < 8; i++) {
            int idx = tid + i*128;
            int r = idx >> 4, c = (idx & 15)*8;
            size_t src = kvbase + (size_t)(k0 + r)*HDc + c;
            cpa16(&Kb[r*FSTR + c], g_Kh + src);
            cpa16(&Vb[r*FSTR + c], g_Vh + src);
        }
    };

    #pragma unroll
    for (int phase = 0; phase < 2; phase++) {
        const int qt = phase ? (NT - 1 - (int)blockIdx.x) : (int)blockIdx.x;
        const int q0 = qt * 64;
        const size_t qbase = ((size_t)(n*Bb + b)*Tt + q0) * Dd + h*HDc;

        if (phase) __syncthreads();   // protect smem reuse across phases

        #pragma unroll
        for (int i = 0; i < 8; i++) {
            int idx = tid + i*128;
            int r = idx >> 4, c = (idx & 15) * 8;
            cpa16(&Qs[r*FSTR + c], g_Qh + qbase + (size_t)r*Dd + c);
        }
        CPCOMMIT();
        copyKV(0, 0);
        CPCOMMIT();
        CPWAIT0();
        __syncthreads();

        uint32_t qf[8][4];
        {
            const __nv_bfloat16* qp = Qs + (warp*16 + (lane & 15))*FSTR + (lane >> 4)*8;
            #pragma unroll
            for (int kf = 0; kf < 8; kf++) ldsm4(qf[kf], qp + kf*16);
        }

        float accO[16][4];
        #pragma unroll
        for (int i = 0; i < 16; i++)
            #pragma unroll
            for (int j = 0; j < 4; j++) accO[i][j] = 0.f;
        float mrow[2] = {-1e30f, -1e30f};
        float lrow[2] = {0.f, 0.f};

        for (int kt = 0; kt <= qt; kt++) {
            if (kt > 0) { CPWAIT0(); __syncthreads(); }
            if (kt < qt) { copyKV((kt+1) & 1, (kt+1)*64); CPCOMMIT(); }

            const __nv_bfloat16* Kb = KV + (size_t)(kt & 1) * 2*64*FSTR;
            const __nv_bfloat16* Vb = Kb + 64*FSTR;

            float sfr[8][4];
            #pragma unroll
            for (int i = 0; i < 8; i++)
                #pragma unroll
                for (int j = 0; j < 4; j++) sfr[i][j] = 0.f;

            {
                const __nv_bfloat16* kp = Kb + ((lane & 7) + ((lane >> 4) & 1)*8)*FSTR
                                             + ((lane >> 3) & 1)*8;
                #pragma unroll
                for (int ng = 0; ng < 4; ng++) {
                    #pragma unroll
                    for (int kf = 0; kf < 8; kf++) {
                        uint32_t bf[4];
                        ldsm4(bf, kp + ng*16*FSTR + kf*16);
                        mmabf(sfr[2*ng],   qf[kf], bf[0], bf[1]);
                        mmabf(sfr[2*ng+1], qf[kf], bf[2], bf[3]);
                    }
                }
            }

            if (kt == qt) {
                #pragma unroll
                for (int j = 0; j < 8; j++) {
                    int cj = 8*j + c0q;
                    #pragma unroll
                    for (int rr = 0; rr < 2; rr++) {
                        int ri = r0q + 8*rr;
                        if (cj     > ri) sfr[j][2*rr]   = -1e30f;
                        if (cj + 1 > ri) sfr[j][2*rr+1] = -1e30f;
                    }
                }
            }

            #pragma unroll
            for (int rr = 0; rr < 2; rr++) {
                float tm = -1e30f;
                #pragma unroll
                for (int j = 0; j < 8; j++)
                    tm = fmaxf(tm, fmaxf(sfr[j][2*rr], sfr[j][2*rr+1]));
                tm = fmaxf(tm, __shfl_xor_sync(0xffffffffu, tm, 1));
                tm = fmaxf(tm, __shfl_xor_sync(0xffffffffu, tm, 2));
                float mnew = fmaxf(mrow[rr], tm);
                float scl = exp2f((mrow[rr] - mnew) * L2E);
                float ps = 0.f;
                #pragma unroll
                for (int j = 0; j < 8; j++) {
                    float e0 = exp2f((sfr[j][2*rr]   - mnew) * L2E);
                    float e1 = exp2f((sfr[j][2*rr+1] - mnew) * L2E);
                    sfr[j][2*rr] = e0; sfr[j][2*rr+1] = e1;
                    ps += e0 + e1;
                }
                ps += __shfl_xor_sync(0xffffffffu, ps, 1);
                ps += __shfl_xor_sync(0xffffffffu, ps, 2);
                lrow[rr] = lrow[rr]*scl + ps;
                mrow[rr] = mnew;
                #pragma unroll
                for (int nf = 0; nf < 16; nf++) {
                    accO[nf][2*rr]   *= scl;
                    accO[nf][2*rr+1] *= scl;
                }
            }

            uint32_t pa[4][4];
            #pragma unroll
            for (int kg = 0; kg < 4; kg++) {
                pa[kg][0] = pk2(sfr[2*kg][0],   sfr[2*kg][1]);
                pa[kg][1] = pk2(sfr[2*kg][2],   sfr[2*kg][3]);
                pa[kg][2] = pk2(sfr[2*kg+1][0], sfr[2*kg+1][1]);
                pa[kg][3] = pk2(sfr[2*kg+1][2], sfr[2*kg+1][3]);
            }

            {
                const __nv_bfloat16* vp = Vb + (lane & 15)*FSTR + (lane >> 4)*8;
                #pragma unroll
                for (int dg = 0; dg < 8; dg++) {
                    #pragma unroll
                    for (int kg = 0; kg < 4; kg++) {
                        uint32_t vb[4];
                        ldsm4t(vb, vp + kg*16*FSTR + dg*16);
                        mmabf(accO[2*dg],   pa[kg], vb[0], vb[1]);
                        mmabf(accO[2*dg+1], pa[kg], vb[2], vb[3]);
                    }
                }
            }
        }

        #pragma unroll
        for (int rr = 0; rr < 2; rr++) {
            float inv = 1.f / lrow[rr];
            size_t row = (size_t)(n*Bb + b)*Tt + q0 + r0q + 8*rr;
            __nv_bfloat16* dst = g_AOh + row*Dd + h*HDc;
            #pragma unroll
            for (int nf = 0; nf < 16; nf++) {
                *(uint32_t*)(dst + 8*nf + c0q) =
                    pk2(accO[nf][2*rr]*inv, accO[nf][2*rr+1]*inv);
            }
        }
    }
}

// ---------------- launch ----------------
extern "C" void kernel_launch(void* const* d_in, const int* in_sizes, int n_in,
                              void* d_out, int out_size)
{
    (void)in_sizes; (void)n_in; (void)out_size;
    const float* x     = (const float*)d_in[0];
    const unsigned char* mask = (const unsigned char*)d_in[1];
    const float* lnkw  = (const float*)d_in[2];
    const float* lnkb  = (const float*)d_in[3];
    const float* lnqw  = (const float*)d_in[4];
    const float* lnqb  = (const float*)d_in[5];
    const float* wk    = (const float*)d_in[6];
    const float* wv    = (const float*)d_in[7];
    const float* wq    = (const float*)d_in[8];
    const float* wo    = (const float*)d_in[9];
    const float* kcomp = (const float*)d_in[10];
    const float* vcomp = (const float*)d_in[11];
    const float* kdec  = (const float*)d_in[12];
    const float* vdec  = (const float*)d_in[13];
    float* out = (float*)d_out;

    static cudaStream_t s1 = nullptr, s2 = nullptr;
    static cudaEvent_t eRoot, eLn, eTd, eH0;
    static bool init_done = false;
    if (!init_done) {
        cudaStreamCreateWithFlags(&s1, cudaStreamNonBlocking);
        cudaStreamCreateWithFlags(&s2, cudaStreamNonBlocking);
        cudaEventCreateWithFlags(&eRoot, cudaEventDisableTiming);
        cudaEventCreateWithFlags(&eLn,   cudaEventDisableTiming);
        cudaEventCreateWithFlags(&eTd,   cudaEventDisableTiming);
        cudaEventCreateWithFlags(&eH0,   cudaEventDisableTiming);
        cudaFuncSetAttribute(k_flash, cudaFuncAttributeMaxDynamicSharedMemorySize,
                             5*64*FSTR*2);
        cudaFuncSetAttribute(k_kvmma, cudaFuncAttributeMaxDynamicSharedMemorySize,
                             2*4*5120*2);
        init_done = true;
    }

    // fork
    cudaEventRecord(eRoot, 0);
    cudaStreamWaitEvent(s1, eRoot, 0);
    cudaStreamWaitEvent(s2, eRoot, 0);

    // s1: LN stats + x bf16 split, then decoder transpose + w_o convert
    k_lnstats<<<NROWS/8, 256, 0, s1>>>(x);
    cudaEventRecord(eLn, s1);
    k_transdec<<<128, 256, 0, s1>>>(kdec, vdec);
    k_convwo<<<Nn*Dd*Dd/4/256, 256, 0, s1>>>(wo);
    cudaEventRecord(eTd, s1);

    // s2: Q-branch fold + Q projection
    k_foldQ<<<Nn*Dd/8, 256, 0, s2>>>(lnqw, lnqb, wq);
    cudaStreamWaitEvent(s2, eLn, 0);
    k_hgemm<0><<<dim3(4, NROWS/128), 256, 0, s2>>>(nullptr, nullptr);
    cudaEventRecord(eH0, s2);

    // s0: KV chain
    k_mask<<<1, 32>>>(mask);
    k_compgemm<<<dim3(Nn, 2, 8), 256>>>(kcomp, vcomp, wk, wv);
    k_foldM<<<Nn*128/8, 256>>>(lnkw, lnkb);
    cudaStreamWaitEvent(0, eLn, 0);
    k_kvmma<<<NROWS/128, 256, 2*4*5120*2>>>();
    cudaStreamWaitEvent(0, eTd, 0);
    k_decomp<<<dim3(BTc/16, 2), 256>>>();
    cudaStreamWaitEvent(0, eH0, 0);
    k_flash<<<dim3(NT/2, Nn*Bb*Hh), 128, 5*64*FSTR*2>>>();
    k_hgemm<1><<<dim3(4, NROWS/128), 256>>>(x, out);
}